// round 1
// baseline (speedup 1.0000x reference)
#include <cuda_runtime.h>
#include <cuda_bf16.h>
#include <cuda_fp16.h>
#include <cstdint>

// ---------------------------------------------------------------------------
// LSTM with attention-weighted inputs.
//   B=256 batches, SEQ=128 steps, IN=512, H=512, 4H=2048 gates, K=IN+H=1024.
// Per step t:
//   attn = softmax(c @ Wa^T + ba)          [B,128]
//   xi   = attn @ x                        [B,512]
//   gates= [xi|h] @ Wf^T + bias            [B,2048]   (Wf = [W_ih | W_hh])
//   c,h update; out[:,t,:] = h
// Precision: c/h/softmax fp32; x fp16; GEMM = bf16 3-term split (~fp32 grade).
// ---------------------------------------------------------------------------

#define BATCH 256
#define SEQ   128
#define IN    512
#define H     512
#define NG    2048           // 4*H
#define KK    1024           // IN + H

// ---------------- device scratch (static; no allocation allowed) -----------
__device__ __half2        g_x16 [BATCH * SEQ * (IN/2)];   // x as fp16, 16 MB
__device__ __nv_bfloat16  g_Whi [NG * KK];                // fused weight hi, 4 MB
__device__ __nv_bfloat16  g_Wlo [NG * KK];                // fused weight lo, 4 MB
__device__ float          g_bias[NG];
__device__ __half         g_WaT [IN * SEQ];               // Wa transposed, fp16
__device__ float          g_c   [BATCH * H];              // cell state fp32
__device__ __nv_bfloat16  g_Ahi [BATCH * KK];             // [xi|h] hi
__device__ __nv_bfloat16  g_Alo [BATCH * KK];             // [xi|h] lo
__device__ float          g_gates[BATCH * NG];

__device__ __forceinline__ float sigf(float x) { return 1.0f / (1.0f + expf(-x)); }

__device__ __forceinline__ void bf16_split(float v, __nv_bfloat16* hi, __nv_bfloat16* lo) {
    __nv_bfloat16 h = __float2bfloat16(v);
    *hi = h;
    *lo = __float2bfloat16(v - __bfloat162float(h));
}

// ---------------- prep kernels ---------------------------------------------
__global__ void p1_convert_x(const float* __restrict__ x) {
    size_t i = (size_t)blockIdx.x * blockDim.x + threadIdx.x;   // over 8,388,608 half2
    const float2* xf = (const float2*)x;
    float2 v = xf[i];
    g_x16[i] = __floats2half2_rn(v.x, v.y);
}

__global__ void p2_weights(const float* __restrict__ W_ih, const float* __restrict__ W_hh,
                           const float* __restrict__ b_ih, const float* __restrict__ b_hh) {
    int i = blockIdx.x * blockDim.x + threadIdx.x;              // over 2,097,152
    int j = i >> 10, k = i & 1023;
    float w = (k < IN) ? W_ih[j * IN + k] : W_hh[j * H + (k - IN)];
    bf16_split(w, &g_Whi[i], &g_Wlo[i]);
    if (i < NG) g_bias[i] = b_ih[i] + b_hh[i];
}

__global__ void p3_wa(const float* __restrict__ Wa) {
    int i = blockIdx.x * blockDim.x + threadIdx.x;              // over 65536
    int d = i >> 7, s = i & 127;
    g_WaT[i] = __float2half_rn(Wa[s * IN + d]);
}

// initial cell on zero input & zero state: gates = bias only
__global__ void p4_init() {
    int b = blockIdx.x, k = threadIdx.x;                        // 256 x 512
    float gi = g_bias[k], gg = g_bias[1024 + k], go = g_bias[1536 + k];
    float c0 = sigf(gi) * tanhf(gg);
    float h0 = sigf(go) * tanhf(c0);
    g_c[b * H + k] = c0;
    bf16_split(h0, &g_Ahi[b * KK + IN + k], &g_Alo[b * KK + IN + k]);
}

// ---------------- KA: attention + xi, one block per batch ------------------
__global__ void __launch_bounds__(256) ka_attn(const float* __restrict__ ba) {
    __shared__ float c_sm[IN];
    __shared__ float part[256];
    __shared__ float attn[SEQ];
    __shared__ float red[SEQ];

    const int b = blockIdx.x, tid = threadIdx.x;

    c_sm[tid]       = g_c[b * H + tid];
    c_sm[256 + tid] = g_c[b * H + 256 + tid];
    __syncthreads();

    // logits: 2 threads per s, each sums 256 of the 512 dims
    const int s = tid & 127, half = tid >> 7;
    {
        float acc = 0.0f;
        const __half* wp = g_WaT + (half * 256) * SEQ + s;
        const float*  cp = c_sm + half * 256;
        #pragma unroll 8
        for (int d = 0; d < 256; d++)
            acc += cp[d] * __half2float(wp[d * SEQ]);
        part[tid] = acc;
    }
    __syncthreads();

    float l = 0.0f;
    if (tid < 128) { l = part[tid] + part[tid + 128] + ba[tid]; red[tid] = l; }
    __syncthreads();
    for (int off = 64; off > 0; off >>= 1) {
        if (tid < off) red[tid] = fmaxf(red[tid], red[tid + off]);
        __syncthreads();
    }
    const float m = red[0];
    __syncthreads();
    float e = 0.0f;
    if (tid < 128) { e = expf(l - m); red[tid] = e; }
    __syncthreads();
    for (int off = 64; off > 0; off >>= 1) {
        if (tid < off) red[tid] += red[tid + off];
        __syncthreads();
    }
    const float inv = 1.0f / red[0];
    if (tid < 128) attn[tid] = e * inv;
    __syncthreads();

    // xi: each thread owns 2 input dims (one half2 column), loops over seq
    const __half2* xp = g_x16 + (size_t)b * SEQ * (IN/2) + tid;
    float ax = 0.0f, ay = 0.0f;
    #pragma unroll 4
    for (int si = 0; si < SEQ; si++) {
        float a = attn[si];
        float2 v = __half22float2(xp[si * (IN/2)]);
        ax += a * v.x;
        ay += a * v.y;
    }
    const int d0 = tid * 2;
    bf16_split(ax, &g_Ahi[b * KK + d0],     &g_Alo[b * KK + d0]);
    bf16_split(ay, &g_Ahi[b * KK + d0 + 1], &g_Alo[b * KK + d0 + 1]);
}

// ---------------- KB: gates GEMM, bf16 3-split mma.sync --------------------
// M=256, N=2048, K=1024. Block tile 64x64, BK=64, 4 warps (32x32 each).
__device__ __forceinline__ void mma16816(float* c, const uint32_t* a, uint32_t b0, uint32_t b1) {
    asm volatile(
        "mma.sync.aligned.m16n8k16.row.col.f32.bf16.bf16.f32 "
        "{%0,%1,%2,%3}, {%4,%5,%6,%7}, {%8,%9}, {%0,%1,%2,%3};"
        : "+f"(c[0]), "+f"(c[1]), "+f"(c[2]), "+f"(c[3])
        : "r"(a[0]), "r"(a[1]), "r"(a[2]), "r"(a[3]), "r"(b0), "r"(b1));
}

#define SST 72   // smem row stride (bf16), 144B: conflict-free frag loads, 16B aligned

__global__ void __launch_bounds__(128) kb_gemm() {
    __shared__ __nv_bfloat16 Ah[64 * SST], Al[64 * SST], Bh[64 * SST], Bl[64 * SST];

    const int tid = threadIdx.x;
    const int bn = blockIdx.x, bm = blockIdx.y;
    const int warp = tid >> 5, lane = tid & 31;
    const int wm = (warp & 1) << 5, wn = (warp >> 1) << 5;
    const int g = lane >> 2, qk = (lane & 3) << 1;

    float acc[2][4][4] = {};

    // cooperative loads: thread owns (row = tid&63, col half = (tid>>6)*32)
    const int lr = tid & 63;
    const int lc = (tid >> 6) << 5;
    const __nv_bfloat16* gAh = g_Ahi + (size_t)(bm * 64 + lr) * KK + lc;
    const __nv_bfloat16* gAl = g_Alo + (size_t)(bm * 64 + lr) * KK + lc;
    const __nv_bfloat16* gBh = g_Whi + (size_t)(bn * 64 + lr) * KK + lc;
    const __nv_bfloat16* gBl = g_Wlo + (size_t)(bn * 64 + lr) * KK + lc;
    __nv_bfloat16* sAh = Ah + lr * SST + lc;
    __nv_bfloat16* sAl = Al + lr * SST + lc;
    __nv_bfloat16* sBh = Bh + lr * SST + lc;
    __nv_bfloat16* sBl = Bl + lr * SST + lc;

    for (int k0 = 0; k0 < KK; k0 += 64) {
        __syncthreads();
        #pragma unroll
        for (int v = 0; v < 4; v++) {
            *(uint4*)(sAh + v * 8) = *(const uint4*)(gAh + k0 + v * 8);
            *(uint4*)(sAl + v * 8) = *(const uint4*)(gAl + k0 + v * 8);
            *(uint4*)(sBh + v * 8) = *(const uint4*)(gBh + k0 + v * 8);
            *(uint4*)(sBl + v * 8) = *(const uint4*)(gBl + k0 + v * 8);
        }
        __syncthreads();

        #pragma unroll
        for (int kq = 0; kq < 4; kq++) {
            const int kb = kq * 16 + qk;
            uint32_t ah[2][4], al[2][4];
            #pragma unroll
            for (int mi = 0; mi < 2; mi++) {
                const int r = wm + mi * 16 + g;
                ah[mi][0] = *(const uint32_t*)(Ah + r * SST + kb);
                ah[mi][1] = *(const uint32_t*)(Ah + (r + 8) * SST + kb);
                ah[mi][2] = *(const uint32_t*)(Ah + r * SST + kb + 8);
                ah[mi][3] = *(const uint32_t*)(Ah + (r + 8) * SST + kb + 8);
                al[mi][0] = *(const uint32_t*)(Al + r * SST + kb);
                al[mi][1] = *(const uint32_t*)(Al + (r + 8) * SST + kb);
                al[mi][2] = *(const uint32_t*)(Al + r * SST + kb + 8);
                al[mi][3] = *(const uint32_t*)(Al + (r + 8) * SST + kb + 8);
            }
            #pragma unroll
            for (int ni = 0; ni < 4; ni++) {
                const int n = wn + ni * 8 + g;
                uint32_t bh0 = *(const uint32_t*)(Bh + n * SST + kb);
                uint32_t bh1 = *(const uint32_t*)(Bh + n * SST + kb + 8);
                uint32_t bl0 = *(const uint32_t*)(Bl + n * SST + kb);
                uint32_t bl1 = *(const uint32_t*)(Bl + n * SST + kb + 8);
                #pragma unroll
                for (int mi = 0; mi < 2; mi++) {
                    mma16816(acc[mi][ni], ah[mi], bh0, bh1);  // hi*hi
                    mma16816(acc[mi][ni], ah[mi], bl0, bl1);  // hi*lo
                    mma16816(acc[mi][ni], al[mi], bh0, bh1);  // lo*hi
                }
            }
        }
    }

    #pragma unroll
    for (int mi = 0; mi < 2; mi++) {
        #pragma unroll
        for (int ni = 0; ni < 4; ni++) {
            const int r  = bm * 64 + wm + mi * 16 + g;
            const int cc = bn * 64 + wn + ni * 8 + qk;
            float* gp0 = g_gates + (size_t)r * NG + cc;
            float* gp1 = g_gates + (size_t)(r + 8) * NG + cc;
            gp0[0] = acc[mi][ni][0];
            gp0[1] = acc[mi][ni][1];
            gp1[0] = acc[mi][ni][2];
            gp1[1] = acc[mi][ni][3];
        }
    }
}

// ---------------- KC: pointwise LSTM update + output -----------------------
__global__ void __launch_bounds__(512) kc_update(float* __restrict__ out, int t) {
    const int b = blockIdx.x, k = threadIdx.x;
    const float* gr = g_gates + (size_t)b * NG;
    float gi = gr[k]        + g_bias[k];
    float gf = gr[512 + k]  + g_bias[512 + k];
    float gg = gr[1024 + k] + g_bias[1024 + k];
    float go = gr[1536 + k] + g_bias[1536 + k];
    float c_old = g_c[b * H + k];
    float cn = sigf(gf) * c_old + sigf(gi) * tanhf(gg);
    float h  = sigf(go) * tanhf(cn);
    g_c[b * H + k] = cn;
    bf16_split(h, &g_Ahi[b * KK + IN + k], &g_Alo[b * KK + IN + k]);
    out[((size_t)b * SEQ + t) * H + k] = h;
}

// ---------------- launcher --------------------------------------------------
extern "C" void kernel_launch(void* const* d_in, const int* in_sizes, int n_in,
                              void* d_out, int out_size) {
    const float* x    = (const float*)d_in[0];
    const float* W_ih = (const float*)d_in[1];
    const float* W_hh = (const float*)d_in[2];
    const float* b_ih = (const float*)d_in[3];
    const float* b_hh = (const float*)d_in[4];
    const float* Wa   = (const float*)d_in[5];
    const float* ba   = (const float*)d_in[6];
    float* out = (float*)d_out;

    p1_convert_x<<<8192, 1024>>>(x);                 // 8,388,608 half2
    p2_weights  <<<2048, 1024>>>(W_ih, W_hh, b_ih, b_hh);
    p3_wa       <<<64,   1024>>>(Wa);
    p4_init     <<<BATCH, 512>>>();

    for (int t = 0; t < SEQ; t++) {
        ka_attn  <<<BATCH, 256>>>(ba);
        kb_gemm  <<<dim3(NG / 64, BATCH / 64), 128>>>();
        kc_update<<<BATCH, 512>>>(out, t);
    }
}

// round 2
// speedup vs baseline: 1.3976x; 1.3976x over previous
#include <cuda_runtime.h>
#include <cuda_bf16.h>
#include <cuda_fp16.h>
#include <cstdint>

// ---------------------------------------------------------------------------
// LSTM with attention-weighted inputs.  B=256, SEQ=128, IN=H=512.
// Per step: attn=softmax(c@Wa^T+ba); xi=attn@x; gates=[xi|h]@Wf^T+b; update.
// Gate dim is PERMUTED: column n = 4*k + gate  (16 hidden units per 64-wide
// N tile -> LSTM pointwise update fused into the GEMM epilogue).
// Precision: c/h/softmax fp32; x fp16; GEMM bf16 3-term split (~fp32 grade).
// ---------------------------------------------------------------------------

#define BATCH 256
#define SEQ   128
#define IN    512
#define H     512
#define NG    2048
#define KK    1024
#define SST   40          // smem tile row stride in bf16 (80B: ldmatrix conflict-free)

// ---------------- device scratch --------------------------------------------
__device__ __half2        g_x16 [BATCH * SEQ * (IN/2)];   // x fp16
__device__ __nv_bfloat16  g_Whi [NG * KK];                // fused W hi (gate-permuted rows)
__device__ __nv_bfloat16  g_Wlo [NG * KK];                // fused W lo
__device__ float          g_bias[NG];                     // gate-permuted
__device__ __half2        g_Wa16[SEQ * (IN/2)];           // Wa [s][d] fp16
__device__ float          g_c   [BATCH * H];
__device__ __nv_bfloat16  g_Ahi [BATCH * KK];             // [xi|h] hi
__device__ __nv_bfloat16  g_Alo [BATCH * KK];             // [xi|h] lo

__device__ __forceinline__ float sigf(float x) { return 1.0f / (1.0f + expf(-x)); }

__device__ __forceinline__ void bf16_split(float v, __nv_bfloat16* hi, __nv_bfloat16* lo) {
    __nv_bfloat16 h = __float2bfloat16(v);
    *hi = h;
    *lo = __float2bfloat16(v - __bfloat162float(h));
}

// ---------------- asm helpers ------------------------------------------------
__device__ __forceinline__ void cp16(void* dst, const void* src) {
    uint32_t d = (uint32_t)__cvta_generic_to_shared(dst);
    asm volatile("cp.async.cg.shared.global [%0], [%1], 16;\n" :: "r"(d), "l"(src));
}
__device__ __forceinline__ void cp_commit() { asm volatile("cp.async.commit_group;\n"); }
__device__ __forceinline__ void cp_wait1()  { asm volatile("cp.async.wait_group 1;\n"); }
__device__ __forceinline__ void cp_wait0()  { asm volatile("cp.async.wait_group 0;\n"); }

__device__ __forceinline__ void ldm_x4(uint32_t* r, const void* p) {
    uint32_t a = (uint32_t)__cvta_generic_to_shared(p);
    asm volatile("ldmatrix.sync.aligned.m8n8.x4.shared.b16 {%0,%1,%2,%3}, [%4];"
                 : "=r"(r[0]), "=r"(r[1]), "=r"(r[2]), "=r"(r[3]) : "r"(a));
}

__device__ __forceinline__ void mma16816(float* c, const uint32_t* a, uint32_t b0, uint32_t b1) {
    asm volatile(
        "mma.sync.aligned.m16n8k16.row.col.f32.bf16.bf16.f32 "
        "{%0,%1,%2,%3}, {%4,%5,%6,%7}, {%8,%9}, {%0,%1,%2,%3};"
        : "+f"(c[0]), "+f"(c[1]), "+f"(c[2]), "+f"(c[3])
        : "r"(a[0]), "r"(a[1]), "r"(a[2]), "r"(a[3]), "r"(b0), "r"(b1));
}

// ---------------- prep kernels -----------------------------------------------
__global__ void p1_convert_x(const float* __restrict__ x) {
    size_t i = (size_t)blockIdx.x * blockDim.x + threadIdx.x;
    float2 v = ((const float2*)x)[i];
    g_x16[i] = __floats2half2_rn(v.x, v.y);
}

// gate-permuted fused weights: row n -> orig gate row j = (n&3)*512 + (n>>2)
__global__ void p2_weights(const float* __restrict__ W_ih, const float* __restrict__ W_hh,
                           const float* __restrict__ b_ih, const float* __restrict__ b_hh) {
    int i = blockIdx.x * blockDim.x + threadIdx.x;     // over 2,097,152
    int n = i >> 10, kc = i & 1023;
    int j = (n & 3) * 512 + (n >> 2);
    float w = (kc < IN) ? W_ih[j * IN + kc] : W_hh[j * H + (kc - IN)];
    bf16_split(w, &g_Whi[i], &g_Wlo[i]);
    if (i < NG) {
        int jb = (i & 3) * 512 + (i >> 2);
        g_bias[i] = b_ih[jb] + b_hh[jb];
    }
}

__global__ void p3_wa(const float* __restrict__ Wa) {
    int i = blockIdx.x * blockDim.x + threadIdx.x;     // over 32768 half2
    float2 v = ((const float2*)Wa)[i];
    g_Wa16[i] = __floats2half2_rn(v.x, v.y);
}

// initial cell on zero input & zero state: gates = bias only (permuted layout)
__global__ void p4_init() {
    int b = blockIdx.x, k = threadIdx.x;
    float gi = g_bias[k * 4 + 0], gg = g_bias[k * 4 + 2], go = g_bias[k * 4 + 3];
    float c0 = sigf(gi) * tanhf(gg);
    float h0 = sigf(go) * tanhf(c0);
    g_c[b * H + k] = c0;
    bf16_split(h0, &g_Ahi[b * KK + IN + k], &g_Alo[b * KK + IN + k]);
}

// ---------------- KA: attention + xi, one block per batch --------------------
__global__ void __launch_bounds__(256) ka_attn(const float* __restrict__ ba) {
    __shared__ float c_sm[IN];
    __shared__ float logit[SEQ];
    __shared__ float attn[SEQ];
    __shared__ float rmax[4], rsum[4];

    const int b = blockIdx.x, tid = threadIdx.x;
    const int lane = tid & 31, warp = tid >> 5;

    c_sm[tid]       = g_c[b * H + tid];
    c_sm[256 + tid] = g_c[b * H + 256 + tid];
    __syncthreads();

    // preload c as float4: lane covers dims 4p..4p+3 for p = j*32+lane
    float4 cf[4];
    #pragma unroll
    for (int j = 0; j < 4; j++) cf[j] = ((const float4*)c_sm)[j * 32 + lane];

    // logits: warp w handles s = w*16 .. w*16+15; uint2 = 4 halves per load
    const uint2* wa = (const uint2*)g_Wa16;   // row stride 128 uint2
    #pragma unroll 2
    for (int si = 0; si < 16; si++) {
        const int s = warp * 16 + si;
        const uint2* wp = wa + s * 128;
        float acc = 0.0f;
        #pragma unroll
        for (int j = 0; j < 4; j++) {
            uint2 v = wp[j * 32 + lane];
            float2 w0 = __half22float2(*(const __half2*)&v.x);
            float2 w1 = __half22float2(*(const __half2*)&v.y);
            acc += cf[j].x * w0.x + cf[j].y * w0.y + cf[j].z * w1.x + cf[j].w * w1.y;
        }
        #pragma unroll
        for (int off = 16; off > 0; off >>= 1) acc += __shfl_xor_sync(0xffffffffu, acc, off);
        if (lane == 0) logit[s] = acc + ba[s];
    }
    __syncthreads();

    if (tid < 128) {
        float l = logit[tid], m = l;
        #pragma unroll
        for (int off = 16; off > 0; off >>= 1) m = fmaxf(m, __shfl_xor_sync(0xffffffffu, m, off));
        if (lane == 0) rmax[tid >> 5] = m;
    }
    __syncthreads();
    if (tid < 128) {
        float m = fmaxf(fmaxf(rmax[0], rmax[1]), fmaxf(rmax[2], rmax[3]));
        float e = expf(logit[tid] - m);
        attn[tid] = e;                                 // unnormalized
        float s = e;
        #pragma unroll
        for (int off = 16; off > 0; off >>= 1) s += __shfl_xor_sync(0xffffffffu, s, off);
        if (lane == 0) rsum[tid >> 5] = s;
    }
    __syncthreads();
    const float inv = 1.0f / (rsum[0] + rsum[1] + rsum[2] + rsum[3]);

    // xi: thread owns 2 dims; accumulate unnormalized, scale by inv at end
    const __half2* xp = g_x16 + (size_t)b * SEQ * (IN/2) + tid;
    float ax = 0.0f, ay = 0.0f;
    #pragma unroll 16
    for (int s = 0; s < SEQ; s++) {
        float a = attn[s];
        float2 v = __half22float2(xp[s * (IN/2)]);
        ax += a * v.x;
        ay += a * v.y;
    }
    ax *= inv; ay *= inv;
    const int d0 = tid * 2;
    bf16_split(ax, &g_Ahi[b * KK + d0],     &g_Alo[b * KK + d0]);
    bf16_split(ay, &g_Ahi[b * KK + d0 + 1], &g_Alo[b * KK + d0 + 1]);
}

// ---------------- KB: gates GEMM (bf16 3-split) + fused LSTM update ----------
// M=256, N=2048(permuted), K=1024. Tile 64x64, BK=32, 8 warps, cp.async x2 buf.
// smem: 2 stages * {Ah,Al,Bh,Bl} each 64*SST bf16 (5120B) = 40960B, unioned
// with the 64x68 float gates staging buffer (17408B).
#define STAGE_BYTES 20480
#define ARR_BYTES   5120

__global__ void __launch_bounds__(256) kb_gemm(float* __restrict__ out, int t) {
    __shared__ __align__(16) char smraw[2 * STAGE_BYTES];

    const int tid = threadIdx.x, lane = tid & 31, warp = tid >> 5;
    const int bn = blockIdx.x, bm = blockIdx.y;        // 32 x 4
    const int wm = (warp & 1) * 32, wn = (warp >> 1) * 16;

    // loader: thread -> (row, 16B segment)
    const int lr = tid & 63, lseg = tid >> 6;
    const size_t gA = (size_t)(bm * 64 + lr) * KK + lseg * 8;
    const size_t gB = (size_t)(bn * 64 + lr) * KK + lseg * 8;
    const int sOff = lr * SST + lseg * 8;

    float acc[2][2][4] = {};

    // prologue load stage 0
    {
        char* base = smraw;
        cp16((__nv_bfloat16*)(base)                 + sOff, g_Ahi + gA);
        cp16((__nv_bfloat16*)(base + ARR_BYTES)     + sOff, g_Alo + gA);
        cp16((__nv_bfloat16*)(base + 2 * ARR_BYTES) + sOff, g_Whi + gB);
        cp16((__nv_bfloat16*)(base + 3 * ARR_BYTES) + sOff, g_Wlo + gB);
        cp_commit();
    }

    for (int ks = 0; ks < 32; ks++) {
        if (ks + 1 < 32) {
            char* base = smraw + ((ks + 1) & 1) * STAGE_BYTES;
            const int k0 = (ks + 1) * 32;
            cp16((__nv_bfloat16*)(base)                 + sOff, g_Ahi + gA + k0);
            cp16((__nv_bfloat16*)(base + ARR_BYTES)     + sOff, g_Alo + gA + k0);
            cp16((__nv_bfloat16*)(base + 2 * ARR_BYTES) + sOff, g_Whi + gB + k0);
            cp16((__nv_bfloat16*)(base + 3 * ARR_BYTES) + sOff, g_Wlo + gB + k0);
            cp_commit();
            cp_wait1();
        } else {
            cp_wait0();
        }
        __syncthreads();

        char* base = smraw + (ks & 1) * STAGE_BYTES;
        const __nv_bfloat16* Ah = (const __nv_bfloat16*)(base);
        const __nv_bfloat16* Al = (const __nv_bfloat16*)(base + ARR_BYTES);
        const __nv_bfloat16* Bh = (const __nv_bfloat16*)(base + 2 * ARR_BYTES);
        const __nv_bfloat16* Bl = (const __nv_bfloat16*)(base + 3 * ARR_BYTES);

        #pragma unroll
        for (int kq = 0; kq < 2; kq++) {
            const int kb = kq * 16;
            uint32_t ah[2][4], al[2][4], bh[4], bl[4];
            // A: lanes 0-15 rows, lanes 16-31 col+8 (canonical x4)
            const int ar = (lane & 15), ac = kb + (lane >> 4) * 8;
            #pragma unroll
            for (int mi = 0; mi < 2; mi++) {
                ldm_x4(ah[mi], Ah + (wm + mi * 16 + ar) * SST + ac);
                ldm_x4(al[mi], Al + (wm + mi * 16 + ar) * SST + ac);
            }
            // B: m0 rows wn+0..7 k+0 | m1 rows wn+0..7 k+8 | m2 rows+8 k+0 | m3 rows+8 k+8
            const int brow = wn + (lane & 7) + ((lane >> 4) << 3);
            const int bcol = kb + ((lane >> 3) & 1) * 8;
            ldm_x4(bh, Bh + brow * SST + bcol);
            ldm_x4(bl, Bl + brow * SST + bcol);

            #pragma unroll
            for (int mi = 0; mi < 2; mi++)
                #pragma unroll
                for (int ni = 0; ni < 2; ni++) {
                    mma16816(acc[mi][ni], ah[mi], bh[ni * 2], bh[ni * 2 + 1]);   // hi*hi
                    mma16816(acc[mi][ni], ah[mi], bl[ni * 2], bl[ni * 2 + 1]);   // hi*lo
                    mma16816(acc[mi][ni], al[mi], bh[ni * 2], bh[ni * 2 + 1]);   // lo*hi
                }
        }
        __syncthreads();
    }

    // ---- epilogue: stage gates in smem, fused LSTM pointwise update ----
    float* gsm = (float*)smraw;                        // [64][68]
    #pragma unroll
    for (int mi = 0; mi < 2; mi++)
        #pragma unroll
        for (int ni = 0; ni < 2; ni++) {
            const int r = wm + mi * 16 + (lane >> 2);
            const int c = wn + ni * 8 + (lane & 3) * 2;
            gsm[r * 68 + c]           = acc[mi][ni][0];
            gsm[r * 68 + c + 1]       = acc[mi][ni][1];
            gsm[(r + 8) * 68 + c]     = acc[mi][ni][2];
            gsm[(r + 8) * 68 + c + 1] = acc[mi][ni][3];
        }
    __syncthreads();

    // thread -> (kl = tid&15, bl = tid>>4 + 16j): coalesced in k
    const int kl = tid & 15;
    const int k  = bn * 16 + kl;
    #pragma unroll
    for (int j = 0; j < 4; j++) {
        const int bl = (tid >> 4) + j * 16;
        const int batch = bm * 64 + bl;
        float4 g4 = *(const float4*)&gsm[bl * 68 + kl * 4];
        float gi = g4.x + g_bias[k * 4 + 0];
        float gf = g4.y + g_bias[k * 4 + 1];
        float gg = g4.z + g_bias[k * 4 + 2];
        float go = g4.w + g_bias[k * 4 + 3];
        float cold = g_c[batch * H + k];
        float cn = sigf(gf) * cold + sigf(gi) * tanhf(gg);
        float h  = sigf(go) * tanhf(cn);
        g_c[batch * H + k] = cn;
        bf16_split(h, &g_Ahi[batch * KK + IN + k], &g_Alo[batch * KK + IN + k]);
        out[((size_t)batch * SEQ + t) * H + k] = h;
    }
}

// ---------------- launcher ----------------------------------------------------
extern "C" void kernel_launch(void* const* d_in, const int* in_sizes, int n_in,
                              void* d_out, int out_size) {
    const float* x    = (const float*)d_in[0];
    const float* W_ih = (const float*)d_in[1];
    const float* W_hh = (const float*)d_in[2];
    const float* b_ih = (const float*)d_in[3];
    const float* b_hh = (const float*)d_in[4];
    const float* Wa   = (const float*)d_in[5];
    const float* ba   = (const float*)d_in[6];
    float* out = (float*)d_out;

    p1_convert_x<<<8192, 1024>>>(x);
    p2_weights  <<<2048, 1024>>>(W_ih, W_hh, b_ih, b_hh);
    p3_wa       <<<32,   1024>>>(Wa);
    p4_init     <<<BATCH, 512>>>();

    for (int t = 0; t < SEQ; t++) {
        ka_attn<<<BATCH, 256>>>(ba);
        kb_gemm<<<dim3(NG / 64, BATCH / 64), 256>>>(out, t);
    }
}

// round 3
// speedup vs baseline: 1.7502x; 1.2523x over previous
#include <cuda_runtime.h>
#include <cuda_bf16.h>
#include <cuda_fp16.h>
#include <cstdint>

// ---------------------------------------------------------------------------
// LSTM with attention-weighted inputs.  B=256, SEQ=128, IN=H=512.
// Per step: attn=softmax(c@Wa^T+ba); xi=attn@x; gates=[xi|h]@Wf^T+b; update.
// Gate dim PERMUTED: column n = 4*k + gate.
// Step pipeline:
//   K1: even blocks -> h-half GEMM (K=512..1023) writes partial gates (fp32)
//       odd  blocks -> attention + xi (writes xi hi/lo into A cols 0..511)
//   K2: xi-half GEMM (K=0..511) + partial + bias -> fused LSTM update
// Precision: c/h/softmax fp32; x fp16; GEMM bf16 3-term split (~fp32 grade).
// ---------------------------------------------------------------------------

#define BATCH 256
#define SEQ   128
#define IN    512
#define H     512
#define NG    2048
#define KK    1024
#define SST   40                 // smem row stride (bf16), conflict-free ldmatrix

// GEMM tiling: 32x64 tile, BK=32, 8 warps (warp tile 16x16)
#define ASTG  2560               // 32*40*2
#define BSTG  5120               // 64*40*2
#define STGB  15360              // Ah+Al+Bh+Bl
#define SMEM_BYTES (2 * STGB)    // 30720

// ---------------- device scratch --------------------------------------------
__device__ __half2        g_x16 [BATCH * SEQ * (IN/2)];
__device__ __nv_bfloat16  g_Whi [NG * KK];
__device__ __nv_bfloat16  g_Wlo [NG * KK];
__device__ float          g_bias[NG];
__device__ __half2        g_Wa16[SEQ * (IN/2)];
__device__ float          g_c   [BATCH * H];
__device__ __nv_bfloat16  g_Ahi [BATCH * KK];
__device__ __nv_bfloat16  g_Alo [BATCH * KK];
__device__ float          g_gates[BATCH * NG];          // h-half partial

__device__ __forceinline__ float sigf(float x) { return 1.0f / (1.0f + expf(-x)); }

__device__ __forceinline__ void bf16_split(float v, __nv_bfloat16* hi, __nv_bfloat16* lo) {
    __nv_bfloat16 h = __float2bfloat16(v);
    *hi = h;
    *lo = __float2bfloat16(v - __bfloat162float(h));
}

// ---------------- asm helpers ------------------------------------------------
__device__ __forceinline__ void cp16(void* dst, const void* src) {
    uint32_t d = (uint32_t)__cvta_generic_to_shared(dst);
    asm volatile("cp.async.cg.shared.global [%0], [%1], 16;\n" :: "r"(d), "l"(src));
}
__device__ __forceinline__ void cp_commit() { asm volatile("cp.async.commit_group;\n"); }
__device__ __forceinline__ void cp_wait1()  { asm volatile("cp.async.wait_group 1;\n"); }
__device__ __forceinline__ void cp_wait0()  { asm volatile("cp.async.wait_group 0;\n"); }

__device__ __forceinline__ void ldm_x4(uint32_t* r, const void* p) {
    uint32_t a = (uint32_t)__cvta_generic_to_shared(p);
    asm volatile("ldmatrix.sync.aligned.m8n8.x4.shared.b16 {%0,%1,%2,%3}, [%4];"
                 : "=r"(r[0]), "=r"(r[1]), "=r"(r[2]), "=r"(r[3]) : "r"(a));
}

__device__ __forceinline__ void mma16816(float* c, const uint32_t* a, uint32_t b0, uint32_t b1) {
    asm volatile(
        "mma.sync.aligned.m16n8k16.row.col.f32.bf16.bf16.f32 "
        "{%0,%1,%2,%3}, {%4,%5,%6,%7}, {%8,%9}, {%0,%1,%2,%3};"
        : "+f"(c[0]), "+f"(c[1]), "+f"(c[2]), "+f"(c[3])
        : "r"(a[0]), "r"(a[1]), "r"(a[2]), "r"(a[3]), "r"(b0), "r"(b1));
}

// ---------------- prep -------------------------------------------------------
// prep_a: fused gate-permuted weights + bias.  row n -> j = (n&3)*512 + (n>>2)
__global__ void prep_a(const float* __restrict__ W_ih, const float* __restrict__ W_hh,
                       const float* __restrict__ b_ih, const float* __restrict__ b_hh) {
    int i = blockIdx.x * blockDim.x + threadIdx.x;
    int n = i >> 10, kc = i & 1023;
    int j = (n & 3) * 512 + (n >> 2);
    float w = (kc < IN) ? W_ih[j * IN + kc] : W_hh[j * H + (kc - IN)];
    bf16_split(w, &g_Whi[i], &g_Wlo[i]);
    if (i < NG) {
        int jb = (i & 3) * 512 + (i >> 2);
        g_bias[i] = b_ih[jb] + b_hh[jb];
    }
}

// prep_b: fused x->fp16, Wa->fp16, initial (zero-input, zero-state) cell
__global__ void prep_b(const float* __restrict__ x, const float* __restrict__ Wa) {
    int blk = blockIdx.x, tid = threadIdx.x;
    if (blk < 8192) {                                   // x: 8,388,608 half2
        size_t i = (size_t)blk * 1024 + tid;
        float2 v = ((const float2*)x)[i];
        g_x16[i] = __floats2half2_rn(v.x, v.y);
    } else if (blk < 8224) {                            // Wa: 32768 half2
        int i = (blk - 8192) * 1024 + tid;
        float2 v = ((const float2*)Wa)[i];
        g_Wa16[i] = __floats2half2_rn(v.x, v.y);
    } else {                                            // init: 128 blocks x 2 batches
        int b = (blk - 8224) * 2 + (tid >> 9);
        int k = tid & 511;
        float gi = g_bias[k * 4 + 0], gg = g_bias[k * 4 + 2], go = g_bias[k * 4 + 3];
        float c0 = sigf(gi) * tanhf(gg);
        float h0 = sigf(go) * tanhf(c0);
        g_c[b * H + k] = c0;
        bf16_split(h0, &g_Ahi[b * KK + IN + k], &g_Alo[b * KK + IN + k]);
    }
}

// ---------------- GEMM core: 32x64 tile, K=512 half --------------------------
// KOFF: column offset into A/W (0 = xi half, 512 = h half).
// FINAL=false: store raw partial gates. FINAL=true: add partial+bias, update.
template <int KOFF, bool FINAL>
__device__ __forceinline__ void gemm_half(char* smraw, int bidx, float* out, int t) {
    const int tid = threadIdx.x, lane = tid & 31, warp = tid >> 5;
    const int bn = bidx & 31, bm = bidx >> 5;           // 32 n-tiles x 8 m-tiles
    const int wm = (warp & 1) * 16, wn = (warp >> 1) * 16;

    // loaders: every thread: 1 A seg + Bh seg + Bl seg
    const int arow = (tid & 127) >> 2;                  // 0..31
    const int brow = tid >> 2;                          // 0..63
    const int seg  = tid & 3;
    const __nv_bfloat16* gA = ((tid < 128) ? g_Ahi : g_Alo)
                              + (size_t)(bm * 32 + arow) * KK + KOFF + seg * 8;
    const __nv_bfloat16* gBh = g_Whi + (size_t)(bn * 64 + brow) * KK + KOFF + seg * 8;
    const __nv_bfloat16* gBl = g_Wlo + (size_t)(bn * 64 + brow) * KK + KOFF + seg * 8;
    const int sAoff = arow * SST + seg * 8 + ((tid < 128) ? 0 : ASTG / 2);
    const int sBoff = brow * SST + seg * 8;

    float acc[2][4] = {};

    {
        char* base = smraw;
        cp16((__nv_bfloat16*)base + sAoff, gA);
        cp16((__nv_bfloat16*)(base + 2 * ASTG) + sBoff, gBh);
        cp16((__nv_bfloat16*)(base + 2 * ASTG + BSTG) + sBoff, gBl);
        cp_commit();
    }

    for (int ks = 0; ks < 16; ks++) {
        if (ks + 1 < 16) {
            char* base = smraw + ((ks + 1) & 1) * STGB;
            const int k0 = (ks + 1) * 32;
            cp16((__nv_bfloat16*)base + sAoff, gA + k0);
            cp16((__nv_bfloat16*)(base + 2 * ASTG) + sBoff, gBh + k0);
            cp16((__nv_bfloat16*)(base + 2 * ASTG + BSTG) + sBoff, gBl + k0);
            cp_commit();
            cp_wait1();
        } else {
            cp_wait0();
        }
        __syncthreads();

        char* base = smraw + (ks & 1) * STGB;
        const __nv_bfloat16* Ah = (const __nv_bfloat16*)base;
        const __nv_bfloat16* Al = (const __nv_bfloat16*)(base + ASTG);
        const __nv_bfloat16* Bh = (const __nv_bfloat16*)(base + 2 * ASTG);
        const __nv_bfloat16* Bl = (const __nv_bfloat16*)(base + 2 * ASTG + BSTG);

        #pragma unroll
        for (int kq = 0; kq < 2; kq++) {
            const int kb = kq * 16;
            uint32_t ah[4], al[4], bh[4], bl[4];
            const int ar = wm + (lane & 15), ac = kb + (lane >> 4) * 8;
            ldm_x4(ah, Ah + ar * SST + ac);
            ldm_x4(al, Al + ar * SST + ac);
            const int br = wn + (lane & 7) + ((lane >> 4) << 3);
            const int bc = kb + ((lane >> 3) & 1) * 8;
            ldm_x4(bh, Bh + br * SST + bc);
            ldm_x4(bl, Bl + br * SST + bc);
            #pragma unroll
            for (int ni = 0; ni < 2; ni++) {
                mma16816(acc[ni], ah, bh[ni * 2], bh[ni * 2 + 1]);   // hi*hi
                mma16816(acc[ni], ah, bl[ni * 2], bl[ni * 2 + 1]);   // hi*lo
                mma16816(acc[ni], al, bh[ni * 2], bh[ni * 2 + 1]);   // lo*hi
            }
        }
        __syncthreads();
    }

    if (!FINAL) {
        // store raw partial gates (fp32), direct from fragments
        #pragma unroll
        for (int ni = 0; ni < 2; ni++) {
            const int r = bm * 32 + wm + (lane >> 2);
            const int c = bn * 64 + wn + ni * 8 + (lane & 3) * 2;
            *(float2*)&g_gates[(size_t)r * NG + c]       = make_float2(acc[ni][0], acc[ni][1]);
            *(float2*)&g_gates[(size_t)(r + 8) * NG + c] = make_float2(acc[ni][2], acc[ni][3]);
        }
    } else {
        // stage to smem, then fused LSTM pointwise update
        float* gsm = (float*)smraw;                     // [32][68]
        #pragma unroll
        for (int ni = 0; ni < 2; ni++) {
            const int r = wm + (lane >> 2);
            const int c = wn + ni * 8 + (lane & 3) * 2;
            gsm[r * 68 + c]           = acc[ni][0];
            gsm[r * 68 + c + 1]       = acc[ni][1];
            gsm[(r + 8) * 68 + c]     = acc[ni][2];
            gsm[(r + 8) * 68 + c + 1] = acc[ni][3];
        }
        __syncthreads();

        const int kl = tid & 15;
        const int k  = bn * 16 + kl;
        #pragma unroll
        for (int j = 0; j < 2; j++) {
            const int bl = (tid >> 4) + j * 16;
            const int batch = bm * 32 + bl;
            float4 g4 = *(const float4*)&gsm[bl * 68 + kl * 4];
            float4 gp = *(const float4*)&g_gates[(size_t)batch * NG + k * 4];
            float gi = g4.x + gp.x + g_bias[k * 4 + 0];
            float gf = g4.y + gp.y + g_bias[k * 4 + 1];
            float gg = g4.z + gp.z + g_bias[k * 4 + 2];
            float go = g4.w + gp.w + g_bias[k * 4 + 3];
            float cold = g_c[batch * H + k];
            float cn = sigf(gf) * cold + sigf(gi) * tanhf(gg);
            float h  = sigf(go) * tanhf(cn);
            g_c[batch * H + k] = cn;
            bf16_split(h, &g_Ahi[batch * KK + IN + k], &g_Alo[batch * KK + IN + k]);
            out[((size_t)batch * SEQ + t) * H + k] = h;
        }
    }
}

// ---------------- attention body (one batch per block, 256 thr) --------------
struct AttnSmem {
    float c_sm[IN];
    float logit[SEQ];
    float attn[SEQ];
    float rmax[4], rsum[4];
};

__device__ __forceinline__ void attn_body(char* smraw, int b, const float* __restrict__ ba) {
    AttnSmem* s = (AttnSmem*)smraw;
    const int tid = threadIdx.x, lane = tid & 31, warp = tid >> 5;

    s->c_sm[tid]       = g_c[b * H + tid];
    s->c_sm[256 + tid] = g_c[b * H + 256 + tid];
    __syncthreads();

    float4 cf[4];
    #pragma unroll
    for (int j = 0; j < 4; j++) cf[j] = ((const float4*)s->c_sm)[j * 32 + lane];

    const uint2* wa = (const uint2*)g_Wa16;             // row stride 128 uint2
    #pragma unroll 2
    for (int si = 0; si < 16; si++) {
        const int sq = warp * 16 + si;
        const uint2* wp = wa + sq * 128;
        float acc = 0.0f;
        #pragma unroll
        for (int j = 0; j < 4; j++) {
            uint2 v = wp[j * 32 + lane];
            float2 w0 = __half22float2(*(const __half2*)&v.x);
            float2 w1 = __half22float2(*(const __half2*)&v.y);
            acc += cf[j].x * w0.x + cf[j].y * w0.y + cf[j].z * w1.x + cf[j].w * w1.y;
        }
        #pragma unroll
        for (int off = 16; off > 0; off >>= 1) acc += __shfl_xor_sync(0xffffffffu, acc, off);
        if (lane == 0) s->logit[sq] = acc + ba[sq];
    }
    __syncthreads();

    if (tid < 128) {
        float l = s->logit[tid], m = l;
        #pragma unroll
        for (int off = 16; off > 0; off >>= 1) m = fmaxf(m, __shfl_xor_sync(0xffffffffu, m, off));
        if (lane == 0) s->rmax[tid >> 5] = m;
    }
    __syncthreads();
    if (tid < 128) {
        float m = fmaxf(fmaxf(s->rmax[0], s->rmax[1]), fmaxf(s->rmax[2], s->rmax[3]));
        float e = expf(s->logit[tid] - m);
        s->attn[tid] = e;
        #pragma unroll
        for (int off = 16; off > 0; off >>= 1) e += __shfl_xor_sync(0xffffffffu, e, off);
        if (lane == 0) s->rsum[tid >> 5] = e;
    }
    __syncthreads();
    const float inv = 1.0f / (s->rsum[0] + s->rsum[1] + s->rsum[2] + s->rsum[3]);

    const __half2* xp = g_x16 + (size_t)b * SEQ * (IN/2) + tid;
    float ax = 0.0f, ay = 0.0f;
    #pragma unroll 16
    for (int sq = 0; sq < SEQ; sq++) {
        float a = s->attn[sq];
        float2 v = __half22float2(xp[sq * (IN/2)]);
        ax += a * v.x;
        ay += a * v.y;
    }
    ax *= inv; ay *= inv;
    const int d0 = tid * 2;
    bf16_split(ax, &g_Ahi[b * KK + d0],     &g_Alo[b * KK + d0]);
    bf16_split(ay, &g_Ahi[b * KK + d0 + 1], &g_Alo[b * KK + d0 + 1]);
}

// ---------------- per-step kernels -------------------------------------------
// K1: even blocks = h-half GEMM (256 tiles), odd blocks = attention (256 batches)
__global__ void __launch_bounds__(256) k1_hgemm_attn(const float* __restrict__ ba) {
    __shared__ __align__(16) char smraw[SMEM_BYTES];
    if ((blockIdx.x & 1) == 0) gemm_half<IN, false>(smraw, blockIdx.x >> 1, nullptr, 0);
    else                       attn_body(smraw, blockIdx.x >> 1, ba);
}

// K2: xi-half GEMM + fused update
__global__ void __launch_bounds__(256) k2_xgemm_update(float* __restrict__ out, int t) {
    __shared__ __align__(16) char smraw[SMEM_BYTES];
    gemm_half<0, true>(smraw, blockIdx.x, out, t);
}

// ---------------- launcher ----------------------------------------------------
extern "C" void kernel_launch(void* const* d_in, const int* in_sizes, int n_in,
                              void* d_out, int out_size) {
    const float* x    = (const float*)d_in[0];
    const float* W_ih = (const float*)d_in[1];
    const float* W_hh = (const float*)d_in[2];
    const float* b_ih = (const float*)d_in[3];
    const float* b_hh = (const float*)d_in[4];
    const float* Wa   = (const float*)d_in[5];
    const float* ba   = (const float*)d_in[6];
    float* out = (float*)d_out;

    prep_a<<<2048, 1024>>>(W_ih, W_hh, b_ih, b_hh);
    prep_b<<<8352, 1024>>>(x, Wa);

    for (int t = 0; t < SEQ; t++) {
        k1_hgemm_attn  <<<512, 256>>>(ba);
        k2_xgemm_update<<<256, 256>>>(out, t);
    }
}

// round 4
// speedup vs baseline: 1.9123x; 1.0926x over previous
#include <cuda_runtime.h>
#include <cuda_bf16.h>
#include <cuda_fp16.h>
#include <cstdint>

// ---------------------------------------------------------------------------
// LSTM with attention-weighted inputs.  B=256, SEQ=128, IN=H=512.
// Per step: attn=softmax(c@Wa^T+ba); xi=attn@x; gates=[xi|h]@Wf^T+b; update.
// Gate dim PERMUTED: column n = 4*k + gate.
//   K1: even blocks -> h-half GEMM (K=512..1023) writes partial gates (fp32)
//       odd  blocks -> attention + xi
//   K2: xi-half GEMM (K=0..511) + partial + bias -> fused LSTM update
// GEMM: bf16 3-term split, 3 independent accumulator banks (no mma chains),
// 3-stage cp.async pipeline with ONE __syncthreads per K-iteration.
// ---------------------------------------------------------------------------

#define BATCH 256
#define SEQ   128
#define IN    512
#define H     512
#define NG    2048
#define KK    1024
#define SST   40                 // smem row stride (bf16), conflict-free ldmatrix

// GEMM tiling: 32x64 tile, BK=32, 8 warps (warp tile 16x16), 3 stages
#define ASTG  2560               // 32*40*2
#define BSTG  5120               // 64*40*2
#define STGB  15360              // Ah+Al+Bh+Bl per stage
#define NSTAGE 3
#define SMEM_BYTES (NSTAGE * STGB)   // 46080

// ---------------- device scratch --------------------------------------------
__device__ __half2        g_x16 [BATCH * SEQ * (IN/2)];
__device__ __nv_bfloat16  g_Whi [NG * KK];
__device__ __nv_bfloat16  g_Wlo [NG * KK];
__device__ float          g_bias[NG];
__device__ __half2        g_Wa16[SEQ * (IN/2)];
__device__ float          g_c   [BATCH * H];
__device__ __nv_bfloat16  g_Ahi [BATCH * KK];
__device__ __nv_bfloat16  g_Alo [BATCH * KK];
__device__ float          g_gates[BATCH * NG];          // h-half partial

__device__ __forceinline__ float sigf(float x) { return 1.0f / (1.0f + expf(-x)); }

__device__ __forceinline__ void bf16_split(float v, __nv_bfloat16* hi, __nv_bfloat16* lo) {
    __nv_bfloat16 h = __float2bfloat16(v);
    *hi = h;
    *lo = __float2bfloat16(v - __bfloat162float(h));
}

// ---------------- asm helpers ------------------------------------------------
__device__ __forceinline__ void cp16(void* dst, const void* src) {
    uint32_t d = (uint32_t)__cvta_generic_to_shared(dst);
    asm volatile("cp.async.cg.shared.global [%0], [%1], 16;\n" :: "r"(d), "l"(src));
}
__device__ __forceinline__ void cp_commit() { asm volatile("cp.async.commit_group;\n"); }
__device__ __forceinline__ void cp_wait1()  { asm volatile("cp.async.wait_group 1;\n"); }
__device__ __forceinline__ void cp_wait0()  { asm volatile("cp.async.wait_group 0;\n"); }

__device__ __forceinline__ void ldm_x4(uint32_t* r, const void* p) {
    uint32_t a = (uint32_t)__cvta_generic_to_shared(p);
    asm volatile("ldmatrix.sync.aligned.m8n8.x4.shared.b16 {%0,%1,%2,%3}, [%4];"
                 : "=r"(r[0]), "=r"(r[1]), "=r"(r[2]), "=r"(r[3]) : "r"(a));
}

__device__ __forceinline__ void mma16816(float* c, const uint32_t* a, uint32_t b0, uint32_t b1) {
    asm volatile(
        "mma.sync.aligned.m16n8k16.row.col.f32.bf16.bf16.f32 "
        "{%0,%1,%2,%3}, {%4,%5,%6,%7}, {%8,%9}, {%0,%1,%2,%3};"
        : "+f"(c[0]), "+f"(c[1]), "+f"(c[2]), "+f"(c[3])
        : "r"(a[0]), "r"(a[1]), "r"(a[2]), "r"(a[3]), "r"(b0), "r"(b1));
}

// ---------------- prep -------------------------------------------------------
__global__ void prep_a(const float* __restrict__ W_ih, const float* __restrict__ W_hh,
                       const float* __restrict__ b_ih, const float* __restrict__ b_hh) {
    int i = blockIdx.x * blockDim.x + threadIdx.x;
    int n = i >> 10, kc = i & 1023;
    int j = (n & 3) * 512 + (n >> 2);
    float w = (kc < IN) ? W_ih[j * IN + kc] : W_hh[j * H + (kc - IN)];
    bf16_split(w, &g_Whi[i], &g_Wlo[i]);
    if (i < NG) {
        int jb = (i & 3) * 512 + (i >> 2);
        g_bias[i] = b_ih[jb] + b_hh[jb];
    }
}

__global__ void prep_b(const float* __restrict__ x, const float* __restrict__ Wa) {
    int blk = blockIdx.x, tid = threadIdx.x;
    if (blk < 8192) {
        size_t i = (size_t)blk * 1024 + tid;
        float2 v = ((const float2*)x)[i];
        g_x16[i] = __floats2half2_rn(v.x, v.y);
    } else if (blk < 8224) {
        int i = (blk - 8192) * 1024 + tid;
        float2 v = ((const float2*)Wa)[i];
        g_Wa16[i] = __floats2half2_rn(v.x, v.y);
    } else {
        int b = (blk - 8224) * 2 + (tid >> 9);
        int k = tid & 511;
        float gi = g_bias[k * 4 + 0], gg = g_bias[k * 4 + 2], go = g_bias[k * 4 + 3];
        float c0 = sigf(gi) * tanhf(gg);
        float h0 = sigf(go) * tanhf(c0);
        g_c[b * H + k] = c0;
        bf16_split(h0, &g_Ahi[b * KK + IN + k], &g_Alo[b * KK + IN + k]);
    }
}

// ---------------- GEMM core: 32x64 tile, K=512 half --------------------------
template <int KOFF, bool FINAL>
__device__ __forceinline__ void gemm_half(char* smraw, int bidx, float* out, int t) {
    const int tid = threadIdx.x, lane = tid & 31, warp = tid >> 5;
    const int bn = bidx & 31, bm = bidx >> 5;           // 32 n-tiles x 8 m-tiles
    const int wm = (warp & 1) * 16, wn = (warp >> 1) * 16;

    const int arow = (tid & 127) >> 2;
    const int brow = tid >> 2;
    const int seg  = tid & 3;
    const __nv_bfloat16* gA = ((tid < 128) ? g_Ahi : g_Alo)
                              + (size_t)(bm * 32 + arow) * KK + KOFF + seg * 8;
    const __nv_bfloat16* gBh = g_Whi + (size_t)(bn * 64 + brow) * KK + KOFF + seg * 8;
    const __nv_bfloat16* gBl = g_Wlo + (size_t)(bn * 64 + brow) * KK + KOFF + seg * 8;
    const int sAoff = arow * SST + seg * 8 + ((tid < 128) ? 0 : ASTG / 2);
    const int sBoff = brow * SST + seg * 8;

    // 3 independent accumulator banks: no dependent mma chains
    float hh[2][4] = {}, hl[2][4] = {}, lh[2][4] = {};

    auto issue_stage = [&](int ks) {
        char* base = smraw + (ks % NSTAGE) * STGB;
        const int k0 = ks * 32;
        cp16((__nv_bfloat16*)base + sAoff, gA + k0);
        cp16((__nv_bfloat16*)(base + 2 * ASTG) + sBoff, gBh + k0);
        cp16((__nv_bfloat16*)(base + 2 * ASTG + BSTG) + sBoff, gBl + k0);
        cp_commit();
    };
    issue_stage(0);
    issue_stage(1);

    for (int ks = 0; ks < 16; ks++) {
        if (ks < 15) cp_wait1(); else cp_wait0();
        __syncthreads();
        if (ks + 2 < 16) issue_stage(ks + 2);

        char* base = smraw + (ks % NSTAGE) * STGB;
        const __nv_bfloat16* Ah = (const __nv_bfloat16*)base;
        const __nv_bfloat16* Al = (const __nv_bfloat16*)(base + ASTG);
        const __nv_bfloat16* Bh = (const __nv_bfloat16*)(base + 2 * ASTG);
        const __nv_bfloat16* Bl = (const __nv_bfloat16*)(base + 2 * ASTG + BSTG);

        #pragma unroll
        for (int kq = 0; kq < 2; kq++) {
            const int kb = kq * 16;
            uint32_t ah[4], al[4], bh[4], bl[4];
            const int ar = wm + (lane & 15), ac = kb + (lane >> 4) * 8;
            ldm_x4(ah, Ah + ar * SST + ac);
            ldm_x4(al, Al + ar * SST + ac);
            const int br = wn + (lane & 7) + ((lane >> 4) << 3);
            const int bc = kb + ((lane >> 3) & 1) * 8;
            ldm_x4(bh, Bh + br * SST + bc);
            ldm_x4(bl, Bl + br * SST + bc);
            #pragma unroll
            for (int ni = 0; ni < 2; ni++) {
                mma16816(hh[ni], ah, bh[ni * 2], bh[ni * 2 + 1]);
                mma16816(hl[ni], ah, bl[ni * 2], bl[ni * 2 + 1]);
                mma16816(lh[ni], al, bh[ni * 2], bh[ni * 2 + 1]);
            }
        }
    }

    // merge banks
    float acc[2][4];
    #pragma unroll
    for (int ni = 0; ni < 2; ni++)
        #pragma unroll
        for (int j = 0; j < 4; j++)
            acc[ni][j] = hh[ni][j] + hl[ni][j] + lh[ni][j];

    if (!FINAL) {
        #pragma unroll
        for (int ni = 0; ni < 2; ni++) {
            const int r = bm * 32 + wm + (lane >> 2);
            const int c = bn * 64 + wn + ni * 8 + (lane & 3) * 2;
            *(float2*)&g_gates[(size_t)r * NG + c]       = make_float2(acc[ni][0], acc[ni][1]);
            *(float2*)&g_gates[(size_t)(r + 8) * NG + c] = make_float2(acc[ni][2], acc[ni][3]);
        }
    } else {
        __syncthreads();                                // smem reuse: all reads done
        float* gsm = (float*)smraw;                     // [32][68]
        #pragma unroll
        for (int ni = 0; ni < 2; ni++) {
            const int r = wm + (lane >> 2);
            const int c = wn + ni * 8 + (lane & 3) * 2;
            gsm[r * 68 + c]           = acc[ni][0];
            gsm[r * 68 + c + 1]       = acc[ni][1];
            gsm[(r + 8) * 68 + c]     = acc[ni][2];
            gsm[(r + 8) * 68 + c + 1] = acc[ni][3];
        }
        __syncthreads();

        const int kl = tid & 15;
        const int k  = bn * 16 + kl;
        #pragma unroll
        for (int j = 0; j < 2; j++) {
            const int bl = (tid >> 4) + j * 16;
            const int batch = bm * 32 + bl;
            float4 g4 = *(const float4*)&gsm[bl * 68 + kl * 4];
            float4 gp = *(const float4*)&g_gates[(size_t)batch * NG + k * 4];
            float gi = g4.x + gp.x + g_bias[k * 4 + 0];
            float gf = g4.y + gp.y + g_bias[k * 4 + 1];
            float gg = g4.z + gp.z + g_bias[k * 4 + 2];
            float go = g4.w + gp.w + g_bias[k * 4 + 3];
            float cold = g_c[batch * H + k];
            float cn = sigf(gf) * cold + sigf(gi) * tanhf(gg);
            float h  = sigf(go) * tanhf(cn);
            g_c[batch * H + k] = cn;
            bf16_split(h, &g_Ahi[batch * KK + IN + k], &g_Alo[batch * KK + IN + k]);
            out[((size_t)batch * SEQ + t) * H + k] = h;
        }
    }
}

// ---------------- attention body (one batch per block, 256 thr) --------------
struct AttnSmem {
    float c_sm[IN];
    float logit[SEQ];
    float attn[SEQ];
    float rmax[4], rsum[4];
};

__device__ __forceinline__ void attn_body(char* smraw, int b, const float* __restrict__ ba) {
    AttnSmem* s = (AttnSmem*)smraw;
    const int tid = threadIdx.x, lane = tid & 31, warp = tid >> 5;

    s->c_sm[tid]       = g_c[b * H + tid];
    s->c_sm[256 + tid] = g_c[b * H + 256 + tid];
    __syncthreads();

    float4 cf[4];
    #pragma unroll
    for (int j = 0; j < 4; j++) cf[j] = ((const float4*)s->c_sm)[j * 32 + lane];

    const uint2* wa = (const uint2*)g_Wa16;
    #pragma unroll 2
    for (int si = 0; si < 16; si++) {
        const int sq = warp * 16 + si;
        const uint2* wp = wa + sq * 128;
        float acc = 0.0f;
        #pragma unroll
        for (int j = 0; j < 4; j++) {
            uint2 v = wp[j * 32 + lane];
            float2 w0 = __half22float2(*(const __half2*)&v.x);
            float2 w1 = __half22float2(*(const __half2*)&v.y);
            acc += cf[j].x * w0.x + cf[j].y * w0.y + cf[j].z * w1.x + cf[j].w * w1.y;
        }
        #pragma unroll
        for (int off = 16; off > 0; off >>= 1) acc += __shfl_xor_sync(0xffffffffu, acc, off);
        if (lane == 0) s->logit[sq] = acc + ba[sq];
    }
    __syncthreads();

    if (tid < 128) {
        float l = s->logit[tid], m = l;
        #pragma unroll
        for (int off = 16; off > 0; off >>= 1) m = fmaxf(m, __shfl_xor_sync(0xffffffffu, m, off));
        if (lane == 0) s->rmax[tid >> 5] = m;
    }
    __syncthreads();
    if (tid < 128) {
        float m = fmaxf(fmaxf(s->rmax[0], s->rmax[1]), fmaxf(s->rmax[2], s->rmax[3]));
        float e = expf(s->logit[tid] - m);
        s->attn[tid] = e;
        #pragma unroll
        for (int off = 16; off > 0; off >>= 1) e += __shfl_xor_sync(0xffffffffu, e, off);
        if (lane == 0) s->rsum[tid >> 5] = e;
    }
    __syncthreads();
    const float inv = 1.0f / (s->rsum[0] + s->rsum[1] + s->rsum[2] + s->rsum[3]);

    const __half2* xp = g_x16 + (size_t)b * SEQ * (IN/2) + tid;
    float ax = 0.0f, ay = 0.0f;
    #pragma unroll 16
    for (int sq = 0; sq < SEQ; sq++) {
        float a = s->attn[sq];
        float2 v = __half22float2(xp[sq * (IN/2)]);
        ax += a * v.x;
        ay += a * v.y;
    }
    ax *= inv; ay *= inv;
    const int d0 = tid * 2;
    bf16_split(ax, &g_Ahi[b * KK + d0],     &g_Alo[b * KK + d0]);
    bf16_split(ay, &g_Ahi[b * KK + d0 + 1], &g_Alo[b * KK + d0 + 1]);
}

// ---------------- per-step kernels -------------------------------------------
__global__ void __launch_bounds__(256) k1_hgemm_attn(const float* __restrict__ ba) {
    __shared__ __align__(16) char smraw[SMEM_BYTES];
    if ((blockIdx.x & 1) == 0) gemm_half<IN, false>(smraw, blockIdx.x >> 1, nullptr, 0);
    else                       attn_body(smraw, blockIdx.x >> 1, ba);
}

__global__ void __launch_bounds__(256) k2_xgemm_update(float* __restrict__ out, int t) {
    __shared__ __align__(16) char smraw[SMEM_BYTES];
    gemm_half<0, true>(smraw, blockIdx.x, out, t);
}

// ---------------- launcher ----------------------------------------------------
extern "C" void kernel_launch(void* const* d_in, const int* in_sizes, int n_in,
                              void* d_out, int out_size) {
    const float* x    = (const float*)d_in[0];
    const float* W_ih = (const float*)d_in[1];
    const float* W_hh = (const float*)d_in[2];
    const float* b_ih = (const float*)d_in[3];
    const float* b_hh = (const float*)d_in[4];
    const float* Wa   = (const float*)d_in[5];
    const float* ba   = (const float*)d_in[6];
    float* out = (float*)d_out;

    prep_a<<<2048, 1024>>>(W_ih, W_hh, b_ih, b_hh);
    prep_b<<<8352, 1024>>>(x, Wa);

    for (int t = 0; t < SEQ; t++) {
        k1_hgemm_attn  <<<512, 256>>>(ba);
        k2_xgemm_update<<<256, 256>>>(out, t);
    }
}

// round 5
// speedup vs baseline: 1.9125x; 1.0001x over previous
#include <cuda_runtime.h>
#include <cuda_bf16.h>
#include <cuda_fp16.h>
#include <cstdint>

// ---------------------------------------------------------------------------
// LSTM with attention-weighted inputs.  B=256, SEQ=128, IN=H=512.
// Per step: attn=softmax(c@Wa^T+ba); xi=attn@x; gates=[xi|h]@Wf^T+b; update.
// Gate dim PERMUTED: column n = 4*k + gate.
//   K1: even blocks -> h-half GEMM (K=512..1023) writes partial gates (fp32)
//       odd  blocks -> attention + xi
//   K2: xi-half GEMM (K=0..511) + partial + bias -> fused LSTM update
// GEMM: bf16 3-term split, 3 independent accumulator banks (no mma chains),
// 3-stage cp.async pipeline with ONE __syncthreads per K-iteration.
// ---------------------------------------------------------------------------

#define BATCH 256
#define SEQ   128
#define IN    512
#define H     512
#define NG    2048
#define KK    1024
#define SST   40                 // smem row stride (bf16), conflict-free ldmatrix

// GEMM tiling: 32x64 tile, BK=32, 8 warps (warp tile 16x16), 3 stages
#define ASTG  2560               // 32*40*2
#define BSTG  5120               // 64*40*2
#define STGB  15360              // Ah+Al+Bh+Bl per stage
#define NSTAGE 3
#define SMEM_BYTES (NSTAGE * STGB)   // 46080

// ---------------- device scratch --------------------------------------------
__device__ __half2        g_x16 [BATCH * SEQ * (IN/2)];
__device__ __nv_bfloat16  g_Whi [NG * KK];
__device__ __nv_bfloat16  g_Wlo [NG * KK];
__device__ float          g_bias[NG];
__device__ __half2        g_Wa16[SEQ * (IN/2)];
__device__ float          g_c   [BATCH * H];
__device__ __nv_bfloat16  g_Ahi [BATCH * KK];
__device__ __nv_bfloat16  g_Alo [BATCH * KK];
__device__ float          g_gates[BATCH * NG];          // h-half partial

__device__ __forceinline__ float sigf(float x) { return 1.0f / (1.0f + expf(-x)); }

__device__ __forceinline__ void bf16_split(float v, __nv_bfloat16* hi, __nv_bfloat16* lo) {
    __nv_bfloat16 h = __float2bfloat16(v);
    *hi = h;
    *lo = __float2bfloat16(v - __bfloat162float(h));
}

// ---------------- asm helpers ------------------------------------------------
__device__ __forceinline__ void cp16(void* dst, const void* src) {
    uint32_t d = (uint32_t)__cvta_generic_to_shared(dst);
    asm volatile("cp.async.cg.shared.global [%0], [%1], 16;\n" :: "r"(d), "l"(src));
}
__device__ __forceinline__ void cp_commit() { asm volatile("cp.async.commit_group;\n"); }
__device__ __forceinline__ void cp_wait1()  { asm volatile("cp.async.wait_group 1;\n"); }
__device__ __forceinline__ void cp_wait0()  { asm volatile("cp.async.wait_group 0;\n"); }

__device__ __forceinline__ void ldm_x4(uint32_t* r, const void* p) {
    uint32_t a = (uint32_t)__cvta_generic_to_shared(p);
    asm volatile("ldmatrix.sync.aligned.m8n8.x4.shared.b16 {%0,%1,%2,%3}, [%4];"
                 : "=r"(r[0]), "=r"(r[1]), "=r"(r[2]), "=r"(r[3]) : "r"(a));
}

__device__ __forceinline__ void mma16816(float* c, const uint32_t* a, uint32_t b0, uint32_t b1) {
    asm volatile(
        "mma.sync.aligned.m16n8k16.row.col.f32.bf16.bf16.f32 "
        "{%0,%1,%2,%3}, {%4,%5,%6,%7}, {%8,%9}, {%0,%1,%2,%3};"
        : "+f"(c[0]), "+f"(c[1]), "+f"(c[2]), "+f"(c[3])
        : "r"(a[0]), "r"(a[1]), "r"(a[2]), "r"(a[3]), "r"(b0), "r"(b1));
}

// ---------------- prep -------------------------------------------------------
__global__ void prep_a(const float* __restrict__ W_ih, const float* __restrict__ W_hh,
                       const float* __restrict__ b_ih, const float* __restrict__ b_hh) {
    int i = blockIdx.x * blockDim.x + threadIdx.x;
    int n = i >> 10, kc = i & 1023;
    int j = (n & 3) * 512 + (n >> 2);
    float w = (kc < IN) ? W_ih[j * IN + kc] : W_hh[j * H + (kc - IN)];
    bf16_split(w, &g_Whi[i], &g_Wlo[i]);
    if (i < NG) {
        int jb = (i & 3) * 512 + (i >> 2);
        g_bias[i] = b_ih[jb] + b_hh[jb];
    }
}

__global__ void prep_b(const float* __restrict__ x, const float* __restrict__ Wa) {
    int blk = blockIdx.x, tid = threadIdx.x;
    if (blk < 8192) {
        size_t i = (size_t)blk * 1024 + tid;
        float2 v = ((const float2*)x)[i];
        g_x16[i] = __floats2half2_rn(v.x, v.y);
    } else if (blk < 8224) {
        int i = (blk - 8192) * 1024 + tid;
        float2 v = ((const float2*)Wa)[i];
        g_Wa16[i] = __floats2half2_rn(v.x, v.y);
    } else {
        int b = (blk - 8224) * 2 + (tid >> 9);
        int k = tid & 511;
        float gi = g_bias[k * 4 + 0], gg = g_bias[k * 4 + 2], go = g_bias[k * 4 + 3];
        float c0 = sigf(gi) * tanhf(gg);
        float h0 = sigf(go) * tanhf(c0);
        g_c[b * H + k] = c0;
        bf16_split(h0, &g_Ahi[b * KK + IN + k], &g_Alo[b * KK + IN + k]);
    }
}

// ---------------- GEMM core: 32x64 tile, K=512 half --------------------------
template <int KOFF, bool FINAL>
__device__ __forceinline__ void gemm_half(char* smraw, int bidx, float* out, int t) {
    const int tid = threadIdx.x, lane = tid & 31, warp = tid >> 5;
    const int bn = bidx & 31, bm = bidx >> 5;           // 32 n-tiles x 8 m-tiles
    const int wm = (warp & 1) * 16, wn = (warp >> 1) * 16;

    const int arow = (tid & 127) >> 2;
    const int brow = tid >> 2;
    const int seg  = tid & 3;
    const __nv_bfloat16* gA = ((tid < 128) ? g_Ahi : g_Alo)
                              + (size_t)(bm * 32 + arow) * KK + KOFF + seg * 8;
    const __nv_bfloat16* gBh = g_Whi + (size_t)(bn * 64 + brow) * KK + KOFF + seg * 8;
    const __nv_bfloat16* gBl = g_Wlo + (size_t)(bn * 64 + brow) * KK + KOFF + seg * 8;
    const int sAoff = arow * SST + seg * 8 + ((tid < 128) ? 0 : ASTG / 2);
    const int sBoff = brow * SST + seg * 8;

    // 3 independent accumulator banks: no dependent mma chains
    float hh[2][4] = {}, hl[2][4] = {}, lh[2][4] = {};

    auto issue_stage = [&](int ks) {
        char* base = smraw + (ks % NSTAGE) * STGB;
        const int k0 = ks * 32;
        cp16((__nv_bfloat16*)base + sAoff, gA + k0);
        cp16((__nv_bfloat16*)(base + 2 * ASTG) + sBoff, gBh + k0);
        cp16((__nv_bfloat16*)(base + 2 * ASTG + BSTG) + sBoff, gBl + k0);
        cp_commit();
    };
    issue_stage(0);
    issue_stage(1);

    for (int ks = 0; ks < 16; ks++) {
        if (ks < 15) cp_wait1(); else cp_wait0();
        __syncthreads();
        if (ks + 2 < 16) issue_stage(ks + 2);

        char* base = smraw + (ks % NSTAGE) * STGB;
        const __nv_bfloat16* Ah = (const __nv_bfloat16*)base;
        const __nv_bfloat16* Al = (const __nv_bfloat16*)(base + ASTG);
        const __nv_bfloat16* Bh = (const __nv_bfloat16*)(base + 2 * ASTG);
        const __nv_bfloat16* Bl = (const __nv_bfloat16*)(base + 2 * ASTG + BSTG);

        #pragma unroll
        for (int kq = 0; kq < 2; kq++) {
            const int kb = kq * 16;
            uint32_t ah[4], al[4], bh[4], bl[4];
            const int ar = wm + (lane & 15), ac = kb + (lane >> 4) * 8;
            ldm_x4(ah, Ah + ar * SST + ac);
            ldm_x4(al, Al + ar * SST + ac);
            const int br = wn + (lane & 7) + ((lane >> 4) << 3);
            const int bc = kb + ((lane >> 3) & 1) * 8;
            ldm_x4(bh, Bh + br * SST + bc);
            ldm_x4(bl, Bl + br * SST + bc);
            #pragma unroll
            for (int ni = 0; ni < 2; ni++) {
                mma16816(hh[ni], ah, bh[ni * 2], bh[ni * 2 + 1]);
                mma16816(hl[ni], ah, bl[ni * 2], bl[ni * 2 + 1]);
                mma16816(lh[ni], al, bh[ni * 2], bh[ni * 2 + 1]);
            }
        }
    }

    // merge banks
    float acc[2][4];
    #pragma unroll
    for (int ni = 0; ni < 2; ni++)
        #pragma unroll
        for (int j = 0; j < 4; j++)
            acc[ni][j] = hh[ni][j] + hl[ni][j] + lh[ni][j];

    if (!FINAL) {
        #pragma unroll
        for (int ni = 0; ni < 2; ni++) {
            const int r = bm * 32 + wm + (lane >> 2);
            const int c = bn * 64 + wn + ni * 8 + (lane & 3) * 2;
            *(float2*)&g_gates[(size_t)r * NG + c]       = make_float2(acc[ni][0], acc[ni][1]);
            *(float2*)&g_gates[(size_t)(r + 8) * NG + c] = make_float2(acc[ni][2], acc[ni][3]);
        }
    } else {
        __syncthreads();                                // smem reuse: all reads done
        float* gsm = (float*)smraw;                     // [32][68]
        #pragma unroll
        for (int ni = 0; ni < 2; ni++) {
            const int r = wm + (lane >> 2);
            const int c = wn + ni * 8 + (lane & 3) * 2;
            gsm[r * 68 + c]           = acc[ni][0];
            gsm[r * 68 + c + 1]       = acc[ni][1];
            gsm[(r + 8) * 68 + c]     = acc[ni][2];
            gsm[(r + 8) * 68 + c + 1] = acc[ni][3];
        }
        __syncthreads();

        const int kl = tid & 15;
        const int k  = bn * 16 + kl;
        #pragma unroll
        for (int j = 0; j < 2; j++) {
            const int bl = (tid >> 4) + j * 16;
            const int batch = bm * 32 + bl;
            float4 g4 = *(const float4*)&gsm[bl * 68 + kl * 4];
            float4 gp = *(const float4*)&g_gates[(size_t)batch * NG + k * 4];
            float gi = g4.x + gp.x + g_bias[k * 4 + 0];
            float gf = g4.y + gp.y + g_bias[k * 4 + 1];
            float gg = g4.z + gp.z + g_bias[k * 4 + 2];
            float go = g4.w + gp.w + g_bias[k * 4 + 3];
            float cold = g_c[batch * H + k];
            float cn = sigf(gf) * cold + sigf(gi) * tanhf(gg);
            float h  = sigf(go) * tanhf(cn);
            g_c[batch * H + k] = cn;
            bf16_split(h, &g_Ahi[batch * KK + IN + k], &g_Alo[batch * KK + IN + k]);
            out[((size_t)batch * SEQ + t) * H + k] = h;
        }
    }
}

// ---------------- attention body (one batch per block, 256 thr) --------------
struct AttnSmem {
    float c_sm[IN];
    float logit[SEQ];
    float attn[SEQ];
    float rmax[4], rsum[4];
};

__device__ __forceinline__ void attn_body(char* smraw, int b, const float* __restrict__ ba) {
    AttnSmem* s = (AttnSmem*)smraw;
    const int tid = threadIdx.x, lane = tid & 31, warp = tid >> 5;

    s->c_sm[tid]       = g_c[b * H + tid];
    s->c_sm[256 + tid] = g_c[b * H + 256 + tid];
    __syncthreads();

    float4 cf[4];
    #pragma unroll
    for (int j = 0; j < 4; j++) cf[j] = ((const float4*)s->c_sm)[j * 32 + lane];

    const uint2* wa = (const uint2*)g_Wa16;
    #pragma unroll 2
    for (int si = 0; si < 16; si++) {
        const int sq = warp * 16 + si;
        const uint2* wp = wa + sq * 128;
        float acc = 0.0f;
        #pragma unroll
        for (int j = 0; j < 4; j++) {
            uint2 v = wp[j * 32 + lane];
            float2 w0 = __half22float2(*(const __half2*)&v.x);
            float2 w1 = __half22float2(*(const __half2*)&v.y);
            acc += cf[j].x * w0.x + cf[j].y * w0.y + cf[j].z * w1.x + cf[j].w * w1.y;
        }
        #pragma unroll
        for (int off = 16; off > 0; off >>= 1) acc += __shfl_xor_sync(0xffffffffu, acc, off);
        if (lane == 0) s->logit[sq] = acc + ba[sq];
    }
    __syncthreads();

    if (tid < 128) {
        float l = s->logit[tid], m = l;
        #pragma unroll
        for (int off = 16; off > 0; off >>= 1) m = fmaxf(m, __shfl_xor_sync(0xffffffffu, m, off));
        if (lane == 0) s->rmax[tid >> 5] = m;
    }
    __syncthreads();
    if (tid < 128) {
        float m = fmaxf(fmaxf(s->rmax[0], s->rmax[1]), fmaxf(s->rmax[2], s->rmax[3]));
        float e = expf(s->logit[tid] - m);
        s->attn[tid] = e;
        #pragma unroll
        for (int off = 16; off > 0; off >>= 1) e += __shfl_xor_sync(0xffffffffu, e, off);
        if (lane == 0) s->rsum[tid >> 5] = e;
    }
    __syncthreads();
    const float inv = 1.0f / (s->rsum[0] + s->rsum[1] + s->rsum[2] + s->rsum[3]);

    const __half2* xp = g_x16 + (size_t)b * SEQ * (IN/2) + tid;
    float ax = 0.0f, ay = 0.0f;
    #pragma unroll 16
    for (int sq = 0; sq < SEQ; sq++) {
        float a = s->attn[sq];
        float2 v = __half22float2(xp[sq * (IN/2)]);
        ax += a * v.x;
        ay += a * v.y;
    }
    ax *= inv; ay *= inv;
    const int d0 = tid * 2;
    bf16_split(ax, &g_Ahi[b * KK + d0],     &g_Alo[b * KK + d0]);
    bf16_split(ay, &g_Ahi[b * KK + d0 + 1], &g_Alo[b * KK + d0 + 1]);
}

// ---------------- per-step kernels -------------------------------------------
__global__ void __launch_bounds__(256) k1_hgemm_attn(const float* __restrict__ ba) {
    __shared__ __align__(16) char smraw[SMEM_BYTES];
    if ((blockIdx.x & 1) == 0) gemm_half<IN, false>(smraw, blockIdx.x >> 1, nullptr, 0);
    else                       attn_body(smraw, blockIdx.x >> 1, ba);
}

__global__ void __launch_bounds__(256) k2_xgemm_update(float* __restrict__ out, int t) {
    __shared__ __align__(16) char smraw[SMEM_BYTES];
    gemm_half<0, true>(smraw, blockIdx.x, out, t);
}

// ---------------- launcher ----------------------------------------------------
extern "C" void kernel_launch(void* const* d_in, const int* in_sizes, int n_in,
                              void* d_out, int out_size) {
    const float* x    = (const float*)d_in[0];
    const float* W_ih = (const float*)d_in[1];
    const float* W_hh = (const float*)d_in[2];
    const float* b_ih = (const float*)d_in[3];
    const float* b_hh = (const float*)d_in[4];
    const float* Wa   = (const float*)d_in[5];
    const float* ba   = (const float*)d_in[6];
    float* out = (float*)d_out;

    prep_a<<<2048, 1024>>>(W_ih, W_hh, b_ih, b_hh);
    prep_b<<<8352, 1024>>>(x, Wa);

    for (int t = 0; t < SEQ; t++) {
        k1_hgemm_attn  <<<512, 256>>>(ba);
        k2_xgemm_update<<<256, 256>>>(out, t);
    }
}

// round 6
// speedup vs baseline: 2.2079x; 1.1544x over previous
#include <cuda_runtime.h>
#include <cuda_bf16.h>
#include <cuda_fp16.h>
#include <cstdint>

// ---------------------------------------------------------------------------
// LSTM with attention-weighted inputs.  B=256, SEQ=128, IN=H=512.
// Gate dim PERMUTED: column n = 4*k + gate.
// A ([xi|h], bf16 hi/lo) and W (fused weights, bf16 hi/lo) live in gmem as
// PRE-SWIZZLED (SW128) 64row x 128B tiles -> K-stages load with cp.async.bulk.
//   k1: blocks 0..127  h-half GEMM (K=512..1023) -> partial gates + bias
//       blocks 128..383 attention + xi (writes xi tiles, stages 0..7)
//   k2: xi-half GEMM (K=0..511) + partial -> fused LSTM update, h tiles out.
// GEMM: mma.sync bf16 3-term split (fp32-grade), 3 acc banks, 3-stage bulk
// pipeline (mbarrier full + __syncthreads reuse), 1 elected producer thread.
// ---------------------------------------------------------------------------

#define BATCH 256
#define SEQ   128
#define IN    512
#define H     512
#define NG    2048
#define TILE  8192                 // 64 rows x 128B, swizzled
#define STGB  32768                // Ah+Al+Bh+Bl per stage
#define DSMEM 98304                // 3 stages

__device__ unsigned char g_AhiT[4 * 16 * TILE];    // [mblk][stage] 512KB
__device__ unsigned char g_AloT[4 * 16 * TILE];
__device__ unsigned char g_WhiT[32 * 16 * TILE];   // [nblk][stage] 4MB
__device__ unsigned char g_WloT[32 * 16 * TILE];
__device__ float         g_bias[NG];
__device__ __half2       g_x16 [BATCH * SEQ * (IN/2)];
__device__ __half2       g_Wa16[SEQ * (IN/2)];
__device__ float         g_c   [BATCH * H];
__device__ float         g_gates[BATCH * NG];      // h-half partial (+bias)

__device__ __forceinline__ uint32_t swz(uint32_t o) { return o ^ ((o >> 3) & 0x70u); }
__device__ __forceinline__ float sigf(float x) { return 1.0f / (1.0f + expf(-x)); }

__device__ __forceinline__ uint32_t smem_u32(const void* p) {
    uint32_t a;
    asm("{ .reg .u64 t; cvta.to.shared.u64 t, %1; cvt.u32.u64 %0, t; }" : "=r"(a) : "l"(p));
    return a;
}
#define MBAR_INIT(a, n) asm volatile("mbarrier.init.shared.b64 [%0], %1;" :: "r"(a), "r"(n) : "memory")
#define MBAR_EXPECT_TX(a, b) asm volatile("mbarrier.arrive.expect_tx.shared.b64 _, [%0], %1;" :: "r"(a), "r"(b) : "memory")
#define MBAR_WAIT(a, par) do { \
    asm volatile("{ .reg .pred P; WL%=: mbarrier.try_wait.parity.acquire.cta.shared::cta.b64 P, [%0], %1, 0x989680; @P bra.uni WD%=; bra.uni WL%=; WD%=: }" \
                 :: "r"(a), "r"(par) : "memory"); } while (0)

__device__ __forceinline__ void bulk_g2s(uint32_t dst, const void* src, uint32_t mbar) {
    asm volatile("cp.async.bulk.shared::cluster.global.mbarrier::complete_tx::bytes [%0], [%1], %2, [%3];"
                 :: "r"(dst), "l"(src), "n"(TILE), "r"(mbar) : "memory");
}

__device__ __forceinline__ void ldm_x4(uint32_t* r, const void* p) {
    uint32_t a = smem_u32(p);
    asm volatile("ldmatrix.sync.aligned.m8n8.x4.shared.b16 {%0,%1,%2,%3}, [%4];"
                 : "=r"(r[0]), "=r"(r[1]), "=r"(r[2]), "=r"(r[3]) : "r"(a));
}
__device__ __forceinline__ void mma16816(float* c, const uint32_t* a, uint32_t b0, uint32_t b1) {
    asm volatile(
        "mma.sync.aligned.m16n8k16.row.col.f32.bf16.bf16.f32 "
        "{%0,%1,%2,%3}, {%4,%5,%6,%7}, {%8,%9}, {%0,%1,%2,%3};"
        : "+f"(c[0]), "+f"(c[1]), "+f"(c[2]), "+f"(c[3])
        : "r"(a[0]), "r"(a[1]), "r"(a[2]), "r"(a[3]), "r"(b0), "r"(b1));
}

// ---------------- prep ---------------------------------------------------------
__global__ void prep_a(const float* __restrict__ W_ih, const float* __restrict__ W_hh,
                       const float* __restrict__ b_ih, const float* __restrict__ b_hh) {
    int i = blockIdx.x * blockDim.x + threadIdx.x;      // 2,097,152
    int n = i >> 10, kc = i & 1023;
    int j = (n & 3) * 512 + (n >> 2);
    float w = (kc < IN) ? W_ih[j * IN + kc] : W_hh[j * H + (kc - IN)];
    __nv_bfloat16 hi = __float2bfloat16(w);
    __nv_bfloat16 lo = __float2bfloat16(w - __bfloat162float(hi));
    uint32_t off = (uint32_t)((n >> 6) * 16 + (kc >> 6)) * TILE + swz((n & 63) * 128 + (kc & 63) * 2);
    *(__nv_bfloat16*)(g_WhiT + off) = hi;
    *(__nv_bfloat16*)(g_WloT + off) = lo;
    if (i < NG) {
        int jb = (i & 3) * 512 + (i >> 2);
        g_bias[i] = b_ih[jb] + b_hh[jb];
    }
}

__global__ void prep_b(const float* __restrict__ x, const float* __restrict__ Wa) {
    int blk = blockIdx.x, tid = threadIdx.x;
    if (blk < 8192) {
        size_t i = (size_t)blk * 1024 + tid;
        float2 v = ((const float2*)x)[i];
        g_x16[i] = __floats2half2_rn(v.x, v.y);
    } else if (blk < 8224) {
        int i = (blk - 8192) * 1024 + tid;
        float2 v = ((const float2*)Wa)[i];
        g_Wa16[i] = __floats2half2_rn(v.x, v.y);
    } else {                                            // zero-input initial cell
        int b = (blk - 8224) * 2 + (tid >> 9);
        int k = tid & 511;
        float gi = g_bias[k * 4 + 0], gg = g_bias[k * 4 + 2], go = g_bias[k * 4 + 3];
        float c0 = sigf(gi) * tanhf(gg);
        float h0 = sigf(go) * tanhf(c0);
        g_c[b * H + k] = c0;
        __nv_bfloat16 hi = __float2bfloat16(h0);
        __nv_bfloat16 lo = __float2bfloat16(h0 - __bfloat162float(hi));
        uint32_t off = (uint32_t)((b >> 6) * 16 + 8 + (k >> 6)) * TILE + swz((b & 63) * 128 + (k & 63) * 2);
        *(__nv_bfloat16*)(g_AhiT + off) = hi;
        *(__nv_bfloat16*)(g_AloT + off) = lo;
    }
}

// ---------------- GEMM core: 64x64 tile, BK=64, bulk pipeline -----------------
template <int ST0, bool FINAL>
__device__ __forceinline__ void gemm_core(unsigned char* sm, int bidx, float* out, int t) {
    __shared__ __align__(8) uint64_t mbar[3];
    const int tid = threadIdx.x, lane = tid & 31, warp = tid >> 5;
    const int bn = bidx & 31, bm = bidx >> 5;           // 32 n x 4 m
    const int wm = (warp & 1) * 32, wn = (warp >> 1) * 16;

    if (tid == 0) {
        MBAR_INIT(smem_u32(&mbar[0]), 1);
        MBAR_INIT(smem_u32(&mbar[1]), 1);
        MBAR_INIT(smem_u32(&mbar[2]), 1);
    }
    __syncthreads();

    const unsigned char* sAh = g_AhiT + (bm * 16 + ST0) * TILE;
    const unsigned char* sAl = g_AloT + (bm * 16 + ST0) * TILE;
    const unsigned char* sBh = g_WhiT + (bn * 16 + ST0) * TILE;
    const unsigned char* sBl = g_WloT + (bn * 16 + ST0) * TILE;
    const uint32_t smb = smem_u32(sm);

    auto prefetch = [&](int s) {
        uint32_t bar = smem_u32(&mbar[s % 3]);
        uint32_t d = smb + (s % 3) * STGB;
        MBAR_EXPECT_TX(bar, STGB);
        bulk_g2s(d,                 sAh + s * TILE, bar);
        bulk_g2s(d + TILE,          sAl + s * TILE, bar);
        bulk_g2s(d + 2 * TILE,      sBh + s * TILE, bar);
        bulk_g2s(d + 3 * TILE,      sBl + s * TILE, bar);
    };
    if (tid == 0) { prefetch(0); prefetch(1); }

    float hh[2][2][4] = {}, hl[2][2][4] = {}, lh[2][2][4] = {};

    for (int s = 0; s < 8; s++) {
        if (tid == 0 && s + 2 < 8) prefetch(s + 2);     // buffer freed by prev sync
        MBAR_WAIT(smem_u32(&mbar[s % 3]), (s / 3) & 1);
        unsigned char* buf = sm + (s % 3) * STGB;
        const unsigned char* Ah = buf;
        const unsigned char* Al = buf + TILE;
        const unsigned char* Bh = buf + 2 * TILE;
        const unsigned char* Bl = buf + 3 * TILE;

        #pragma unroll
        for (int kq = 0; kq < 4; kq++) {
            const int kb = kq * 16;
            uint32_t fah[2][4], fal[2][4], fbh[4], fbl[4];
            const int ar = wm + (lane & 15);
            const uint32_t ac = (kb + (lane >> 4) * 8) * 2;
            #pragma unroll
            for (int mi = 0; mi < 2; mi++) {
                uint32_t o = swz((ar + mi * 16) * 128 + ac);
                ldm_x4(fah[mi], Ah + o);
                ldm_x4(fal[mi], Al + o);
            }
            const int br = wn + (lane & 7) + ((lane >> 4) << 3);
            const uint32_t ob = swz(br * 128 + (kb + ((lane >> 3) & 1) * 8) * 2);
            ldm_x4(fbh, Bh + ob);
            ldm_x4(fbl, Bl + ob);
            #pragma unroll
            for (int mi = 0; mi < 2; mi++)
                #pragma unroll
                for (int ni = 0; ni < 2; ni++) {
                    mma16816(hh[mi][ni], fah[mi], fbh[ni * 2], fbh[ni * 2 + 1]);
                    mma16816(hl[mi][ni], fah[mi], fbl[ni * 2], fbl[ni * 2 + 1]);
                    mma16816(lh[mi][ni], fal[mi], fbh[ni * 2], fbh[ni * 2 + 1]);
                }
        }
        __syncthreads();
    }

    float acc[2][2][4];
    #pragma unroll
    for (int mi = 0; mi < 2; mi++)
        #pragma unroll
        for (int ni = 0; ni < 2; ni++)
            #pragma unroll
            for (int j = 0; j < 4; j++)
                acc[mi][ni][j] = hh[mi][ni][j] + hl[mi][ni][j] + lh[mi][ni][j];

    if (!FINAL) {
        #pragma unroll
        for (int mi = 0; mi < 2; mi++)
            #pragma unroll
            for (int ni = 0; ni < 2; ni++) {
                const int r = bm * 64 + wm + mi * 16 + (lane >> 2);
                const int c = bn * 64 + wn + ni * 8 + (lane & 3) * 2;
                const float b0 = g_bias[c], b1 = g_bias[c + 1];
                *(float2*)&g_gates[(size_t)r * NG + c] =
                    make_float2(acc[mi][ni][0] + b0, acc[mi][ni][1] + b1);
                *(float2*)&g_gates[(size_t)(r + 8) * NG + c] =
                    make_float2(acc[mi][ni][2] + b0, acc[mi][ni][3] + b1);
            }
    } else {
        float* gsm = (float*)sm;                        // [64][68]
        #pragma unroll
        for (int mi = 0; mi < 2; mi++)
            #pragma unroll
            for (int ni = 0; ni < 2; ni++) {
                const int r = wm + mi * 16 + (lane >> 2);
                const int c = wn + ni * 8 + (lane & 3) * 2;
                gsm[r * 68 + c]           = acc[mi][ni][0];
                gsm[r * 68 + c + 1]       = acc[mi][ni][1];
                gsm[(r + 8) * 68 + c]     = acc[mi][ni][2];
                gsm[(r + 8) * 68 + c + 1] = acc[mi][ni][3];
            }
        __syncthreads();

        const int kl = tid & 15;
        const int k  = bn * 16 + kl;
        const uint32_t tbase = ((uint32_t)bm * 16 + 8 + (k >> 6)) * TILE;  // h stage
        #pragma unroll
        for (int j = 0; j < 4; j++) {
            const int bl = (tid >> 4) + j * 16;
            const int batch = bm * 64 + bl;
            float4 g4 = *(const float4*)&gsm[bl * 68 + kl * 4];
            float4 gp = *(const float4*)&g_gates[(size_t)batch * NG + bn * 64 + kl * 4];
            float gi = g4.x + gp.x, gf = g4.y + gp.y, gg = g4.z + gp.z, go = g4.w + gp.w;
            float cold = g_c[batch * H + k];
            float cn = sigf(gf) * cold + sigf(gi) * tanhf(gg);
            float h  = sigf(go) * tanhf(cn);
            g_c[batch * H + k] = cn;
            __nv_bfloat16 hi = __float2bfloat16(h);
            __nv_bfloat16 lo = __float2bfloat16(h - __bfloat162float(hi));
            uint32_t off = tbase + swz(bl * 128 + (k & 63) * 2);
            *(__nv_bfloat16*)(g_AhiT + off) = hi;
            *(__nv_bfloat16*)(g_AloT + off) = lo;
            out[((size_t)batch * SEQ + t) * H + k] = h;
        }
    }
}

// ---------------- attention body (one batch per block, 256 thr) ---------------
struct AttnS {
    float c_sm[IN];
    float logit[SEQ], attn[SEQ];
    float rmax[4], rsum[4];
    float xpart[4][IN];
};

__device__ __forceinline__ void attn_body(unsigned char* dyn, int b, const float* __restrict__ ba) {
    AttnS* s = (AttnS*)dyn;
    const int tid = threadIdx.x, lane = tid & 31, warp = tid >> 5;

    s->c_sm[tid]       = g_c[b * H + tid];
    s->c_sm[256 + tid] = g_c[b * H + 256 + tid];
    __syncthreads();

    float4 cf[4];
    #pragma unroll
    for (int j = 0; j < 4; j++) cf[j] = ((const float4*)s->c_sm)[j * 32 + lane];

    const uint2* wa = (const uint2*)g_Wa16;
    #pragma unroll 2
    for (int si = 0; si < 16; si++) {
        const int sq = warp * 16 + si;
        const uint2* wp = wa + sq * 128;
        float acc = 0.0f;
        #pragma unroll
        for (int j = 0; j < 4; j++) {
            uint2 v = wp[j * 32 + lane];
            float2 w0 = __half22float2(*(const __half2*)&v.x);
            float2 w1 = __half22float2(*(const __half2*)&v.y);
            acc += cf[j].x * w0.x + cf[j].y * w0.y + cf[j].z * w1.x + cf[j].w * w1.y;
        }
        #pragma unroll
        for (int off = 16; off > 0; off >>= 1) acc += __shfl_xor_sync(0xffffffffu, acc, off);
        if (lane == 0) s->logit[sq] = acc + ba[sq];
    }
    __syncthreads();

    if (tid < 128) {
        float l = s->logit[tid], m = l;
        #pragma unroll
        for (int off = 16; off > 0; off >>= 1) m = fmaxf(m, __shfl_xor_sync(0xffffffffu, m, off));
        if (lane == 0) s->rmax[tid >> 5] = m;
    }
    __syncthreads();
    if (tid < 128) {
        float m = fmaxf(fmaxf(s->rmax[0], s->rmax[1]), fmaxf(s->rmax[2], s->rmax[3]));
        float e = expf(s->logit[tid] - m);
        s->attn[tid] = e;
        #pragma unroll
        for (int off = 16; off > 0; off >>= 1) e += __shfl_xor_sync(0xffffffffu, e, off);
        if (lane == 0) s->rsum[tid >> 5] = e;
    }
    __syncthreads();
    const float inv = 1.0f / (s->rsum[0] + s->rsum[1] + s->rsum[2] + s->rsum[3]);

    // xi: 4 seq-groups x 64 col-threads, uint4 loads (8 halves)
    {
        const int g = tid >> 6, cth = tid & 63;
        const uint4* xp = ((const uint4*)g_x16) + (size_t)b * SEQ * 64 + cth;
        float acc[8] = {};
        #pragma unroll 4
        for (int i = 0; i < 32; i++) {
            const int sq = g * 32 + i;
            const float a = s->attn[sq];
            uint4 v = xp[(size_t)sq * 64];
            float2 p0 = __half22float2(*(const __half2*)&v.x);
            float2 p1 = __half22float2(*(const __half2*)&v.y);
            float2 p2 = __half22float2(*(const __half2*)&v.z);
            float2 p3 = __half22float2(*(const __half2*)&v.w);
            acc[0] += a * p0.x; acc[1] += a * p0.y;
            acc[2] += a * p1.x; acc[3] += a * p1.y;
            acc[4] += a * p2.x; acc[5] += a * p2.y;
            acc[6] += a * p3.x; acc[7] += a * p3.y;
        }
        #pragma unroll
        for (int q = 0; q < 8; q++) s->xpart[g][cth * 8 + q] = acc[q];
    }
    __syncthreads();

    {
        const int d0 = tid * 2;
        float v0 = (s->xpart[0][d0]   + s->xpart[1][d0])   + (s->xpart[2][d0]   + s->xpart[3][d0]);
        float v1 = (s->xpart[0][d0+1] + s->xpart[1][d0+1]) + (s->xpart[2][d0+1] + s->xpart[3][d0+1]);
        v0 *= inv; v1 *= inv;
        __nv_bfloat16 h0 = __float2bfloat16(v0);
        __nv_bfloat16 l0 = __float2bfloat16(v0 - __bfloat162float(h0));
        __nv_bfloat16 h1 = __float2bfloat16(v1);
        __nv_bfloat16 l1 = __float2bfloat16(v1 - __bfloat162float(h1));
        uint32_t off = ((uint32_t)(b >> 6) * 16 + (d0 >> 6)) * TILE + swz((b & 63) * 128 + (d0 & 63) * 2);
        *(__nv_bfloat162*)(g_AhiT + off) = __nv_bfloat162(h0, h1);
        *(__nv_bfloat162*)(g_AloT + off) = __nv_bfloat162(l0, l1);
    }
}

// ---------------- per-step kernels ---------------------------------------------
__global__ void __launch_bounds__(256) k1_hgemm_attn(const float* __restrict__ ba) {
    extern __shared__ unsigned char dyn[];
    if (blockIdx.x < 128) gemm_core<8, false>(dyn, blockIdx.x, nullptr, 0);
    else                  attn_body(dyn, blockIdx.x - 128, ba);
}

__global__ void __launch_bounds__(256) k2_xgemm_update(float* __restrict__ out, int t) {
    extern __shared__ unsigned char dyn[];
    gemm_core<0, true>(dyn, blockIdx.x, out, t);
}

// ---------------- launcher -------------------------------------------------------
extern "C" void kernel_launch(void* const* d_in, const int* in_sizes, int n_in,
                              void* d_out, int out_size) {
    const float* x    = (const float*)d_in[0];
    const float* W_ih = (const float*)d_in[1];
    const float* W_hh = (const float*)d_in[2];
    const float* b_ih = (const float*)d_in[3];
    const float* b_hh = (const float*)d_in[4];
    const float* Wa   = (const float*)d_in[5];
    const float* ba   = (const float*)d_in[6];
    float* out = (float*)d_out;

    cudaFuncSetAttribute(k1_hgemm_attn,   cudaFuncAttributeMaxDynamicSharedMemorySize, DSMEM);
    cudaFuncSetAttribute(k2_xgemm_update, cudaFuncAttributeMaxDynamicSharedMemorySize, DSMEM);

    prep_a<<<2048, 1024>>>(W_ih, W_hh, b_ih, b_hh);
    prep_b<<<8352, 1024>>>(x, Wa);

    for (int t = 0; t < SEQ; t++) {
        k1_hgemm_attn  <<<384, 256, DSMEM>>>(ba);
        k2_xgemm_update<<<128, 256, DSMEM>>>(out, t);
    }
}

// round 8
// speedup vs baseline: 2.3957x; 1.0851x over previous
#include <cuda_runtime.h>
#include <cuda_bf16.h>
#include <cuda_fp16.h>
#include <cstdint>

// ---------------------------------------------------------------------------
// LSTM with attention-weighted inputs.  B=256, SEQ=128, IN=H=512.
// Gate dim PERMUTED: column n = 4*k + gate.
// A ([xi|h] bf16 hi/lo) and W (bf16 hi/lo) are PRE-SWIZZLED (SW128) 64rx128B
// tiles in gmem; K-stages stream in via cp.async.bulk + mbarrier (3 stages).
//   k1: blocks 0..127 h-half GEMM (K=512..1023) -> partial gates(+bias)
//       blocks 128..255 attention + xi (2 batches/block)
//   k2: xi-half GEMM (K=0..511) + partial -> fused LSTM update, h tiles out.
// GEMM: mma.sync bf16 3-term split, 3 acc banks, 16 warps (4x4, 16x16 tiles).
// NOTE: tcgen05 unavailable (harness PTX target is sm_103, not sm_103a).
// ---------------------------------------------------------------------------

#define BATCH 256
#define SEQ   128
#define IN    512
#define H     512
#define NG    2048
#define TILE  8192                 // 64 rows x 128B, SW128
#define STGB  32768                // Ah+Al+Bh+Bl per stage
#define DSMEM 98304                // 3 stages

__device__ unsigned char g_AhiT[4 * 16 * TILE];    // [mblk][stage]
__device__ unsigned char g_AloT[4 * 16 * TILE];
__device__ unsigned char g_WhiT[32 * 16 * TILE];   // [nblk][stage]
__device__ unsigned char g_WloT[32 * 16 * TILE];
__device__ float         g_bias[NG];
__device__ __half2       g_x16 [BATCH * SEQ * (IN/2)];
__device__ __half2       g_Wa16[SEQ * (IN/2)];
__device__ float         g_c   [BATCH * H];
__device__ float         g_gates[BATCH * NG];      // h-half partial (+bias)

__device__ __forceinline__ uint32_t swz(uint32_t o) { return o ^ ((o >> 3) & 0x70u); }
__device__ __forceinline__ float sigf(float x) { return 1.0f / (1.0f + expf(-x)); }

__device__ __forceinline__ uint32_t smem_u32(const void* p) {
    uint32_t a;
    asm("{ .reg .u64 t; cvta.to.shared.u64 t, %1; cvt.u32.u64 %0, t; }" : "=r"(a) : "l"(p));
    return a;
}
#define MBAR_INIT(a, n) asm volatile("mbarrier.init.shared.b64 [%0], %1;" :: "r"(a), "r"(n) : "memory")
#define MBAR_EXPECT_TX(a, b) asm volatile("mbarrier.arrive.expect_tx.shared.b64 _, [%0], %1;" :: "r"(a), "r"(b) : "memory")
#define MBAR_WAIT(a, par) do { \
    asm volatile("{ .reg .pred P; WL%=: mbarrier.try_wait.parity.acquire.cta.shared::cta.b64 P, [%0], %1, 0x989680; @P bra.uni WD%=; bra.uni WL%=; WD%=: }" \
                 :: "r"(a), "r"(par) : "memory"); } while (0)

__device__ __forceinline__ void bulk_g2s(uint32_t dst, const void* src, uint32_t mbar) {
    asm volatile("cp.async.bulk.shared::cluster.global.mbarrier::complete_tx::bytes [%0], [%1], %2, [%3];"
                 :: "r"(dst), "l"(src), "n"(TILE), "r"(mbar) : "memory");
}

__device__ __forceinline__ void ldm_x4(uint32_t* r, const void* p) {
    uint32_t a = smem_u32(p);
    asm volatile("ldmatrix.sync.aligned.m8n8.x4.shared.b16 {%0,%1,%2,%3}, [%4];"
                 : "=r"(r[0]), "=r"(r[1]), "=r"(r[2]), "=r"(r[3]) : "r"(a));
}
__device__ __forceinline__ void mma16816(float* c, const uint32_t* a, uint32_t b0, uint32_t b1) {
    asm volatile(
        "mma.sync.aligned.m16n8k16.row.col.f32.bf16.bf16.f32 "
        "{%0,%1,%2,%3}, {%4,%5,%6,%7}, {%8,%9}, {%0,%1,%2,%3};"
        : "+f"(c[0]), "+f"(c[1]), "+f"(c[2]), "+f"(c[3])
        : "r"(a[0]), "r"(a[1]), "r"(a[2]), "r"(a[3]), "r"(b0), "r"(b1));
}

// ---------------- prep ---------------------------------------------------------
__global__ void prep_a(const float* __restrict__ W_ih, const float* __restrict__ W_hh,
                       const float* __restrict__ b_ih, const float* __restrict__ b_hh) {
    int i = blockIdx.x * blockDim.x + threadIdx.x;      // 2,097,152
    int n = i >> 10, kc = i & 1023;
    int j = (n & 3) * 512 + (n >> 2);
    float w = (kc < IN) ? W_ih[j * IN + kc] : W_hh[j * H + (kc - IN)];
    __nv_bfloat16 hi = __float2bfloat16(w);
    __nv_bfloat16 lo = __float2bfloat16(w - __bfloat162float(hi));
    uint32_t off = (uint32_t)((n >> 6) * 16 + (kc >> 6)) * TILE + swz((n & 63) * 128 + (kc & 63) * 2);
    *(__nv_bfloat16*)(g_WhiT + off) = hi;
    *(__nv_bfloat16*)(g_WloT + off) = lo;
    if (i < NG) {
        int jb = (i & 3) * 512 + (i >> 2);
        g_bias[i] = b_ih[jb] + b_hh[jb];
    }
}

__global__ void prep_b(const float* __restrict__ x, const float* __restrict__ Wa) {
    int blk = blockIdx.x, tid = threadIdx.x;
    if (blk < 8192) {
        size_t i = (size_t)blk * 1024 + tid;
        float2 v = ((const float2*)x)[i];
        g_x16[i] = __floats2half2_rn(v.x, v.y);
    } else if (blk < 8224) {
        int i = (blk - 8192) * 1024 + tid;
        float2 v = ((const float2*)Wa)[i];
        g_Wa16[i] = __floats2half2_rn(v.x, v.y);
    } else {                                            // zero-input initial cell
        int b = (blk - 8224) * 2 + (tid >> 9);
        int k = tid & 511;
        float gi = g_bias[k * 4 + 0], gg = g_bias[k * 4 + 2], go = g_bias[k * 4 + 3];
        float c0 = sigf(gi) * tanhf(gg);
        float h0 = sigf(go) * tanhf(c0);
        g_c[b * H + k] = c0;
        __nv_bfloat16 hi = __float2bfloat16(h0);
        __nv_bfloat16 lo = __float2bfloat16(h0 - __bfloat162float(hi));
        uint32_t off = (uint32_t)((b >> 6) * 16 + 8 + (k >> 6)) * TILE + swz((b & 63) * 128 + (k & 63) * 2);
        *(__nv_bfloat16*)(g_AhiT + off) = hi;
        *(__nv_bfloat16*)(g_AloT + off) = lo;
    }
}

// ---------------- GEMM core: 64x64 tile, BK=64, 16 warps ----------------------
template <int ST0, bool FINAL>
__device__ __forceinline__ void gemm_core(unsigned char* sm, int bidx, float* out, int t) {
    __shared__ __align__(8) uint64_t mbar[3];
    const int tid = threadIdx.x, lane = tid & 31, warp = tid >> 5;
    const int bn = bidx & 31, bm = bidx >> 5;           // 32 n x 4 m
    const int wm = (warp & 3) * 16, wn = (warp >> 2) * 16;

    if (tid == 0) {
        MBAR_INIT(smem_u32(&mbar[0]), 1);
        MBAR_INIT(smem_u32(&mbar[1]), 1);
        MBAR_INIT(smem_u32(&mbar[2]), 1);
    }
    __syncthreads();

    const unsigned char* sAh = g_AhiT + (bm * 16 + ST0) * TILE;
    const unsigned char* sAl = g_AloT + (bm * 16 + ST0) * TILE;
    const unsigned char* sBh = g_WhiT + (bn * 16 + ST0) * TILE;
    const unsigned char* sBl = g_WloT + (bn * 16 + ST0) * TILE;
    const uint32_t smb = smem_u32(sm);

    auto prefetch = [&](int s) {
        uint32_t bar = smem_u32(&mbar[s % 3]);
        uint32_t d = smb + (s % 3) * STGB;
        MBAR_EXPECT_TX(bar, STGB);
        bulk_g2s(d,            sAh + s * TILE, bar);
        bulk_g2s(d + TILE,     sAl + s * TILE, bar);
        bulk_g2s(d + 2 * TILE, sBh + s * TILE, bar);
        bulk_g2s(d + 3 * TILE, sBl + s * TILE, bar);
    };
    if (tid == 0) { prefetch(0); prefetch(1); }

    float hh[2][4] = {}, hl[2][4] = {}, lh[2][4] = {};

    for (int s = 0; s < 8; s++) {
        if (tid == 0 && s + 2 < 8) prefetch(s + 2);     // buffer freed by prev sync
        MBAR_WAIT(smem_u32(&mbar[s % 3]), (s / 3) & 1);
        unsigned char* buf = sm + (s % 3) * STGB;
        const unsigned char* Ah = buf;
        const unsigned char* Al = buf + TILE;
        const unsigned char* Bh = buf + 2 * TILE;
        const unsigned char* Bl = buf + 3 * TILE;

        #pragma unroll
        for (int kq = 0; kq < 4; kq++) {
            const int kb = kq * 16;
            uint32_t fah[4], fal[4], fbh[4], fbl[4];
            const uint32_t oa = swz((wm + (lane & 15)) * 128 + (kb + (lane >> 4) * 8) * 2);
            ldm_x4(fah, Ah + oa);
            ldm_x4(fal, Al + oa);
            const int br = wn + (lane & 7) + ((lane >> 4) << 3);
            const uint32_t ob = swz(br * 128 + (kb + ((lane >> 3) & 1) * 8) * 2);
            ldm_x4(fbh, Bh + ob);
            ldm_x4(fbl, Bl + ob);
            #pragma unroll
            for (int ni = 0; ni < 2; ni++) {
                mma16816(hh[ni], fah, fbh[ni * 2], fbh[ni * 2 + 1]);
                mma16816(hl[ni], fah, fbl[ni * 2], fbl[ni * 2 + 1]);
                mma16816(lh[ni], fal, fbh[ni * 2], fbh[ni * 2 + 1]);
            }
        }
        __syncthreads();
    }

    float acc[2][4];
    #pragma unroll
    for (int ni = 0; ni < 2; ni++)
        #pragma unroll
        for (int j = 0; j < 4; j++)
            acc[ni][j] = hh[ni][j] + hl[ni][j] + lh[ni][j];

    if (!FINAL) {
        #pragma unroll
        for (int ni = 0; ni < 2; ni++) {
            const int r = bm * 64 + wm + (lane >> 2);
            const int c = bn * 64 + wn + ni * 8 + (lane & 3) * 2;
            const float b0 = g_bias[c], b1 = g_bias[c + 1];
            *(float2*)&g_gates[(size_t)r * NG + c] =
                make_float2(acc[ni][0] + b0, acc[ni][1] + b1);
            *(float2*)&g_gates[(size_t)(r + 8) * NG + c] =
                make_float2(acc[ni][2] + b0, acc[ni][3] + b1);
        }
    } else {
        float* gsm = (float*)sm;                        // [64][68]
        #pragma unroll
        for (int ni = 0; ni < 2; ni++) {
            const int r = wm + (lane >> 2);
            const int c = wn + ni * 8 + (lane & 3) * 2;
            gsm[r * 68 + c]           = acc[ni][0];
            gsm[r * 68 + c + 1]       = acc[ni][1];
            gsm[(r + 8) * 68 + c]     = acc[ni][2];
            gsm[(r + 8) * 68 + c + 1] = acc[ni][3];
        }
        __syncthreads();

        const int kl = tid & 15;
        const int k  = bn * 16 + kl;
        const uint32_t tbase = ((uint32_t)bm * 16 + 8 + (k >> 6)) * TILE;  // h stage
        #pragma unroll
        for (int j = 0; j < 2; j++) {
            const int bl = (tid >> 4) + j * 32;
            const int batch = bm * 64 + bl;
            float4 g4 = *(const float4*)&gsm[bl * 68 + kl * 4];
            float4 gp = *(const float4*)&g_gates[(size_t)batch * NG + bn * 64 + kl * 4];
            float gi = g4.x + gp.x, gf = g4.y + gp.y, gg = g4.z + gp.z, go = g4.w + gp.w;
            float cold = g_c[batch * H + k];
            float cn = sigf(gf) * cold + sigf(gi) * tanhf(gg);
            float h  = sigf(go) * tanhf(cn);
            g_c[batch * H + k] = cn;
            __nv_bfloat16 hi = __float2bfloat16(h);
            __nv_bfloat16 lo = __float2bfloat16(h - __bfloat162float(hi));
            uint32_t off = tbase + swz(bl * 128 + (k & 63) * 2);
            *(__nv_bfloat16*)(g_AhiT + off) = hi;
            *(__nv_bfloat16*)(g_AloT + off) = lo;
            out[((size_t)batch * SEQ + t) * H + k] = h;
        }
    }
}

// ---------------- attention: 2 batches per block (512 thr) --------------------
struct AttnS {
    float c_sm[IN];
    float logit[SEQ], attn[SEQ];
    float rmax[4], rsum[4];
    float xpart[4][IN];
};

__device__ __forceinline__ void attn2(unsigned char* dyn, int bpair, const float* __restrict__ ba) {
    AttnS* s = ((AttnS*)dyn) + (threadIdx.x >> 8);
    const int b = bpair * 2 + (threadIdx.x >> 8);
    const int tid = threadIdx.x & 255;
    const int lane = tid & 31, warp = tid >> 5;

    s->c_sm[tid]       = g_c[b * H + tid];
    s->c_sm[256 + tid] = g_c[b * H + 256 + tid];
    __syncthreads();

    float4 cf[4];
    #pragma unroll
    for (int j = 0; j < 4; j++) cf[j] = ((const float4*)s->c_sm)[j * 32 + lane];

    const uint2* wa = (const uint2*)g_Wa16;
    #pragma unroll 2
    for (int si = 0; si < 16; si++) {
        const int sq = warp * 16 + si;
        const uint2* wp = wa + sq * 128;
        float acc = 0.0f;
        #pragma unroll
        for (int j = 0; j < 4; j++) {
            uint2 v = wp[j * 32 + lane];
            float2 w0 = __half22float2(*(const __half2*)&v.x);
            float2 w1 = __half22float2(*(const __half2*)&v.y);
            acc += cf[j].x * w0.x + cf[j].y * w0.y + cf[j].z * w1.x + cf[j].w * w1.y;
        }
        #pragma unroll
        for (int off = 16; off > 0; off >>= 1) acc += __shfl_xor_sync(0xffffffffu, acc, off);
        if (lane == 0) s->logit[sq] = acc + ba[sq];
    }
    __syncthreads();

    if (tid < 128) {
        float l = s->logit[tid], m = l;
        #pragma unroll
        for (int off = 16; off > 0; off >>= 1) m = fmaxf(m, __shfl_xor_sync(0xffffffffu, m, off));
        if (lane == 0) s->rmax[tid >> 5] = m;
    }
    __syncthreads();
    if (tid < 128) {
        float m = fmaxf(fmaxf(s->rmax[0], s->rmax[1]), fmaxf(s->rmax[2], s->rmax[3]));
        float e = expf(s->logit[tid] - m);
        s->attn[tid] = e;
        #pragma unroll
        for (int off = 16; off > 0; off >>= 1) e += __shfl_xor_sync(0xffffffffu, e, off);
        if (lane == 0) s->rsum[tid >> 5] = e;
    }
    __syncthreads();
    const float inv = 1.0f / (s->rsum[0] + s->rsum[1] + s->rsum[2] + s->rsum[3]);

    {
        const int g = tid >> 6, cth = tid & 63;
        const uint4* xp = ((const uint4*)g_x16) + (size_t)b * SEQ * 64 + cth;
        float acc[8] = {};
        #pragma unroll 4
        for (int i = 0; i < 32; i++) {
            const int sq = g * 32 + i;
            const float a = s->attn[sq];
            uint4 v = xp[(size_t)sq * 64];
            float2 p0 = __half22float2(*(const __half2*)&v.x);
            float2 p1 = __half22float2(*(const __half2*)&v.y);
            float2 p2 = __half22float2(*(const __half2*)&v.z);
            float2 p3 = __half22float2(*(const __half2*)&v.w);
            acc[0] += a * p0.x; acc[1] += a * p0.y;
            acc[2] += a * p1.x; acc[3] += a * p1.y;
            acc[4] += a * p2.x; acc[5] += a * p2.y;
            acc[6] += a * p3.x; acc[7] += a * p3.y;
        }
        #pragma unroll
        for (int q = 0; q < 8; q++) s->xpart[g][cth * 8 + q] = acc[q];
    }
    __syncthreads();

    {
        const int d0 = tid * 2;
        float v0 = (s->xpart[0][d0]     + s->xpart[1][d0])     + (s->xpart[2][d0]     + s->xpart[3][d0]);
        float v1 = (s->xpart[0][d0 + 1] + s->xpart[1][d0 + 1]) + (s->xpart[2][d0 + 1] + s->xpart[3][d0 + 1]);
        v0 *= inv; v1 *= inv;
        __nv_bfloat16 h0 = __float2bfloat16(v0);
        __nv_bfloat16 l0 = __float2bfloat16(v0 - __bfloat162float(h0));
        __nv_bfloat16 h1 = __float2bfloat16(v1);
        __nv_bfloat16 l1 = __float2bfloat16(v1 - __bfloat162float(h1));
        uint32_t off = ((uint32_t)(b >> 6) * 16 + (d0 >> 6)) * TILE + swz((b & 63) * 128 + (d0 & 63) * 2);
        *(__nv_bfloat162*)(g_AhiT + off) = __nv_bfloat162(h0, h1);
        *(__nv_bfloat162*)(g_AloT + off) = __nv_bfloat162(l0, l1);
    }
}

// ---------------- per-step kernels ---------------------------------------------
__global__ void __launch_bounds__(512) k1_hgemm_attn(const float* __restrict__ ba) {
    extern __shared__ unsigned char dyn[];
    if (blockIdx.x < 128) gemm_core<8, false>(dyn, blockIdx.x, nullptr, 0);
    else                  attn2(dyn, blockIdx.x - 128, ba);
}

__global__ void __launch_bounds__(512) k2_xgemm_update(float* __restrict__ out, int t) {
    extern __shared__ unsigned char dyn[];
    gemm_core<0, true>(dyn, blockIdx.x, out, t);
}

// ---------------- launcher -------------------------------------------------------
extern "C" void kernel_launch(void* const* d_in, const int* in_sizes, int n_in,
                              void* d_out, int out_size) {
    const float* x    = (const float*)d_in[0];
    const float* W_ih = (const float*)d_in[1];
    const float* W_hh = (const float*)d_in[2];
    const float* b_ih = (const float*)d_in[3];
    const float* b_hh = (const float*)d_in[4];
    const float* Wa   = (const float*)d_in[5];
    const float* ba   = (const float*)d_in[6];
    float* out = (float*)d_out;

    cudaFuncSetAttribute(k1_hgemm_attn,   cudaFuncAttributeMaxDynamicSharedMemorySize, DSMEM);
    cudaFuncSetAttribute(k2_xgemm_update, cudaFuncAttributeMaxDynamicSharedMemorySize, DSMEM);

    prep_a<<<2048, 1024>>>(W_ih, W_hh, b_ih, b_hh);
    prep_b<<<8352, 1024>>>(x, Wa);

    for (int t = 0; t < SEQ; t++) {
        k1_hgemm_attn  <<<256, 512, DSMEM>>>(ba);
        k2_xgemm_update<<<128, 512, DSMEM>>>(out, t);
    }
}

// round 9
// speedup vs baseline: 2.5074x; 1.0466x over previous
#include <cuda_runtime.h>
#include <cuda_bf16.h>
#include <cuda_fp16.h>
#include <cstdint>

// ---------------------------------------------------------------------------
// LSTM with attention-weighted inputs.  B=256, SEQ=128, IN=H=512.
// Gate dim PERMUTED: column n = 4*k + gate.
// A = [xi|h] single fp16 tiles; W = fp16 hi+lo split tiles. All pre-swizzled
// (SW128) 128B-row tiles in gmem; K-stages stream via cp.async.bulk+mbarrier.
//   k1: blocks 0..255 h-half GEMM (K=512..1023) -> partial gates(+bias)
//       blocks 256..511 attention + xi
//   k2: xi-half GEMM (K=0..511) + partial -> fused LSTM update, h tiles out.
// GEMM: 64x32 tile, 256 CTAs, 8 warps, mma.sync fp16, 2 acc banks, 4-stage
// bulk pipeline.  (tcgen05 unavailable: harness PTX target is sm_103.)
// ---------------------------------------------------------------------------

#define BATCH 256
#define SEQ   128
#define IN    512
#define H     512
#define NG    2048
#define ATILE 8192                 // 64 rows x 128B (K=64 fp16)
#define BTILE 4096                 // 32 rows x 128B
#define STGB  16384                // A + Bh + Bl per stage
#define NSTG  4
#define DSMEM (NSTG * STGB)        // 65536

__device__ unsigned char g_AT  [4 * 16 * ATILE];   // [mblk][stage] fp16
__device__ unsigned char g_WhiT[64 * 16 * BTILE];  // [nblk][stage] fp16
__device__ unsigned char g_WloT[64 * 16 * BTILE];
__device__ float         g_bias[NG];
__device__ __half2       g_x16 [BATCH * SEQ * (IN/2)];
__device__ __half2       g_Wa16[SEQ * (IN/2)];
__device__ float         g_c   [BATCH * H];
__device__ float         g_gates[BATCH * NG];      // h-half partial (+bias)

__device__ __forceinline__ uint32_t swz(uint32_t o) { return o ^ ((o >> 3) & 0x70u); }
__device__ __forceinline__ float sigf(float x) { return 1.0f / (1.0f + expf(-x)); }

__device__ __forceinline__ uint32_t smem_u32(const void* p) {
    uint32_t a;
    asm("{ .reg .u64 t; cvta.to.shared.u64 t, %1; cvt.u32.u64 %0, t; }" : "=r"(a) : "l"(p));
    return a;
}
#define MBAR_INIT(a, n) asm volatile("mbarrier.init.shared.b64 [%0], %1;" :: "r"(a), "r"(n) : "memory")
#define MBAR_EXPECT_TX(a, b) asm volatile("mbarrier.arrive.expect_tx.shared.b64 _, [%0], %1;" :: "r"(a), "r"(b) : "memory")
#define MBAR_WAIT(a, par) do { \
    asm volatile("{ .reg .pred P; WL%=: mbarrier.try_wait.parity.acquire.cta.shared::cta.b64 P, [%0], %1, 0x989680; @P bra.uni WD%=; bra.uni WL%=; WD%=: }" \
                 :: "r"(a), "r"(par) : "memory"); } while (0)

__device__ __forceinline__ void bulk_g2s(uint32_t dst, const void* src, uint32_t bytes, uint32_t mbar) {
    asm volatile("cp.async.bulk.shared::cluster.global.mbarrier::complete_tx::bytes [%0], [%1], %2, [%3];"
                 :: "r"(dst), "l"(src), "r"(bytes), "r"(mbar) : "memory");
}

__device__ __forceinline__ void ldm_x4(uint32_t* r, const void* p) {
    uint32_t a = smem_u32(p);
    asm volatile("ldmatrix.sync.aligned.m8n8.x4.shared.b16 {%0,%1,%2,%3}, [%4];"
                 : "=r"(r[0]), "=r"(r[1]), "=r"(r[2]), "=r"(r[3]) : "r"(a));
}
__device__ __forceinline__ void mma16816(float* c, const uint32_t* a, uint32_t b0, uint32_t b1) {
    asm volatile(
        "mma.sync.aligned.m16n8k16.row.col.f32.f16.f16.f32 "
        "{%0,%1,%2,%3}, {%4,%5,%6,%7}, {%8,%9}, {%0,%1,%2,%3};"
        : "+f"(c[0]), "+f"(c[1]), "+f"(c[2]), "+f"(c[3])
        : "r"(a[0]), "r"(a[1]), "r"(a[2]), "r"(a[3]), "r"(b0), "r"(b1));
}

// ---------------- prep ---------------------------------------------------------
__global__ void prep_a(const float* __restrict__ W_ih, const float* __restrict__ W_hh,
                       const float* __restrict__ b_ih, const float* __restrict__ b_hh) {
    int i = blockIdx.x * blockDim.x + threadIdx.x;      // 2,097,152
    int n = i >> 10, kc = i & 1023;
    int j = (n & 3) * 512 + (n >> 2);
    float w = (kc < IN) ? W_ih[j * IN + kc] : W_hh[j * H + (kc - IN)];
    __half hi = __float2half_rn(w);
    __half lo = __float2half_rn(w - __half2float(hi));
    uint32_t off = (uint32_t)((n >> 5) * 16 + (kc >> 6)) * BTILE + swz((n & 31) * 128 + (kc & 63) * 2);
    *(__half*)(g_WhiT + off) = hi;
    *(__half*)(g_WloT + off) = lo;
    if (i < NG) {
        int jb = (i & 3) * 512 + (i >> 2);
        g_bias[i] = b_ih[jb] + b_hh[jb];
    }
}

__global__ void prep_b(const float* __restrict__ x, const float* __restrict__ Wa) {
    int blk = blockIdx.x, tid = threadIdx.x;
    if (blk < 8192) {
        size_t i = (size_t)blk * 1024 + tid;
        float2 v = ((const float2*)x)[i];
        g_x16[i] = __floats2half2_rn(v.x, v.y);
    } else if (blk < 8224) {
        int i = (blk - 8192) * 1024 + tid;
        float2 v = ((const float2*)Wa)[i];
        g_Wa16[i] = __floats2half2_rn(v.x, v.y);
    } else {                                            // zero-input initial cell
        int b = (blk - 8224) * 2 + (tid >> 9);
        int k = tid & 511;
        float gi = g_bias[k * 4 + 0], gg = g_bias[k * 4 + 2], go = g_bias[k * 4 + 3];
        float c0 = sigf(gi) * tanhf(gg);
        float h0 = sigf(go) * tanhf(c0);
        g_c[b * H + k] = c0;
        uint32_t off = (uint32_t)((b >> 6) * 16 + 8 + (k >> 6)) * ATILE + swz((b & 63) * 128 + (k & 63) * 2);
        *(__half*)(g_AT + off) = __float2half_rn(h0);
    }
}

// ---------------- GEMM core: 64x32 tile, BK=64, 8 warps -----------------------
template <int ST0, bool FINAL>
__device__ __forceinline__ void gemm_core(unsigned char* sm, int bidx, float* out, int t) {
    __shared__ __align__(8) uint64_t mbar[NSTG];
    const int tid = threadIdx.x, lane = tid & 31, warp = tid >> 5;
    const int bn = bidx & 63, bm = bidx >> 6;           // 64 n x 4 m
    const int wm = (warp & 3) * 16, wn = (warp >> 2) * 16;

    if (tid == 0)
        #pragma unroll
        for (int i = 0; i < NSTG; i++) MBAR_INIT(smem_u32(&mbar[i]), 1);
    __syncthreads();

    const unsigned char* sA  = g_AT   + (bm * 16 + ST0) * ATILE;
    const unsigned char* sBh = g_WhiT + (bn * 16 + ST0) * BTILE;
    const unsigned char* sBl = g_WloT + (bn * 16 + ST0) * BTILE;
    const uint32_t smb = smem_u32(sm);

    auto prefetch = [&](int s) {
        uint32_t bar = smem_u32(&mbar[s % NSTG]);
        uint32_t d = smb + (s % NSTG) * STGB;
        MBAR_EXPECT_TX(bar, STGB);
        bulk_g2s(d,                 sA  + s * ATILE, ATILE, bar);
        bulk_g2s(d + ATILE,         sBh + s * BTILE, BTILE, bar);
        bulk_g2s(d + ATILE + BTILE, sBl + s * BTILE, BTILE, bar);
    };
    if (tid == 0) { prefetch(0); prefetch(1); prefetch(2); }

    float hh[2][4] = {}, hl[2][4] = {};

    for (int s = 0; s < 8; s++) {
        if (tid == 0 && s + 3 < 8) prefetch(s + 3);     // buffer freed by prev sync
        MBAR_WAIT(smem_u32(&mbar[s % NSTG]), (s / NSTG) & 1);
        unsigned char* buf = sm + (s % NSTG) * STGB;
        const unsigned char* A  = buf;
        const unsigned char* Bh = buf + ATILE;
        const unsigned char* Bl = buf + ATILE + BTILE;

        #pragma unroll
        for (int kq = 0; kq < 4; kq++) {
            const int kb = kq * 16;
            uint32_t fa[4], fbh[4], fbl[4];
            const uint32_t oa = swz((wm + (lane & 15)) * 128 + (kb + (lane >> 4) * 8) * 2);
            ldm_x4(fa, A + oa);
            const int br = wn + (lane & 7) + ((lane >> 4) << 3);
            const uint32_t ob = swz(br * 128 + (kb + ((lane >> 3) & 1) * 8) * 2);
            ldm_x4(fbh, Bh + ob);
            ldm_x4(fbl, Bl + ob);
            #pragma unroll
            for (int ni = 0; ni < 2; ni++) {
                mma16816(hh[ni], fa, fbh[ni * 2], fbh[ni * 2 + 1]);
                mma16816(hl[ni], fa, fbl[ni * 2], fbl[ni * 2 + 1]);
            }
        }
        __syncthreads();
    }

    float acc[2][4];
    #pragma unroll
    for (int ni = 0; ni < 2; ni++)
        #pragma unroll
        for (int j = 0; j < 4; j++)
            acc[ni][j] = hh[ni][j] + hl[ni][j];

    if (!FINAL) {
        #pragma unroll
        for (int ni = 0; ni < 2; ni++) {
            const int r = bm * 64 + wm + (lane >> 2);
            const int c = bn * 32 + wn + ni * 8 + (lane & 3) * 2;
            const float b0 = g_bias[c], b1 = g_bias[c + 1];
            *(float2*)&g_gates[(size_t)r * NG + c] =
                make_float2(acc[ni][0] + b0, acc[ni][1] + b1);
            *(float2*)&g_gates[(size_t)(r + 8) * NG + c] =
                make_float2(acc[ni][2] + b0, acc[ni][3] + b1);
        }
    } else {
        float* gsm = (float*)sm;                        // [64][36]
        #pragma unroll
        for (int ni = 0; ni < 2; ni++) {
            const int r = wm + (lane >> 2);
            const int c = wn + ni * 8 + (lane & 3) * 2;
            gsm[r * 36 + c]           = acc[ni][0];
            gsm[r * 36 + c + 1]       = acc[ni][1];
            gsm[(r + 8) * 36 + c]     = acc[ni][2];
            gsm[(r + 8) * 36 + c + 1] = acc[ni][3];
        }
        __syncthreads();

        const int kl = tid & 7;
        const int k  = bn * 8 + kl;
        const uint32_t tbase = ((uint32_t)bm * 16 + 8 + (k >> 6)) * ATILE;  // h stage
        #pragma unroll
        for (int j = 0; j < 2; j++) {
            const int bl = (tid >> 3) + j * 32;
            const int batch = bm * 64 + bl;
            float4 g4 = *(const float4*)&gsm[bl * 36 + kl * 4];
            float4 gp = *(const float4*)&g_gates[(size_t)batch * NG + bn * 32 + kl * 4];
            float gi = g4.x + gp.x, gf = g4.y + gp.y, gg = g4.z + gp.z, go = g4.w + gp.w;
            float cold = g_c[batch * H + k];
            float cn = sigf(gf) * cold + sigf(gi) * tanhf(gg);
            float h  = sigf(go) * tanhf(cn);
            g_c[batch * H + k] = cn;
            uint32_t off = tbase + swz(bl * 128 + (k & 63) * 2);
            *(__half*)(g_AT + off) = __float2half_rn(h);
            out[((size_t)batch * SEQ + t) * H + k] = h;
        }
    }
}

// ---------------- attention: 1 batch per block, 256 thr ------------------------
struct AttnS {
    float c_sm[IN];
    float logit[SEQ], attn[SEQ];
    float rmax[4], rsum[4];
    float xpart[4][IN];
};

__device__ __forceinline__ void attn_body(unsigned char* dyn, int b, const float* __restrict__ ba) {
    AttnS* s = (AttnS*)dyn;
    const int tid = threadIdx.x, lane = tid & 31, warp = tid >> 5;

    s->c_sm[tid]       = g_c[b * H + tid];
    s->c_sm[256 + tid] = g_c[b * H + 256 + tid];
    __syncthreads();

    float4 cf[4];
    #pragma unroll
    for (int j = 0; j < 4; j++) cf[j] = ((const float4*)s->c_sm)[j * 32 + lane];

    const uint2* wa = (const uint2*)g_Wa16;
    #pragma unroll 2
    for (int si = 0; si < 16; si++) {
        const int sq = warp * 16 + si;
        const uint2* wp = wa + sq * 128;
        float acc = 0.0f;
        #pragma unroll
        for (int j = 0; j < 4; j++) {
            uint2 v = wp[j * 32 + lane];
            float2 w0 = __half22float2(*(const __half2*)&v.x);
            float2 w1 = __half22float2(*(const __half2*)&v.y);
            acc += cf[j].x * w0.x + cf[j].y * w0.y + cf[j].z * w1.x + cf[j].w * w1.y;
        }
        #pragma unroll
        for (int off = 16; off > 0; off >>= 1) acc += __shfl_xor_sync(0xffffffffu, acc, off);
        if (lane == 0) s->logit[sq] = acc + ba[sq];
    }
    __syncthreads();

    if (tid < 128) {
        float l = s->logit[tid], m = l;
        #pragma unroll
        for (int off = 16; off > 0; off >>= 1) m = fmaxf(m, __shfl_xor_sync(0xffffffffu, m, off));
        if (lane == 0) s->rmax[tid >> 5] = m;
    }
    __syncthreads();
    if (tid < 128) {
        float m = fmaxf(fmaxf(s->rmax[0], s->rmax[1]), fmaxf(s->rmax[2], s->rmax[3]));
        float e = expf(s->logit[tid] - m);
        s->attn[tid] = e;
        #pragma unroll
        for (int off = 16; off > 0; off >>= 1) e += __shfl_xor_sync(0xffffffffu, e, off);
        if (lane == 0) s->rsum[tid >> 5] = e;
    }
    __syncthreads();
    const float inv = 1.0f / (s->rsum[0] + s->rsum[1] + s->rsum[2] + s->rsum[3]);

    {
        const int g = tid >> 6, cth = tid & 63;
        const uint4* xp = ((const uint4*)g_x16) + (size_t)b * SEQ * 64 + cth;
        float acc[8] = {};
        #pragma unroll 4
        for (int i = 0; i < 32; i++) {
            const int sq = g * 32 + i;
            const float a = s->attn[sq];
            uint4 v = xp[(size_t)sq * 64];
            float2 p0 = __half22float2(*(const __half2*)&v.x);
            float2 p1 = __half22float2(*(const __half2*)&v.y);
            float2 p2 = __half22float2(*(const __half2*)&v.z);
            float2 p3 = __half22float2(*(const __half2*)&v.w);
            acc[0] += a * p0.x; acc[1] += a * p0.y;
            acc[2] += a * p1.x; acc[3] += a * p1.y;
            acc[4] += a * p2.x; acc[5] += a * p2.y;
            acc[6] += a * p3.x; acc[7] += a * p3.y;
        }
        #pragma unroll
        for (int q = 0; q < 8; q++) s->xpart[g][cth * 8 + q] = acc[q];
    }
    __syncthreads();

    {
        const int d0 = tid * 2;
        float v0 = (s->xpart[0][d0]     + s->xpart[1][d0])     + (s->xpart[2][d0]     + s->xpart[3][d0]);
        float v1 = (s->xpart[0][d0 + 1] + s->xpart[1][d0 + 1]) + (s->xpart[2][d0 + 1] + s->xpart[3][d0 + 1]);
        v0 *= inv; v1 *= inv;
        uint32_t off = ((uint32_t)(b >> 6) * 16 + (d0 >> 6)) * ATILE + swz((b & 63) * 128 + (d0 & 63) * 2);
        *(__half2*)(g_AT + off) = __floats2half2_rn(v0, v1);
    }
}

// ---------------- per-step kernels ---------------------------------------------
__global__ void __launch_bounds__(256) k1_hgemm_attn(const float* __restrict__ ba) {
    extern __shared__ unsigned char dyn[];
    if (blockIdx.x < 256) gemm_core<8, false>(dyn, blockIdx.x, nullptr, 0);
    else                  attn_body(dyn, blockIdx.x - 256, ba);
}

__global__ void __launch_bounds__(256) k2_xgemm_update(float* __restrict__ out, int t) {
    extern __shared__ unsigned char dyn[];
    gemm_core<0, true>(dyn, blockIdx.x, out, t);
}

// ---------------- launcher -------------------------------------------------------
extern "C" void kernel_launch(void* const* d_in, const int* in_sizes, int n_in,
                              void* d_out, int out_size) {
    const float* x    = (const float*)d_in[0];
    const float* W_ih = (const float*)d_in[1];
    const float* W_hh = (const float*)d_in[2];
    const float* b_ih = (const float*)d_in[3];
    const float* b_hh = (const float*)d_in[4];
    const float* Wa   = (const float*)d_in[5];
    const float* ba   = (const float*)d_in[6];
    float* out = (float*)d_out;

    cudaFuncSetAttribute(k1_hgemm_attn,   cudaFuncAttributeMaxDynamicSharedMemorySize, DSMEM);
    cudaFuncSetAttribute(k2_xgemm_update, cudaFuncAttributeMaxDynamicSharedMemorySize, DSMEM);

    prep_a<<<2048, 1024>>>(W_ih, W_hh, b_ih, b_hh);
    prep_b<<<8352, 1024>>>(x, Wa);

    for (int t = 0; t < SEQ; t++) {
        k1_hgemm_attn  <<<512, 256, DSMEM>>>(ba);
        k2_xgemm_update<<<256, 256, DSMEM>>>(out, t);
    }
}

// round 10
// speedup vs baseline: 2.9901x; 1.1925x over previous
#include <cuda_runtime.h>
#include <cuda_bf16.h>
#include <cuda_fp16.h>
#include <cstdint>

// ---------------------------------------------------------------------------
// LSTM with attention-weighted inputs.  B=256, SEQ=128, IN=H=512.
// Gate dim PERMUTED: column n = 4*k + gate.
// A = [xi|h] fp16 tiles; W = fused weights fp16 tiles (single term). All
// pre-swizzled (SW128) 128B-row tiles in gmem; stages via cp.async.bulk.
//   k1: blocks 0..255 h-half GEMM (K=512..1023) -> partial gates(+bias)
//       blocks 256..511 attention + xi
//   k2: xi-half GEMM (K=0..511) + partial -> fused LSTM update, h tiles out.
// GEMM: 64x32 tile, 256 CTAs, 8 warps, mma.sync fp16, 4-stage bulk pipeline.
// (tcgen05 unavailable: harness PTX target is sm_103.)
// ---------------------------------------------------------------------------

#define BATCH 256
#define SEQ   128
#define IN    512
#define H     512
#define NG    2048
#define ATILE 8192                 // 64 rows x 128B (K=64 fp16)
#define BTILE 4096                 // 32 rows x 128B
#define STGB  12288                // A + B per stage
#define NSTG  4
#define DSMEM (NSTG * STGB)        // 49152

__device__ unsigned char g_AT[4 * 16 * ATILE];     // [mblk][stage] fp16
__device__ unsigned char g_WT[64 * 16 * BTILE];    // [nblk][stage] fp16
__device__ float         g_bias[NG];
__device__ __half2       g_x16 [BATCH * SEQ * (IN/2)];
__device__ __half2       g_Wa16[SEQ * (IN/2)];
__device__ float         g_c   [BATCH * H];
__device__ float         g_gates[BATCH * NG];      // h-half partial (+bias)

__device__ __forceinline__ uint32_t swz(uint32_t o) { return o ^ ((o >> 3) & 0x70u); }
__device__ __forceinline__ float sigf(float x) { return 1.0f / (1.0f + expf(-x)); }

__device__ __forceinline__ uint32_t smem_u32(const void* p) {
    uint32_t a;
    asm("{ .reg .u64 t; cvta.to.shared.u64 t, %1; cvt.u32.u64 %0, t; }" : "=r"(a) : "l"(p));
    return a;
}
#define MBAR_INIT(a, n) asm volatile("mbarrier.init.shared.b64 [%0], %1;" :: "r"(a), "r"(n) : "memory")
#define MBAR_EXPECT_TX(a, b) asm volatile("mbarrier.arrive.expect_tx.shared.b64 _, [%0], %1;" :: "r"(a), "r"(b) : "memory")
#define MBAR_WAIT(a, par) do { \
    asm volatile("{ .reg .pred P; WL%=: mbarrier.try_wait.parity.acquire.cta.shared::cta.b64 P, [%0], %1, 0x989680; @P bra.uni WD%=; bra.uni WL%=; WD%=: }" \
                 :: "r"(a), "r"(par) : "memory"); } while (0)

__device__ __forceinline__ void bulk_g2s(uint32_t dst, const void* src, uint32_t bytes, uint32_t mbar) {
    asm volatile("cp.async.bulk.shared::cluster.global.mbarrier::complete_tx::bytes [%0], [%1], %2, [%3];"
                 :: "r"(dst), "l"(src), "r"(bytes), "r"(mbar) : "memory");
}

__device__ __forceinline__ void ldm_x4(uint32_t* r, const void* p) {
    uint32_t a = smem_u32(p);
    asm volatile("ldmatrix.sync.aligned.m8n8.x4.shared.b16 {%0,%1,%2,%3}, [%4];"
                 : "=r"(r[0]), "=r"(r[1]), "=r"(r[2]), "=r"(r[3]) : "r"(a));
}
__device__ __forceinline__ void mma16816(float* c, const uint32_t* a, uint32_t b0, uint32_t b1) {
    asm volatile(
        "mma.sync.aligned.m16n8k16.row.col.f32.f16.f16.f32 "
        "{%0,%1,%2,%3}, {%4,%5,%6,%7}, {%8,%9}, {%0,%1,%2,%3};"
        : "+f"(c[0]), "+f"(c[1]), "+f"(c[2]), "+f"(c[3])
        : "r"(a[0]), "r"(a[1]), "r"(a[2]), "r"(a[3]), "r"(b0), "r"(b1));
}

// ---------------- prep ---------------------------------------------------------
__global__ void prep_a(const float* __restrict__ W_ih, const float* __restrict__ W_hh,
                       const float* __restrict__ b_ih, const float* __restrict__ b_hh) {
    int i = blockIdx.x * blockDim.x + threadIdx.x;      // 2,097,152
    int n = i >> 10, kc = i & 1023;
    int j = (n & 3) * 512 + (n >> 2);
    float w = (kc < IN) ? W_ih[j * IN + kc] : W_hh[j * H + (kc - IN)];
    uint32_t off = (uint32_t)((n >> 5) * 16 + (kc >> 6)) * BTILE + swz((n & 31) * 128 + (kc & 63) * 2);
    *(__half*)(g_WT + off) = __float2half_rn(w);
    if (i < NG) {
        int jb = (i & 3) * 512 + (i >> 2);
        g_bias[i] = b_ih[jb] + b_hh[jb];
    }
}

__global__ void prep_b(const float* __restrict__ x, const float* __restrict__ Wa) {
    int blk = blockIdx.x, tid = threadIdx.x;
    if (blk < 8192) {
        size_t i = (size_t)blk * 1024 + tid;
        float2 v = ((const float2*)x)[i];
        g_x16[i] = __floats2half2_rn(v.x, v.y);
    } else if (blk < 8224) {
        int i = (blk - 8192) * 1024 + tid;
        float2 v = ((const float2*)Wa)[i];
        g_Wa16[i] = __floats2half2_rn(v.x, v.y);
    } else {                                            // zero-input initial cell
        int b = (blk - 8224) * 2 + (tid >> 9);
        int k = tid & 511;
        float gi = g_bias[k * 4 + 0], gg = g_bias[k * 4 + 2], go = g_bias[k * 4 + 3];
        float c0 = sigf(gi) * tanhf(gg);
        float h0 = sigf(go) * tanhf(c0);
        g_c[b * H + k] = c0;
        uint32_t off = (uint32_t)((b >> 6) * 16 + 8 + (k >> 6)) * ATILE + swz((b & 63) * 128 + (k & 63) * 2);
        *(__half*)(g_AT + off) = __float2half_rn(h0);
    }
}

// ---------------- GEMM core: 64x32 tile, BK=64, 8 warps -----------------------
template <int ST0, bool FINAL>
__device__ __forceinline__ void gemm_core(unsigned char* sm, int bidx, float* out, int t) {
    __shared__ __align__(8) uint64_t mbar[NSTG];
    const int tid = threadIdx.x, lane = tid & 31, warp = tid >> 5;
    const int bn = bidx & 63, bm = bidx >> 6;           // 64 n x 4 m
    const int wm = (warp & 3) * 16, wn = (warp >> 2) * 16;

    if (tid == 0)
        #pragma unroll
        for (int i = 0; i < NSTG; i++) MBAR_INIT(smem_u32(&mbar[i]), 1);
    __syncthreads();

    const unsigned char* sA = g_AT + (bm * 16 + ST0) * ATILE;
    const unsigned char* sB = g_WT + (bn * 16 + ST0) * BTILE;
    const uint32_t smb = smem_u32(sm);

    auto prefetch = [&](int s) {
        uint32_t bar = smem_u32(&mbar[s % NSTG]);
        uint32_t d = smb + (s % NSTG) * STGB;
        MBAR_EXPECT_TX(bar, STGB);
        bulk_g2s(d,         sA + s * ATILE, ATILE, bar);
        bulk_g2s(d + ATILE, sB + s * BTILE, BTILE, bar);
    };
    if (tid == 0) { prefetch(0); prefetch(1); prefetch(2); }

    float acc[2][4] = {};

    for (int s = 0; s < 8; s++) {
        if (tid == 0 && s + 3 < 8) prefetch(s + 3);     // buffer freed by prev sync
        MBAR_WAIT(smem_u32(&mbar[s % NSTG]), (s / NSTG) & 1);
        unsigned char* buf = sm + (s % NSTG) * STGB;
        const unsigned char* A = buf;
        const unsigned char* B = buf + ATILE;

        #pragma unroll
        for (int kq = 0; kq < 4; kq++) {
            const int kb = kq * 16;
            uint32_t fa[4], fb[4];
            const uint32_t oa = swz((wm + (lane & 15)) * 128 + (kb + (lane >> 4) * 8) * 2);
            ldm_x4(fa, A + oa);
            const int br = wn + (lane & 7) + ((lane >> 4) << 3);
            const uint32_t ob = swz(br * 128 + (kb + ((lane >> 3) & 1) * 8) * 2);
            ldm_x4(fb, B + ob);
            #pragma unroll
            for (int ni = 0; ni < 2; ni++)
                mma16816(acc[ni], fa, fb[ni * 2], fb[ni * 2 + 1]);
        }
        __syncthreads();
    }

    if (!FINAL) {
        #pragma unroll
        for (int ni = 0; ni < 2; ni++) {
            const int r = bm * 64 + wm + (lane >> 2);
            const int c = bn * 32 + wn + ni * 8 + (lane & 3) * 2;
            const float b0 = g_bias[c], b1 = g_bias[c + 1];
            *(float2*)&g_gates[(size_t)r * NG + c] =
                make_float2(acc[ni][0] + b0, acc[ni][1] + b1);
            *(float2*)&g_gates[(size_t)(r + 8) * NG + c] =
                make_float2(acc[ni][2] + b0, acc[ni][3] + b1);
        }
    } else {
        float* gsm = (float*)sm;                        // [64][36]
        #pragma unroll
        for (int ni = 0; ni < 2; ni++) {
            const int r = wm + (lane >> 2);
            const int c = wn + ni * 8 + (lane & 3) * 2;
            gsm[r * 36 + c]           = acc[ni][0];
            gsm[r * 36 + c + 1]       = acc[ni][1];
            gsm[(r + 8) * 36 + c]     = acc[ni][2];
            gsm[(r + 8) * 36 + c + 1] = acc[ni][3];
        }
        __syncthreads();

        const int kl = tid & 7;
        const int k  = bn * 8 + kl;
        const uint32_t tbase = ((uint32_t)bm * 16 + 8 + (k >> 6)) * ATILE;  // h stage
        #pragma unroll
        for (int j = 0; j < 2; j++) {
            const int bl = (tid >> 3) + j * 32;
            const int batch = bm * 64 + bl;
            float4 g4 = *(const float4*)&gsm[bl * 36 + kl * 4];
            float4 gp = *(const float4*)&g_gates[(size_t)batch * NG + bn * 32 + kl * 4];
            float gi = g4.x + gp.x, gf = g4.y + gp.y, gg = g4.z + gp.z, go = g4.w + gp.w;
            float cold = g_c[batch * H + k];
            float cn = sigf(gf) * cold + sigf(gi) * tanhf(gg);
            float h  = sigf(go) * tanhf(cn);
            g_c[batch * H + k] = cn;
            uint32_t off = tbase + swz(bl * 128 + (k & 63) * 2);
            *(__half*)(g_AT + off) = __float2half_rn(h);
            out[((size_t)batch * SEQ + t) * H + k] = h;
        }
    }
}

// ---------------- attention: 1 batch per block, 256 thr ------------------------
struct AttnS {
    float c_sm[IN];
    float logit[SEQ], attn[SEQ];
    float rmax[4], rsum[4];
    float xpart[4][IN];
};

__device__ __forceinline__ void attn_body(unsigned char* dyn, int b, const float* __restrict__ ba) {
    AttnS* s = (AttnS*)dyn;
    const int tid = threadIdx.x, lane = tid & 31, warp = tid >> 5;

    s->c_sm[tid]       = g_c[b * H + tid];
    s->c_sm[256 + tid] = g_c[b * H + 256 + tid];
    __syncthreads();

    float4 cf[4];
    #pragma unroll
    for (int j = 0; j < 4; j++) cf[j] = ((const float4*)s->c_sm)[j * 32 + lane];

    const uint2* wa = (const uint2*)g_Wa16;
    #pragma unroll 2
    for (int si = 0; si < 16; si++) {
        const int sq = warp * 16 + si;
        const uint2* wp = wa + sq * 128;
        float acc = 0.0f;
        #pragma unroll
        for (int j = 0; j < 4; j++) {
            uint2 v = wp[j * 32 + lane];
            float2 w0 = __half22float2(*(const __half2*)&v.x);
            float2 w1 = __half22float2(*(const __half2*)&v.y);
            acc += cf[j].x * w0.x + cf[j].y * w0.y + cf[j].z * w1.x + cf[j].w * w1.y;
        }
        #pragma unroll
        for (int off = 16; off > 0; off >>= 1) acc += __shfl_xor_sync(0xffffffffu, acc, off);
        if (lane == 0) s->logit[sq] = acc + ba[sq];
    }
    __syncthreads();

    if (tid < 128) {
        float l = s->logit[tid], m = l;
        #pragma unroll
        for (int off = 16; off > 0; off >>= 1) m = fmaxf(m, __shfl_xor_sync(0xffffffffu, m, off));
        if (lane == 0) s->rmax[tid >> 5] = m;
    }
    __syncthreads();
    if (tid < 128) {
        float m = fmaxf(fmaxf(s->rmax[0], s->rmax[1]), fmaxf(s->rmax[2], s->rmax[3]));
        float e = expf(s->logit[tid] - m);
        s->attn[tid] = e;
        #pragma unroll
        for (int off = 16; off > 0; off >>= 1) e += __shfl_xor_sync(0xffffffffu, e, off);
        if (lane == 0) s->rsum[tid >> 5] = e;
    }
    __syncthreads();
    const float inv = 1.0f / (s->rsum[0] + s->rsum[1] + s->rsum[2] + s->rsum[3]);

    {
        const int g = tid >> 6, cth = tid & 63;
        const uint4* xp = ((const uint4*)g_x16) + (size_t)b * SEQ * 64 + cth;
        float acc[8] = {};
        #pragma unroll 4
        for (int i = 0; i < 32; i++) {
            const int sq = g * 32 + i;
            const float a = s->attn[sq];
            uint4 v = xp[(size_t)sq * 64];
            float2 p0 = __half22float2(*(const __half2*)&v.x);
            float2 p1 = __half22float2(*(const __half2*)&v.y);
            float2 p2 = __half22float2(*(const __half2*)&v.z);
            float2 p3 = __half22float2(*(const __half2*)&v.w);
            acc[0] += a * p0.x; acc[1] += a * p0.y;
            acc[2] += a * p1.x; acc[3] += a * p1.y;
            acc[4] += a * p2.x; acc[5] += a * p2.y;
            acc[6] += a * p3.x; acc[7] += a * p3.y;
        }
        #pragma unroll
        for (int q = 0; q < 8; q++) s->xpart[g][cth * 8 + q] = acc[q];
    }
    __syncthreads();

    {
        const int d0 = tid * 2;
        float v0 = (s->xpart[0][d0]     + s->xpart[1][d0])     + (s->xpart[2][d0]     + s->xpart[3][d0]);
        float v1 = (s->xpart[0][d0 + 1] + s->xpart[1][d0 + 1]) + (s->xpart[2][d0 + 1] + s->xpart[3][d0 + 1]);
        v0 *= inv; v1 *= inv;
        uint32_t off = ((uint32_t)(b >> 6) * 16 + (d0 >> 6)) * ATILE + swz((b & 63) * 128 + (d0 & 63) * 2);
        *(__half2*)(g_AT + off) = __floats2half2_rn(v0, v1);
    }
}

// ---------------- per-step kernels ---------------------------------------------
__global__ void __launch_bounds__(256) k1_hgemm_attn(const float* __restrict__ ba) {
    extern __shared__ unsigned char dyn[];
    if (blockIdx.x < 256) gemm_core<8, false>(dyn, blockIdx.x, nullptr, 0);
    else                  attn_body(dyn, blockIdx.x - 256, ba);
}

__global__ void __launch_bounds__(256) k2_xgemm_update(float* __restrict__ out, int t) {
    extern __shared__ unsigned char dyn[];
    gemm_core<0, true>(dyn, blockIdx.x, out, t);
}

// ---------------- launcher -------------------------------------------------------
extern "C" void kernel_launch(void* const* d_in, const int* in_sizes, int n_in,
                              void* d_out, int out_size) {
    const float* x    = (const float*)d_in[0];
    const float* W_ih = (const float*)d_in[1];
    const float* W_hh = (const float*)d_in[2];
    const float* b_ih = (const float*)d_in[3];
    const float* b_hh = (const float*)d_in[4];
    const float* Wa   = (const float*)d_in[5];
    const float* ba   = (const float*)d_in[6];
    float* out = (float*)d_out;

    cudaFuncSetAttribute(k1_hgemm_attn,   cudaFuncAttributeMaxDynamicSharedMemorySize, DSMEM);
    cudaFuncSetAttribute(k2_xgemm_update, cudaFuncAttributeMaxDynamicSharedMemorySize, DSMEM);

    prep_a<<<2048, 1024>>>(W_ih, W_hh, b_ih, b_hh);
    prep_b<<<8352, 1024>>>(x, Wa);

    for (int t = 0; t < SEQ; t++) {
        k1_hgemm_attn  <<<512, 256, DSMEM>>>(ba);
        k2_xgemm_update<<<256, 256, DSMEM>>>(out, t);
    }
}

// round 11
// speedup vs baseline: 3.0984x; 1.0362x over previous
#include <cuda_runtime.h>
#include <cuda_bf16.h>
#include <cuda_fp16.h>
#include <cstdint>

// ---------------------------------------------------------------------------
// LSTM with attention-weighted inputs.  B=256, SEQ=128, IN=H=512.
// Gate dim PERMUTED: column n = 4*k + gate.
// A = [xi|h] fp16 tiles; W = fused weights fp16 tiles. Pre-swizzled (SW128)
// 128B-row tiles in gmem; K streamed via large cp.async.bulk copies.
//   k1: blocks 0..255 h-half GEMM (K=512..1023, 4x24KB refill pipeline)
//       blocks 256..511 attention + xi
//   k2: xi-half GEMM (K=0..511, 2x48KB mega-stages, all prefetched upfront)
//       + partial -> fused LSTM update, h tiles out.
// Epilogue operands (g_gates/g_c/bias) preloaded into registers at start.
// (tcgen05 unavailable: harness PTX target is sm_103.)
// ---------------------------------------------------------------------------

#define BATCH 256
#define SEQ   128
#define IN    512
#define H     512
#define NG    2048
#define ATILE 8192                 // 64 rows x 128B (K=64 fp16)
#define BTILE 4096                 // 32 rows x 128B
#define STG1  24576                // k1 stage: K=128 (A 16K + B 8K)
#define DSM1  49152
#define STG2  49152                // k2 stage: K=256 (A 32K + B 16K)
#define DSM2  98304

__device__ unsigned char g_AT[4 * 16 * ATILE];     // [mblk][ktile] fp16
__device__ unsigned char g_WT[64 * 16 * BTILE];    // [nblk][ktile] fp16
__device__ float         g_bias[NG];
__device__ __half2       g_x16 [BATCH * SEQ * (IN/2)];
__device__ __half2       g_Wa16[SEQ * (IN/2)];
__device__ float         g_c   [BATCH * H];
__device__ float         g_gates[BATCH * NG];      // h-half partial (+bias)

__device__ __forceinline__ uint32_t swz(uint32_t o) { return o ^ ((o >> 3) & 0x70u); }
__device__ __forceinline__ float sigf(float x) { return 1.0f / (1.0f + expf(-x)); }

__device__ __forceinline__ uint32_t smem_u32(const void* p) {
    uint32_t a;
    asm("{ .reg .u64 t; cvta.to.shared.u64 t, %1; cvt.u32.u64 %0, t; }" : "=r"(a) : "l"(p));
    return a;
}
#define MBAR_INIT(a, n) asm volatile("mbarrier.init.shared.b64 [%0], %1;" :: "r"(a), "r"(n) : "memory")
#define MBAR_EXPECT_TX(a, b) asm volatile("mbarrier.arrive.expect_tx.shared.b64 _, [%0], %1;" :: "r"(a), "r"(b) : "memory")
#define MBAR_WAIT(a, par) do { \
    asm volatile("{ .reg .pred P; WL%=: mbarrier.try_wait.parity.acquire.cta.shared::cta.b64 P, [%0], %1, 0x989680; @P bra.uni WD%=; bra.uni WL%=; WD%=: }" \
                 :: "r"(a), "r"(par) : "memory"); } while (0)

__device__ __forceinline__ void bulk_g2s(uint32_t dst, const void* src, uint32_t bytes, uint32_t mbar) {
    asm volatile("cp.async.bulk.shared::cluster.global.mbarrier::complete_tx::bytes [%0], [%1], %2, [%3];"
                 :: "r"(dst), "l"(src), "r"(bytes), "r"(mbar) : "memory");
}

__device__ __forceinline__ void ldm_x4(uint32_t* r, const void* p) {
    uint32_t a = smem_u32(p);
    asm volatile("ldmatrix.sync.aligned.m8n8.x4.shared.b16 {%0,%1,%2,%3}, [%4];"
                 : "=r"(r[0]), "=r"(r[1]), "=r"(r[2]), "=r"(r[3]) : "r"(a));
}
__device__ __forceinline__ void mma16816(float* c, const uint32_t* a, uint32_t b0, uint32_t b1) {
    asm volatile(
        "mma.sync.aligned.m16n8k16.row.col.f32.f16.f16.f32 "
        "{%0,%1,%2,%3}, {%4,%5,%6,%7}, {%8,%9}, {%0,%1,%2,%3};"
        : "+f"(c[0]), "+f"(c[1]), "+f"(c[2]), "+f"(c[3])
        : "r"(a[0]), "r"(a[1]), "r"(a[2]), "r"(a[3]), "r"(b0), "r"(b1));
}

// K=64 subtile compute: A at a_base, B at b_base
__device__ __forceinline__ void compute_k64(const unsigned char* A, const unsigned char* B,
                                            int wm, int wn, int lane, float acc[2][4]) {
    #pragma unroll
    for (int kq = 0; kq < 4; kq++) {
        const int kb = kq * 16;
        uint32_t fa[4], fb[4];
        const uint32_t oa = swz((wm + (lane & 15)) * 128 + (kb + (lane >> 4) * 8) * 2);
        ldm_x4(fa, A + oa);
        const int br = wn + (lane & 7) + ((lane >> 4) << 3);
        const uint32_t ob = swz(br * 128 + (kb + ((lane >> 3) & 1) * 8) * 2);
        ldm_x4(fb, B + ob);
        #pragma unroll
        for (int ni = 0; ni < 2; ni++)
            mma16816(acc[ni], fa, fb[ni * 2], fb[ni * 2 + 1]);
    }
}

// ---------------- prep ---------------------------------------------------------
__global__ void prep_a(const float* __restrict__ W_ih, const float* __restrict__ W_hh,
                       const float* __restrict__ b_ih, const float* __restrict__ b_hh) {
    int i = blockIdx.x * blockDim.x + threadIdx.x;      // 2,097,152
    int n = i >> 10, kc = i & 1023;
    int j = (n & 3) * 512 + (n >> 2);
    float w = (kc < IN) ? W_ih[j * IN + kc] : W_hh[j * H + (kc - IN)];
    uint32_t off = (uint32_t)((n >> 5) * 16 + (kc >> 6)) * BTILE + swz((n & 31) * 128 + (kc & 63) * 2);
    *(__half*)(g_WT + off) = __float2half_rn(w);
    if (i < NG) {
        int jb = (i & 3) * 512 + (i >> 2);
        g_bias[i] = b_ih[jb] + b_hh[jb];
    }
}

__global__ void prep_b(const float* __restrict__ x, const float* __restrict__ Wa) {
    int blk = blockIdx.x, tid = threadIdx.x;
    if (blk < 8192) {
        size_t i = (size_t)blk * 1024 + tid;
        float2 v = ((const float2*)x)[i];
        g_x16[i] = __floats2half2_rn(v.x, v.y);
    } else if (blk < 8224) {
        int i = (blk - 8192) * 1024 + tid;
        float2 v = ((const float2*)Wa)[i];
        g_Wa16[i] = __floats2half2_rn(v.x, v.y);
    } else {                                            // zero-input initial cell
        int b = (blk - 8224) * 2 + (tid >> 9);
        int k = tid & 511;
        float gi = g_bias[k * 4 + 0], gg = g_bias[k * 4 + 2], go = g_bias[k * 4 + 3];
        float c0 = sigf(gi) * tanhf(gg);
        float h0 = sigf(go) * tanhf(c0);
        g_c[b * H + k] = c0;
        uint32_t off = (uint32_t)((b >> 6) * 16 + 8 + (k >> 6)) * ATILE + swz((b & 63) * 128 + (k & 63) * 2);
        *(__half*)(g_AT + off) = __float2half_rn(h0);
    }
}

// ---------------- k1 GEMM: h-half, 4x24KB refill pipeline ----------------------
__device__ __forceinline__ void gemm_k1(unsigned char* sm, int bidx) {
    __shared__ __align__(8) uint64_t mbar[2];
    const int tid = threadIdx.x, lane = tid & 31, warp = tid >> 5;
    const int bn = bidx & 63, bm = bidx >> 6;
    const int wm = (warp & 3) * 16, wn = (warp >> 2) * 16;

    // preload bias (epilogue operands)
    float pb0[2], pb1[2];
    #pragma unroll
    for (int ni = 0; ni < 2; ni++) {
        const int c = bn * 32 + wn + ni * 8 + (lane & 3) * 2;
        pb0[ni] = g_bias[c];
        pb1[ni] = g_bias[c + 1];
    }

    if (tid == 0) { MBAR_INIT(smem_u32(&mbar[0]), 1); MBAR_INIT(smem_u32(&mbar[1]), 1); }
    __syncthreads();

    const unsigned char* sA = g_AT + (bm * 16 + 8) * ATILE;
    const unsigned char* sB = g_WT + (bn * 16 + 8) * BTILE;
    const uint32_t smb = smem_u32(sm);

    auto prefetch = [&](int s) {
        uint32_t bar = smem_u32(&mbar[s & 1]);
        uint32_t d = smb + (s & 1) * STG1;
        MBAR_EXPECT_TX(bar, STG1);
        bulk_g2s(d,         sA + s * 2 * ATILE, 2 * ATILE, bar);
        bulk_g2s(d + 16384, sB + s * 2 * BTILE, 2 * BTILE, bar);
    };
    if (tid == 0) { prefetch(0); prefetch(1); }

    float acc[2][4] = {};
    #pragma unroll
    for (int s = 0; s < 4; s++) {
        MBAR_WAIT(smem_u32(&mbar[s & 1]), (s >> 1) & 1);
        unsigned char* base = sm + (s & 1) * STG1;
        compute_k64(base,         base + 16384,        wm, wn, lane, acc);
        compute_k64(base + ATILE, base + 16384 + BTILE, wm, wn, lane, acc);
        if (s + 2 < 4) {
            __syncthreads();
            if (tid == 0) prefetch(s + 2);
        }
    }

    #pragma unroll
    for (int ni = 0; ni < 2; ni++) {
        const int r = bm * 64 + wm + (lane >> 2);
        const int c = bn * 32 + wn + ni * 8 + (lane & 3) * 2;
        *(float2*)&g_gates[(size_t)r * NG + c] =
            make_float2(acc[ni][0] + pb0[ni], acc[ni][1] + pb1[ni]);
        *(float2*)&g_gates[(size_t)(r + 8) * NG + c] =
            make_float2(acc[ni][2] + pb0[ni], acc[ni][3] + pb1[ni]);
    }
}

// ---------------- k2 GEMM: xi-half, 2x48KB upfront + fused update --------------
__global__ void __launch_bounds__(256) k2_xgemm_update(float* __restrict__ out, int t) {
    extern __shared__ unsigned char sm[];
    __shared__ __align__(8) uint64_t mbar[2];
    const int tid = threadIdx.x, lane = tid & 31, warp = tid >> 5;
    const int bn = blockIdx.x & 63, bm = blockIdx.x >> 6;
    const int wm = (warp & 3) * 16, wn = (warp >> 2) * 16;

    // preload epilogue operands (g_gates partial from k1, g_c) — hides tail latency
    const int kl = tid & 7;
    const int k  = bn * 8 + kl;
    const int bl0 = tid >> 3, bl1 = bl0 + 32;
    const int batch0 = bm * 64 + bl0, batch1 = bm * 64 + bl1;
    const float4 gp0 = *(const float4*)&g_gates[(size_t)batch0 * NG + bn * 32 + kl * 4];
    const float4 gp1 = *(const float4*)&g_gates[(size_t)batch1 * NG + bn * 32 + kl * 4];
    const float cold0 = g_c[batch0 * H + k];
    const float cold1 = g_c[batch1 * H + k];

    if (tid == 0) { MBAR_INIT(smem_u32(&mbar[0]), 1); MBAR_INIT(smem_u32(&mbar[1]), 1); }
    __syncthreads();

    const unsigned char* sA = g_AT + (bm * 16) * ATILE;
    const unsigned char* sB = g_WT + (bn * 16) * BTILE;
    const uint32_t smb = smem_u32(sm);

    if (tid == 0) {                                    // ALL copies issued upfront
        #pragma unroll
        for (int s = 0; s < 2; s++) {
            uint32_t bar = smem_u32(&mbar[s]);
            uint32_t d = smb + s * STG2;
            MBAR_EXPECT_TX(bar, STG2);
            bulk_g2s(d,         sA + s * 4 * ATILE, 4 * ATILE, bar);
            bulk_g2s(d + 32768, sB + s * 4 * BTILE, 4 * BTILE, bar);
        }
    }

    float acc[2][4] = {};
    #pragma unroll
    for (int s = 0; s < 2; s++) {
        MBAR_WAIT(smem_u32(&mbar[s]), 0);
        unsigned char* base = sm + s * STG2;
        #pragma unroll
        for (int kt = 0; kt < 4; kt++)
            compute_k64(base + kt * ATILE, base + 32768 + kt * BTILE, wm, wn, lane, acc);
    }
    __syncthreads();                                   // before smem reuse for gsm

    float* gsm = (float*)sm;                           // [64][36]
    #pragma unroll
    for (int ni = 0; ni < 2; ni++) {
        const int r = wm + (lane >> 2);
        const int c = wn + ni * 8 + (lane & 3) * 2;
        gsm[r * 36 + c]           = acc[ni][0];
        gsm[r * 36 + c + 1]       = acc[ni][1];
        gsm[(r + 8) * 36 + c]     = acc[ni][2];
        gsm[(r + 8) * 36 + c + 1] = acc[ni][3];
    }
    __syncthreads();

    const uint32_t tbase = ((uint32_t)bm * 16 + 8 + (k >> 6)) * ATILE;   // h tiles
    {
        float4 g4 = *(const float4*)&gsm[bl0 * 36 + kl * 4];
        float gi = g4.x + gp0.x, gf = g4.y + gp0.y, gg = g4.z + gp0.z, go = g4.w + gp0.w;
        float cn = sigf(gf) * cold0 + sigf(gi) * tanhf(gg);
        float h  = sigf(go) * tanhf(cn);
        g_c[batch0 * H + k] = cn;
        *(__half*)(g_AT + tbase + swz(bl0 * 128 + (k & 63) * 2)) = __float2half_rn(h);
        out[((size_t)batch0 * SEQ + t) * H + k] = h;
    }
    {
        float4 g4 = *(const float4*)&gsm[bl1 * 36 + kl * 4];
        float gi = g4.x + gp1.x, gf = g4.y + gp1.y, gg = g4.z + gp1.z, go = g4.w + gp1.w;
        float cn = sigf(gf) * cold1 + sigf(gi) * tanhf(gg);
        float h  = sigf(go) * tanhf(cn);
        g_c[batch1 * H + k] = cn;
        *(__half*)(g_AT + tbase + swz(bl1 * 128 + (k & 63) * 2)) = __float2half_rn(h);
        out[((size_t)batch1 * SEQ + t) * H + k] = h;
    }
}

// ---------------- attention: 1 batch per block, 256 thr ------------------------
struct AttnS {
    float c_sm[IN];
    float logit[SEQ], attn[SEQ];
    float rmax[4], rsum[4];
    float xpart[4][IN];
};

__device__ __forceinline__ void attn_body(unsigned char* dyn, int b, const float* __restrict__ ba) {
    AttnS* s = (AttnS*)dyn;
    const int tid = threadIdx.x, lane = tid & 31, warp = tid >> 5;

    s->c_sm[tid]       = g_c[b * H + tid];
    s->c_sm[256 + tid] = g_c[b * H + 256 + tid];
    __syncthreads();

    float4 cf[4];
    #pragma unroll
    for (int j = 0; j < 4; j++) cf[j] = ((const float4*)s->c_sm)[j * 32 + lane];

    const uint2* wa = (const uint2*)g_Wa16;
    #pragma unroll 2
    for (int si = 0; si < 16; si++) {
        const int sq = warp * 16 + si;
        const uint2* wp = wa + sq * 128;
        float acc = 0.0f;
        #pragma unroll
        for (int j = 0; j < 4; j++) {
            uint2 v = wp[j * 32 + lane];
            float2 w0 = __half22float2(*(const __half2*)&v.x);
            float2 w1 = __half22float2(*(const __half2*)&v.y);
            acc += cf[j].x * w0.x + cf[j].y * w0.y + cf[j].z * w1.x + cf[j].w * w1.y;
        }
        #pragma unroll
        for (int off = 16; off > 0; off >>= 1) acc += __shfl_xor_sync(0xffffffffu, acc, off);
        if (lane == 0) s->logit[sq] = acc + ba[sq];
    }
    __syncthreads();

    if (tid < 128) {
        float l = s->logit[tid], m = l;
        #pragma unroll
        for (int off = 16; off > 0; off >>= 1) m = fmaxf(m, __shfl_xor_sync(0xffffffffu, m, off));
        if (lane == 0) s->rmax[tid >> 5] = m;
    }
    __syncthreads();
    if (tid < 128) {
        float m = fmaxf(fmaxf(s->rmax[0], s->rmax[1]), fmaxf(s->rmax[2], s->rmax[3]));
        float e = expf(s->logit[tid] - m);
        s->attn[tid] = e;
        #pragma unroll
        for (int off = 16; off > 0; off >>= 1) e += __shfl_xor_sync(0xffffffffu, e, off);
        if (lane == 0) s->rsum[tid >> 5] = e;
    }
    __syncthreads();
    const float inv = 1.0f / (s->rsum[0] + s->rsum[1] + s->rsum[2] + s->rsum[3]);

    {
        const int g = tid >> 6, cth = tid & 63;
        const uint4* xp = ((const uint4*)g_x16) + (size_t)b * SEQ * 64 + cth;
        float acc[8] = {};
        #pragma unroll 4
        for (int i = 0; i < 32; i++) {
            const int sq = g * 32 + i;
            const float a = s->attn[sq];
            uint4 v = xp[(size_t)sq * 64];
            float2 p0 = __half22float2(*(const __half2*)&v.x);
            float2 p1 = __half22float2(*(const __half2*)&v.y);
            float2 p2 = __half22float2(*(const __half2*)&v.z);
            float2 p3 = __half22float2(*(const __half2*)&v.w);
            acc[0] += a * p0.x; acc[1] += a * p0.y;
            acc[2] += a * p1.x; acc[3] += a * p1.y;
            acc[4] += a * p2.x; acc[5] += a * p2.y;
            acc[6] += a * p3.x; acc[7] += a * p3.y;
        }
        #pragma unroll
        for (int q = 0; q < 8; q++) s->xpart[g][cth * 8 + q] = acc[q];
    }
    __syncthreads();

    {
        const int d0 = tid * 2;
        float v0 = (s->xpart[0][d0]     + s->xpart[1][d0])     + (s->xpart[2][d0]     + s->xpart[3][d0]);
        float v1 = (s->xpart[0][d0 + 1] + s->xpart[1][d0 + 1]) + (s->xpart[2][d0 + 1] + s->xpart[3][d0 + 1]);
        v0 *= inv; v1 *= inv;
        uint32_t off = ((uint32_t)(b >> 6) * 16 + (d0 >> 6)) * ATILE + swz((b & 63) * 128 + (d0 & 63) * 2);
        *(__half2*)(g_AT + off) = __floats2half2_rn(v0, v1);
    }
}

// ---------------- k1: h-GEMM + attention -----------------------------------------
__global__ void __launch_bounds__(256) k1_hgemm_attn(const float* __restrict__ ba) {
    extern __shared__ unsigned char dyn[];
    if (blockIdx.x < 256) gemm_k1(dyn, blockIdx.x);
    else                  attn_body(dyn, blockIdx.x - 256, ba);
}

// ---------------- launcher -------------------------------------------------------
extern "C" void kernel_launch(void* const* d_in, const int* in_sizes, int n_in,
                              void* d_out, int out_size) {
    const float* x    = (const float*)d_in[0];
    const float* W_ih = (const float*)d_in[1];
    const float* W_hh = (const float*)d_in[2];
    const float* b_ih = (const float*)d_in[3];
    const float* b_hh = (const float*)d_in[4];
    const float* Wa   = (const float*)d_in[5];
    const float* ba   = (const float*)d_in[6];
    float* out = (float*)d_out;

    cudaFuncSetAttribute(k1_hgemm_attn,   cudaFuncAttributeMaxDynamicSharedMemorySize, DSM1);
    cudaFuncSetAttribute(k2_xgemm_update, cudaFuncAttributeMaxDynamicSharedMemorySize, DSM2);

    prep_a<<<2048, 1024>>>(W_ih, W_hh, b_ih, b_hh);
    prep_b<<<8352, 1024>>>(x, Wa);

    for (int t = 0; t < SEQ; t++) {
        k1_hgemm_attn  <<<512, 256, DSM1>>>(ba);
        k2_xgemm_update<<<256, 256, DSM2>>>(out, t);
    }
}

// round 12
// speedup vs baseline: 3.1229x; 1.0079x over previous
#include <cuda_runtime.h>
#include <cuda_bf16.h>
#include <cuda_fp16.h>
#include <cstdint>

// ---------------------------------------------------------------------------
// LSTM with attention-weighted inputs.  B=256, SEQ=128, IN=H=512.
// Gate dim PERMUTED: column n = 4*k + gate.
// A=[xi|h] fp16 tiles; W fp16 tiles, pre-swizzled (SW128) in gmem; K streamed
// via large cp.async.bulk copies.  Fat warp tiles + warp-level K-split cut
// smem LDSM traffic (k2: 256B/mma, k1: 384B/mma).
//   k1: blocks 0..255 h-half GEMM (K=512..1023) -> partial gates
//       blocks 256..511 attention + xi
//   k2: xi-half GEMM (K=0..511) + partial + bias -> fused LSTM update.
// (tcgen05 unavailable: harness PTX target is sm_103.)
// ---------------------------------------------------------------------------

#define BATCH 256
#define SEQ   128
#define IN    512
#define H     512
#define NG    2048
#define ATILE 8192                 // 64 rows x 128B (K=64 fp16)
#define BTILE 4096                 // 32 rows x 128B
#define STG1  24576                // k1 stage: K=128 (A 16K + B 8K)
#define DSM1  49152
#define STG2  49152                // k2 stage: K=256 (A 32K + B 16K)
#define DSM2  98304

__device__ unsigned char g_AT[4 * 16 * ATILE];     // [mblk][ktile] fp16
__device__ unsigned char g_WT[64 * 16 * BTILE];    // [nblk][ktile] fp16
__device__ float         g_bias[NG];
__device__ __half2       g_x16 [BATCH * SEQ * (IN/2)];
__device__ __half2       g_Wa16[SEQ * (IN/2)];
__device__ float         g_c   [BATCH * H];
__device__ float         g_gates[BATCH * NG];      // h-half partial

__device__ __forceinline__ uint32_t swz(uint32_t o) { return o ^ ((o >> 3) & 0x70u); }
__device__ __forceinline__ float sigf(float x) { return 1.0f / (1.0f + expf(-x)); }

__device__ __forceinline__ uint32_t smem_u32(const void* p) {
    uint32_t a;
    asm("{ .reg .u64 t; cvta.to.shared.u64 t, %1; cvt.u32.u64 %0, t; }" : "=r"(a) : "l"(p));
    return a;
}
#define MBAR_INIT(a, n) asm volatile("mbarrier.init.shared.b64 [%0], %1;" :: "r"(a), "r"(n) : "memory")
#define MBAR_EXPECT_TX(a, b) asm volatile("mbarrier.arrive.expect_tx.shared.b64 _, [%0], %1;" :: "r"(a), "r"(b) : "memory")
#define MBAR_WAIT(a, par) do { \
    asm volatile("{ .reg .pred P; WL%=: mbarrier.try_wait.parity.acquire.cta.shared::cta.b64 P, [%0], %1, 0x989680; @P bra.uni WD%=; bra.uni WL%=; WD%=: }" \
                 :: "r"(a), "r"(par) : "memory"); } while (0)

__device__ __forceinline__ void bulk_g2s(uint32_t dst, const void* src, uint32_t bytes, uint32_t mbar) {
    asm volatile("cp.async.bulk.shared::cluster.global.mbarrier::complete_tx::bytes [%0], [%1], %2, [%3];"
                 :: "r"(dst), "l"(src), "r"(bytes), "r"(mbar) : "memory");
}

__device__ __forceinline__ void ldm_x4(uint32_t* r, const void* p) {
    uint32_t a = smem_u32(p);
    asm volatile("ldmatrix.sync.aligned.m8n8.x4.shared.b16 {%0,%1,%2,%3}, [%4];"
                 : "=r"(r[0]), "=r"(r[1]), "=r"(r[2]), "=r"(r[3]) : "r"(a));
}
__device__ __forceinline__ void mma16816(float* c, const uint32_t* a, uint32_t b0, uint32_t b1) {
    asm volatile(
        "mma.sync.aligned.m16n8k16.row.col.f32.f16.f16.f32 "
        "{%0,%1,%2,%3}, {%4,%5,%6,%7}, {%8,%9}, {%0,%1,%2,%3};"
        : "+f"(c[0]), "+f"(c[1]), "+f"(c[2]), "+f"(c[3])
        : "r"(a[0]), "r"(a[1]), "r"(a[2]), "r"(a[3]), "r"(b0), "r"(b1));
}

// ---------------- prep ---------------------------------------------------------
__global__ void prep_a(const float* __restrict__ W_ih, const float* __restrict__ W_hh,
                       const float* __restrict__ b_ih, const float* __restrict__ b_hh) {
    int i = blockIdx.x * blockDim.x + threadIdx.x;      // 2,097,152
    int n = i >> 10, kc = i & 1023;
    int j = (n & 3) * 512 + (n >> 2);
    float w = (kc < IN) ? W_ih[j * IN + kc] : W_hh[j * H + (kc - IN)];
    uint32_t off = (uint32_t)((n >> 5) * 16 + (kc >> 6)) * BTILE + swz((n & 31) * 128 + (kc & 63) * 2);
    *(__half*)(g_WT + off) = __float2half_rn(w);
    if (i < NG) {
        int jb = (i & 3) * 512 + (i >> 2);
        g_bias[i] = b_ih[jb] + b_hh[jb];
    }
}

__global__ void prep_b(const float* __restrict__ x, const float* __restrict__ Wa) {
    int blk = blockIdx.x, tid = threadIdx.x;
    if (blk < 8192) {
        size_t i = (size_t)blk * 1024 + tid;
        float2 v = ((const float2*)x)[i];
        g_x16[i] = __floats2half2_rn(v.x, v.y);
    } else if (blk < 8224) {
        int i = (blk - 8192) * 1024 + tid;
        float2 v = ((const float2*)Wa)[i];
        g_Wa16[i] = __floats2half2_rn(v.x, v.y);
    } else {                                            // zero-input initial cell
        int b = (blk - 8224) * 2 + (tid >> 9);
        int k = tid & 511;
        float gi = g_bias[k * 4 + 0], gg = g_bias[k * 4 + 2], go = g_bias[k * 4 + 3];
        float c0 = sigf(gi) * tanhf(gg);
        float h0 = sigf(go) * tanhf(c0);
        g_c[b * H + k] = c0;
        uint32_t off = (uint32_t)((b >> 6) * 16 + 8 + (k >> 6)) * ATILE + swz((b & 63) * 128 + (k & 63) * 2);
        *(__half*)(g_AT + off) = __float2half_rn(h0);
    }
}

// 32m x 32n warp subtile over K=64: 16 LDSM, 32 mma
__device__ __forceinline__ void compute_3232(const unsigned char* A, const unsigned char* B,
                                             int wm, int lane, float acc[2][4][4]) {
    #pragma unroll
    for (int kq = 0; kq < 4; kq++) {
        const int kb = kq * 16;
        uint32_t a0[4], a1[4], b0[4], b1[4];
        const uint32_t kcol = (kb + (lane >> 4) * 8) * 2;
        ldm_x4(a0, A + swz((wm + (lane & 15)) * 128 + kcol));
        ldm_x4(a1, A + swz((wm + 16 + (lane & 15)) * 128 + kcol));
        const int br = (lane & 7) + ((lane >> 4) << 3);
        const uint32_t bk = (kb + ((lane >> 3) & 1) * 8) * 2;
        ldm_x4(b0, B + swz(br * 128 + bk));
        ldm_x4(b1, B + swz((br + 16) * 128 + bk));
        mma16816(acc[0][0], a0, b0[0], b0[1]);
        mma16816(acc[0][1], a0, b0[2], b0[3]);
        mma16816(acc[0][2], a0, b1[0], b1[1]);
        mma16816(acc[0][3], a0, b1[2], b1[3]);
        mma16816(acc[1][0], a1, b0[0], b0[1]);
        mma16816(acc[1][1], a1, b0[2], b0[3]);
        mma16816(acc[1][2], a1, b1[0], b1[1]);
        mma16816(acc[1][3], a1, b1[2], b1[3]);
    }
}

// 32m x 16n warp subtile over K=64: 12 LDSM, 16 mma
__device__ __forceinline__ void compute_3216(const unsigned char* A, const unsigned char* B,
                                             int wm, int wn, int lane, float acc[2][2][4]) {
    #pragma unroll
    for (int kq = 0; kq < 4; kq++) {
        const int kb = kq * 16;
        uint32_t a0[4], a1[4], b0[4];
        const uint32_t kcol = (kb + (lane >> 4) * 8) * 2;
        ldm_x4(a0, A + swz((wm + (lane & 15)) * 128 + kcol));
        ldm_x4(a1, A + swz((wm + 16 + (lane & 15)) * 128 + kcol));
        const int br = wn + (lane & 7) + ((lane >> 4) << 3);
        ldm_x4(b0, B + swz(br * 128 + (kb + ((lane >> 3) & 1) * 8) * 2));
        mma16816(acc[0][0], a0, b0[0], b0[1]);
        mma16816(acc[0][1], a0, b0[2], b0[3]);
        mma16816(acc[1][0], a1, b0[0], b0[1]);
        mma16816(acc[1][1], a1, b0[2], b0[3]);
    }
}

// ---------------- k1 GEMM: h-half, 4x24KB refill, 2-way K-split ----------------
__device__ __forceinline__ void gemm_k1(unsigned char* sm, int bidx) {
    __shared__ __align__(8) uint64_t mbar[2];
    const int tid = threadIdx.x, lane = tid & 31, warp = tid >> 5;
    const int bn = bidx & 63, bm = bidx >> 6;
    const int wk = warp & 1, wm = ((warp >> 1) & 1) * 32, wn = (warp >> 2) * 16;

    if (tid == 0) { MBAR_INIT(smem_u32(&mbar[0]), 1); MBAR_INIT(smem_u32(&mbar[1]), 1); }
    __syncthreads();

    const unsigned char* sA = g_AT + (bm * 16 + 8) * ATILE;
    const unsigned char* sB = g_WT + (bn * 16 + 8) * BTILE;
    const uint32_t smb = smem_u32(sm);

    auto prefetch = [&](int s) {
        uint32_t bar = smem_u32(&mbar[s & 1]);
        uint32_t d = smb + (s & 1) * STG1;
        MBAR_EXPECT_TX(bar, STG1);
        bulk_g2s(d,         sA + s * 2 * ATILE, 2 * ATILE, bar);
        bulk_g2s(d + 16384, sB + s * 2 * BTILE, 2 * BTILE, bar);
    };
    if (tid == 0) { prefetch(0); prefetch(1); }

    float acc[2][2][4] = {};
    #pragma unroll
    for (int s = 0; s < 4; s++) {
        MBAR_WAIT(smem_u32(&mbar[s & 1]), (s >> 1) & 1);
        unsigned char* base = sm + (s & 1) * STG1;
        compute_3216(base + wk * ATILE, base + 16384 + wk * BTILE, wm, wn, lane, acc);
        if (s + 2 < 4) {
            __syncthreads();
            if (tid == 0) prefetch(s + 2);
        }
    }
    __syncthreads();

    // stage K-split partials, reduce, add bias, store
    float* gsm = (float*)sm;                            // [2][64][36]
    float* gk = gsm + wk * 2304;
    #pragma unroll
    for (int mi = 0; mi < 2; mi++)
        #pragma unroll
        for (int ni = 0; ni < 2; ni++) {
            const int r = wm + mi * 16 + (lane >> 2);
            const int c = wn + ni * 8 + (lane & 3) * 2;
            gk[r * 36 + c]           = acc[mi][ni][0];
            gk[r * 36 + c + 1]       = acc[mi][ni][1];
            gk[(r + 8) * 36 + c]     = acc[mi][ni][2];
            gk[(r + 8) * 36 + c + 1] = acc[mi][ni][3];
        }
    __syncthreads();

    const int kl = tid & 7;
    const float4 bias = *(const float4*)&g_bias[bn * 32 + kl * 4];
    #pragma unroll
    for (int j = 0; j < 2; j++) {
        const int bl = (tid >> 3) + j * 32;
        float4 v0 = *(const float4*)&gsm[bl * 36 + kl * 4];
        float4 v1 = *(const float4*)&gsm[2304 + bl * 36 + kl * 4];
        float4 v = make_float4(v0.x + v1.x + bias.x, v0.y + v1.y + bias.y,
                               v0.z + v1.z + bias.z, v0.w + v1.w + bias.w);
        *(float4*)&g_gates[(size_t)(bm * 64 + bl) * NG + bn * 32 + kl * 4] = v;
    }
}

// ---------------- k2: xi-half GEMM (4-way K-split) + fused update --------------
__global__ void __launch_bounds__(256) k2_xgemm_update(float* __restrict__ out, int t) {
    extern __shared__ unsigned char sm[];
    __shared__ __align__(8) uint64_t mbar[2];
    const int tid = threadIdx.x, lane = tid & 31, warp = tid >> 5;
    const int bn = blockIdx.x & 63, bm = blockIdx.x >> 6;
    const int wk = warp & 3, wm = (warp >> 2) * 32;

    // preload epilogue operands (hides tail latency)
    const int kl = tid & 7;
    const int k  = bn * 8 + kl;
    const int bl0 = tid >> 3, bl1 = bl0 + 32;
    const int batch0 = bm * 64 + bl0, batch1 = bm * 64 + bl1;
    const float4 gp0 = *(const float4*)&g_gates[(size_t)batch0 * NG + bn * 32 + kl * 4];
    const float4 gp1 = *(const float4*)&g_gates[(size_t)batch1 * NG + bn * 32 + kl * 4];
    const float cold0 = g_c[batch0 * H + k];
    const float cold1 = g_c[batch1 * H + k];

    if (tid == 0) { MBAR_INIT(smem_u32(&mbar[0]), 1); MBAR_INIT(smem_u32(&mbar[1]), 1); }
    __syncthreads();

    const unsigned char* sA = g_AT + (bm * 16) * ATILE;
    const unsigned char* sB = g_WT + (bn * 16) * BTILE;
    const uint32_t smb = smem_u32(sm);

    if (tid == 0) {                                    // ALL copies issued upfront
        #pragma unroll
        for (int s = 0; s < 2; s++) {
            uint32_t bar = smem_u32(&mbar[s]);
            uint32_t d = smb + s * STG2;
            MBAR_EXPECT_TX(bar, STG2);
            bulk_g2s(d,         sA + s * 4 * ATILE, 4 * ATILE, bar);
            bulk_g2s(d + 32768, sB + s * 4 * BTILE, 4 * BTILE, bar);
        }
    }

    float acc[2][4][4] = {};
    #pragma unroll
    for (int s = 0; s < 2; s++) {
        MBAR_WAIT(smem_u32(&mbar[s]), 0);
        unsigned char* base = sm + s * STG2;
        compute_3232(base + wk * ATILE, base + 32768 + wk * BTILE, wm, lane, acc);
    }
    __syncthreads();                                   // all reads done; reuse smem

    float* gsm = (float*)sm;                           // [4][64][36]
    float* gk = gsm + wk * 2304;
    #pragma unroll
    for (int mi = 0; mi < 2; mi++)
        #pragma unroll
        for (int ni = 0; ni < 4; ni++) {
            const int r = wm + mi * 16 + (lane >> 2);
            const int c = ni * 8 + (lane & 3) * 2;
            gk[r * 36 + c]           = acc[mi][ni][0];
            gk[r * 36 + c + 1]       = acc[mi][ni][1];
            gk[(r + 8) * 36 + c]     = acc[mi][ni][2];
            gk[(r + 8) * 36 + c + 1] = acc[mi][ni][3];
        }
    __syncthreads();

    const uint32_t tbase = ((uint32_t)bm * 16 + 8 + (k >> 6)) * ATILE;   // h tiles
    {
        float4 s0 = *(const float4*)&gsm[bl0 * 36 + kl * 4];
        float4 s1 = *(const float4*)&gsm[2304 + bl0 * 36 + kl * 4];
        float4 s2 = *(const float4*)&gsm[4608 + bl0 * 36 + kl * 4];
        float4 s3 = *(const float4*)&gsm[6912 + bl0 * 36 + kl * 4];
        float gi = s0.x + s1.x + s2.x + s3.x + gp0.x;
        float gf = s0.y + s1.y + s2.y + s3.y + gp0.y;
        float gg = s0.z + s1.z + s2.z + s3.z + gp0.z;
        float go = s0.w + s1.w + s2.w + s3.w + gp0.w;
        float cn = sigf(gf) * cold0 + sigf(gi) * tanhf(gg);
        float h  = sigf(go) * tanhf(cn);
        g_c[batch0 * H + k] = cn;
        *(__half*)(g_AT + tbase + swz(bl0 * 128 + (k & 63) * 2)) = __float2half_rn(h);
        out[((size_t)batch0 * SEQ + t) * H + k] = h;
    }
    {
        float4 s0 = *(const float4*)&gsm[bl1 * 36 + kl * 4];
        float4 s1 = *(const float4*)&gsm[2304 + bl1 * 36 + kl * 4];
        float4 s2 = *(const float4*)&gsm[4608 + bl1 * 36 + kl * 4];
        float4 s3 = *(const float4*)&gsm[6912 + bl1 * 36 + kl * 4];
        float gi = s0.x + s1.x + s2.x + s3.x + gp1.x;
        float gf = s0.y + s1.y + s2.y + s3.y + gp1.y;
        float gg = s0.z + s1.z + s2.z + s3.z + gp1.z;
        float go = s0.w + s1.w + s2.w + s3.w + gp1.w;
        float cn = sigf(gf) * cold1 + sigf(gi) * tanhf(gg);
        float h  = sigf(go) * tanhf(cn);
        g_c[batch1 * H + k] = cn;
        *(__half*)(g_AT + tbase + swz(bl1 * 128 + (k & 63) * 2)) = __float2half_rn(h);
        out[((size_t)batch1 * SEQ + t) * H + k] = h;
    }
}

// ---------------- attention: 1 batch per block, 256 thr ------------------------
struct AttnS {
    float c_sm[IN];
    float logit[SEQ], attn[SEQ];
    float rmax[4], rsum[4];
    float xpart[4][IN];
};

__device__ __forceinline__ void attn_body(unsigned char* dyn, int b, const float* __restrict__ ba) {
    AttnS* s = (AttnS*)dyn;
    const int tid = threadIdx.x, lane = tid & 31, warp = tid >> 5;

    s->c_sm[tid]       = g_c[b * H + tid];
    s->c_sm[256 + tid] = g_c[b * H + 256 + tid];
    __syncthreads();

    float4 cf[4];
    #pragma unroll
    for (int j = 0; j < 4; j++) cf[j] = ((const float4*)s->c_sm)[j * 32 + lane];

    const uint2* wa = (const uint2*)g_Wa16;
    #pragma unroll 2
    for (int si = 0; si < 16; si++) {
        const int sq = warp * 16 + si;
        const uint2* wp = wa + sq * 128;
        float acc = 0.0f;
        #pragma unroll
        for (int j = 0; j < 4; j++) {
            uint2 v = wp[j * 32 + lane];
            float2 w0 = __half22float2(*(const __half2*)&v.x);
            float2 w1 = __half22float2(*(const __half2*)&v.y);
            acc += cf[j].x * w0.x + cf[j].y * w0.y + cf[j].z * w1.x + cf[j].w * w1.y;
        }
        #pragma unroll
        for (int off = 16; off > 0; off >>= 1) acc += __shfl_xor_sync(0xffffffffu, acc, off);
        if (lane == 0) s->logit[sq] = acc + ba[sq];
    }
    __syncthreads();

    if (tid < 128) {
        float l = s->logit[tid], m = l;
        #pragma unroll
        for (int off = 16; off > 0; off >>= 1) m = fmaxf(m, __shfl_xor_sync(0xffffffffu, m, off));
        if (lane == 0) s->rmax[tid >> 5] = m;
    }
    __syncthreads();
    if (tid < 128) {
        float m = fmaxf(fmaxf(s->rmax[0], s->rmax[1]), fmaxf(s->rmax[2], s->rmax[3]));
        float e = expf(s->logit[tid] - m);
        s->attn[tid] = e;
        #pragma unroll
        for (int off = 16; off > 0; off >>= 1) e += __shfl_xor_sync(0xffffffffu, e, off);
        if (lane == 0) s->rsum[tid >> 5] = e;
    }
    __syncthreads();
    const float inv = 1.0f / (s->rsum[0] + s->rsum[1] + s->rsum[2] + s->rsum[3]);

    {
        const int g = tid >> 6, cth = tid & 63;
        const uint4* xp = ((const uint4*)g_x16) + (size_t)b * SEQ * 64 + cth;
        float acc[8] = {};
        #pragma unroll 4
        for (int i = 0; i < 32; i++) {
            const int sq = g * 32 + i;
            const float a = s->attn[sq];
            uint4 v = xp[(size_t)sq * 64];
            float2 p0 = __half22float2(*(const __half2*)&v.x);
            float2 p1 = __half22float2(*(const __half2*)&v.y);
            float2 p2 = __half22float2(*(const __half2*)&v.z);
            float2 p3 = __half22float2(*(const __half2*)&v.w);
            acc[0] += a * p0.x; acc[1] += a * p0.y;
            acc[2] += a * p1.x; acc[3] += a * p1.y;
            acc[4] += a * p2.x; acc[5] += a * p2.y;
            acc[6] += a * p3.x; acc[7] += a * p3.y;
        }
        #pragma unroll
        for (int q = 0; q < 8; q++) s->xpart[g][cth * 8 + q] = acc[q];
    }
    __syncthreads();

    {
        const int d0 = tid * 2;
        float v0 = (s->xpart[0][d0]     + s->xpart[1][d0])     + (s->xpart[2][d0]     + s->xpart[3][d0]);
        float v1 = (s->xpart[0][d0 + 1] + s->xpart[1][d0 + 1]) + (s->xpart[2][d0 + 1] + s->xpart[3][d0 + 1]);
        v0 *= inv; v1 *= inv;
        uint32_t off = ((uint32_t)(b >> 6) * 16 + (d0 >> 6)) * ATILE + swz((b & 63) * 128 + (d0 & 63) * 2);
        *(__half2*)(g_AT + off) = __floats2half2_rn(v0, v1);
    }
}

// ---------------- k1: h-GEMM + attention -----------------------------------------
__global__ void __launch_bounds__(256) k1_hgemm_attn(const float* __restrict__ ba) {
    extern __shared__ unsigned char dyn[];
    if (blockIdx.x < 256) gemm_k1(dyn, blockIdx.x);
    else                  attn_body(dyn, blockIdx.x - 256, ba);
}

// ---------------- launcher -------------------------------------------------------
extern "C" void kernel_launch(void* const* d_in, const int* in_sizes, int n_in,
                              void* d_out, int out_size) {
    const float* x    = (const float*)d_in[0];
    const float* W_ih = (const float*)d_in[1];
    const float* W_hh = (const float*)d_in[2];
    const float* b_ih = (const float*)d_in[3];
    const float* b_hh = (const float*)d_in[4];
    const float* Wa   = (const float*)d_in[5];
    const float* ba   = (const float*)d_in[6];
    float* out = (float*)d_out;

    cudaFuncSetAttribute(k1_hgemm_attn,   cudaFuncAttributeMaxDynamicSharedMemorySize, DSM1);
    cudaFuncSetAttribute(k2_xgemm_update, cudaFuncAttributeMaxDynamicSharedMemorySize, DSM2);

    prep_a<<<2048, 1024>>>(W_ih, W_hh, b_ih, b_hh);
    prep_b<<<8352, 1024>>>(x, Wa);

    for (int t = 0; t < SEQ; t++) {
        k1_hgemm_attn  <<<512, 256, DSM1>>>(ba);
        k2_xgemm_update<<<256, 256, DSM2>>>(out, t);
    }
}

// round 13
// speedup vs baseline: 3.5472x; 1.1358x over previous
#include <cuda_runtime.h>
#include <cuda_bf16.h>
#include <cuda_fp16.h>
#include <cstdint>

// ---------------------------------------------------------------------------
// LSTM with attention-weighted inputs.  B=256, SEQ=128, IN=H=512.
// Gate dim PERMUTED: column n = 4*k + gate.
// A=[xi|h] fp16 tiles; W fp16 tiles, pre-swizzled (SW128) in gmem.
// PDL (griddepcontrol): each step kernel prefetches its W slab into smem
// while the PREVIOUS kernel is still running, then waits; A streams in fine
// stages after the wait.  W resident in smem for the whole kernel.
//   k1: blocks 0..255 h-half GEMM -> partial gates(+bias); 256..511 attn+xi
//   k2: xi-half GEMM + partial -> fused LSTM update, h tiles out.
// (tcgen05 unavailable: harness PTX target is sm_103.)
// ---------------------------------------------------------------------------

#define BATCH 256
#define SEQ   128
#define IN    512
#define H     512
#define NG    2048
#define ATILE 8192                 // 64 rows x 128B (K=64 fp16)
#define BTILE 4096                 // 32 rows x 128B
#define DSM1  49152                // k1: W 32K + A 2x8K
#define DSM2  98304                // k2: W 32K + A 4x16K

__device__ unsigned char g_AT[4 * 16 * ATILE];     // [mblk][ktile] fp16
__device__ unsigned char g_WT[64 * 16 * BTILE];    // [nblk][ktile] fp16
__device__ float         g_bias[NG];
__device__ __half2       g_x16 [BATCH * SEQ * (IN/2)];
__device__ __half2       g_Wa16[SEQ * (IN/2)];
__device__ float         g_c   [BATCH * H];
__device__ float         g_gates[BATCH * NG];      // h-half partial (+bias)

__device__ __forceinline__ uint32_t swz(uint32_t o) { return o ^ ((o >> 3) & 0x70u); }
__device__ __forceinline__ float sigf(float x) { return 1.0f / (1.0f + expf(-x)); }

__device__ __forceinline__ uint32_t smem_u32(const void* p) {
    uint32_t a;
    asm("{ .reg .u64 t; cvta.to.shared.u64 t, %1; cvt.u32.u64 %0, t; }" : "=r"(a) : "l"(p));
    return a;
}
#define GRIDDEP_LAUNCH asm volatile("griddepcontrol.launch_dependents;" ::: "memory")
#define GRIDDEP_WAIT   asm volatile("griddepcontrol.wait;" ::: "memory")
#define MBAR_INIT(a, n) asm volatile("mbarrier.init.shared.b64 [%0], %1;" :: "r"(a), "r"(n) : "memory")
#define MBAR_EXPECT_TX(a, b) asm volatile("mbarrier.arrive.expect_tx.shared.b64 _, [%0], %1;" :: "r"(a), "r"(b) : "memory")
#define MBAR_WAIT(a, par) do { \
    asm volatile("{ .reg .pred P; WL%=: mbarrier.try_wait.parity.acquire.cta.shared::cta.b64 P, [%0], %1, 0x989680; @P bra.uni WD%=; bra.uni WL%=; WD%=: }" \
                 :: "r"(a), "r"(par) : "memory"); } while (0)

__device__ __forceinline__ void bulk_g2s(uint32_t dst, const void* src, uint32_t bytes, uint32_t mbar) {
    asm volatile("cp.async.bulk.shared::cluster.global.mbarrier::complete_tx::bytes [%0], [%1], %2, [%3];"
                 :: "r"(dst), "l"(src), "r"(bytes), "r"(mbar) : "memory");
}

__device__ __forceinline__ void ldm_x4(uint32_t* r, const void* p) {
    uint32_t a = smem_u32(p);
    asm volatile("ldmatrix.sync.aligned.m8n8.x4.shared.b16 {%0,%1,%2,%3}, [%4];"
                 : "=r"(r[0]), "=r"(r[1]), "=r"(r[2]), "=r"(r[3]) : "r"(a));
}
__device__ __forceinline__ void mma16816(float* c, const uint32_t* a, uint32_t b0, uint32_t b1) {
    asm volatile(
        "mma.sync.aligned.m16n8k16.row.col.f32.f16.f16.f32 "
        "{%0,%1,%2,%3}, {%4,%5,%6,%7}, {%8,%9}, {%0,%1,%2,%3};"
        : "+f"(c[0]), "+f"(c[1]), "+f"(c[2]), "+f"(c[3])
        : "r"(a[0]), "r"(a[1]), "r"(a[2]), "r"(a[3]), "r"(b0), "r"(b1));
}

// ---------------- prep ---------------------------------------------------------
__global__ void prep_a(const float* __restrict__ W_ih, const float* __restrict__ W_hh,
                       const float* __restrict__ b_ih, const float* __restrict__ b_hh) {
    int i = blockIdx.x * blockDim.x + threadIdx.x;
    int n = i >> 10, kc = i & 1023;
    int j = (n & 3) * 512 + (n >> 2);
    float w = (kc < IN) ? W_ih[j * IN + kc] : W_hh[j * H + (kc - IN)];
    uint32_t off = (uint32_t)((n >> 5) * 16 + (kc >> 6)) * BTILE + swz((n & 31) * 128 + (kc & 63) * 2);
    *(__half*)(g_WT + off) = __float2half_rn(w);
    if (i < NG) {
        int jb = (i & 3) * 512 + (i >> 2);
        g_bias[i] = b_ih[jb] + b_hh[jb];
    }
}

__global__ void prep_b(const float* __restrict__ x, const float* __restrict__ Wa) {
    int blk = blockIdx.x, tid = threadIdx.x;
    if (blk < 8192) {
        size_t i = (size_t)blk * 1024 + tid;
        float2 v = ((const float2*)x)[i];
        g_x16[i] = __floats2half2_rn(v.x, v.y);
    } else if (blk < 8224) {
        int i = (blk - 8192) * 1024 + tid;
        float2 v = ((const float2*)Wa)[i];
        g_Wa16[i] = __floats2half2_rn(v.x, v.y);
    } else {
        int b = (blk - 8224) * 2 + (tid >> 9);
        int k = tid & 511;
        float gi = g_bias[k * 4 + 0], gg = g_bias[k * 4 + 2], go = g_bias[k * 4 + 3];
        float c0 = sigf(gi) * tanhf(gg);
        float h0 = sigf(go) * tanhf(c0);
        g_c[b * H + k] = c0;
        uint32_t off = (uint32_t)((b >> 6) * 16 + 8 + (k >> 6)) * ATILE + swz((b & 63) * 128 + (k & 63) * 2);
        *(__half*)(g_AT + off) = __float2half_rn(h0);
    }
}

// 32m x 16n over 2 kq (K=32): 6 LDSM, 8 mma
__device__ __forceinline__ void c3216(const unsigned char* A, const unsigned char* B,
                                      int wm, int wn, int lane, int kq0, float acc[2][2][4]) {
    #pragma unroll
    for (int q = 0; q < 2; q++) {
        const int kb = (kq0 + q) * 16;
        uint32_t a0[4], a1[4], b0[4];
        const uint32_t kcol = (kb + (lane >> 4) * 8) * 2;
        ldm_x4(a0, A + swz((wm + (lane & 15)) * 128 + kcol));
        ldm_x4(a1, A + swz((wm + 16 + (lane & 15)) * 128 + kcol));
        const int br = wn + (lane & 7) + ((lane >> 4) << 3);
        ldm_x4(b0, B + swz(br * 128 + (kb + ((lane >> 3) & 1) * 8) * 2));
        mma16816(acc[0][0], a0, b0[0], b0[1]);
        mma16816(acc[0][1], a0, b0[2], b0[3]);
        mma16816(acc[1][0], a1, b0[0], b0[1]);
        mma16816(acc[1][1], a1, b0[2], b0[3]);
    }
}

// 32m x 32n over 2 kq (K=32): 8 LDSM, 16 mma
__device__ __forceinline__ void c3232(const unsigned char* A, const unsigned char* B,
                                      int wm, int lane, int kq0, float acc[2][4][4]) {
    #pragma unroll
    for (int q = 0; q < 2; q++) {
        const int kb = (kq0 + q) * 16;
        uint32_t a0[4], a1[4], b0[4], b1[4];
        const uint32_t kcol = (kb + (lane >> 4) * 8) * 2;
        ldm_x4(a0, A + swz((wm + (lane & 15)) * 128 + kcol));
        ldm_x4(a1, A + swz((wm + 16 + (lane & 15)) * 128 + kcol));
        const int br = (lane & 7) + ((lane >> 4) << 3);
        const uint32_t bk = (kb + ((lane >> 3) & 1) * 8) * 2;
        ldm_x4(b0, B + swz(br * 128 + bk));
        ldm_x4(b1, B + swz((br + 16) * 128 + bk));
        mma16816(acc[0][0], a0, b0[0], b0[1]);
        mma16816(acc[0][1], a0, b0[2], b0[3]);
        mma16816(acc[0][2], a0, b1[0], b1[1]);
        mma16816(acc[0][3], a0, b1[2], b1[3]);
        mma16816(acc[1][0], a1, b0[0], b0[1]);
        mma16816(acc[1][1], a1, b0[2], b0[3]);
        mma16816(acc[1][2], a1, b1[0], b1[1]);
        mma16816(acc[1][3], a1, b1[2], b1[3]);
    }
}

// ---------------- k1 GEMM: h-half, W resident, A 8x8KB stages ------------------
__device__ __forceinline__ void gemm_k1(unsigned char* sm, int bidx) {
    __shared__ __align__(8) uint64_t wbar, abar[2];
    const int tid = threadIdx.x, lane = tid & 31, warp = tid >> 5;
    const int bn = bidx & 63, bm = bidx >> 6;
    const int wk = warp & 1, wm = ((warp >> 1) & 1) * 32, wn = (warp >> 2) * 16;

    if (tid == 0) {
        MBAR_INIT(smem_u32(&wbar), 1);
        MBAR_INIT(smem_u32(&abar[0]), 1);
        MBAR_INIT(smem_u32(&abar[1]), 1);
    }
    __syncthreads();

    // prologue (overlaps previous kernel): W slab, static data
    if (tid == 0) {
        MBAR_EXPECT_TX(smem_u32(&wbar), 32768);
        bulk_g2s(smem_u32(sm), g_WT + (size_t)(bn * 16 + 8) * BTILE, 32768, smem_u32(&wbar));
    }
    GRIDDEP_WAIT;                                       // prev kernel complete

    const unsigned char* sA = g_AT + (size_t)(bm * 16 + 8) * ATILE;
    const uint32_t smA = smem_u32(sm) + 32768;
    if (tid == 0) {
        MBAR_EXPECT_TX(smem_u32(&abar[0]), 8192);
        bulk_g2s(smA, sA, 8192, smem_u32(&abar[0]));
        MBAR_EXPECT_TX(smem_u32(&abar[1]), 8192);
        bulk_g2s(smA + 8192, sA + ATILE, 8192, smem_u32(&abar[1]));
    }
    MBAR_WAIT(smem_u32(&wbar), 0);

    float acc[2][2][4] = {};
    for (int s = 0; s < 8; s++) {
        MBAR_WAIT(smem_u32(&abar[s & 1]), (s >> 1) & 1);
        c3216(sm + 32768 + (s & 1) * 8192, sm + s * BTILE, wm, wn, lane, wk * 2, acc);
        __syncthreads();
        if (tid == 0 && s + 2 < 8) {
            MBAR_EXPECT_TX(smem_u32(&abar[s & 1]), 8192);
            bulk_g2s(smA + (s & 1) * 8192, sA + (size_t)(s + 2) * ATILE, 8192, smem_u32(&abar[s & 1]));
        }
    }

    float* gsm = (float*)sm;                            // reuse W region: [2][64][36]
    float* gk = gsm + wk * 2304;
    #pragma unroll
    for (int mi = 0; mi < 2; mi++)
        #pragma unroll
        for (int ni = 0; ni < 2; ni++) {
            const int r = wm + mi * 16 + (lane >> 2);
            const int c = wn + ni * 8 + (lane & 3) * 2;
            gk[r * 36 + c]           = acc[mi][ni][0];
            gk[r * 36 + c + 1]       = acc[mi][ni][1];
            gk[(r + 8) * 36 + c]     = acc[mi][ni][2];
            gk[(r + 8) * 36 + c + 1] = acc[mi][ni][3];
        }
    __syncthreads();

    const int kl = tid & 7;
    const float4 bias = *(const float4*)&g_bias[bn * 32 + kl * 4];
    #pragma unroll
    for (int j = 0; j < 2; j++) {
        const int bl = (tid >> 3) + j * 32;
        float4 v0 = *(const float4*)&gsm[bl * 36 + kl * 4];
        float4 v1 = *(const float4*)&gsm[2304 + bl * 36 + kl * 4];
        float4 v = make_float4(v0.x + v1.x + bias.x, v0.y + v1.y + bias.y,
                               v0.z + v1.z + bias.z, v0.w + v1.w + bias.w);
        *(float4*)&g_gates[(size_t)(bm * 64 + bl) * NG + bn * 32 + kl * 4] = v;
    }
}

// ---------------- k2: xi-half GEMM, W resident, A 4x16KB, fused update ---------
__global__ void __launch_bounds__(256, 2) k2_xgemm_update(float* __restrict__ out, int t) {
    extern __shared__ unsigned char sm[];
    __shared__ __align__(8) uint64_t wbar, abar[4];
    GRIDDEP_LAUNCH;
    const int tid = threadIdx.x, lane = tid & 31, warp = tid >> 5;
    const int bn = blockIdx.x & 63, bm = blockIdx.x >> 6;
    const int wk = warp & 3, wm = (warp >> 2) * 32;

    if (tid == 0) {
        MBAR_INIT(smem_u32(&wbar), 1);
        #pragma unroll
        for (int i = 0; i < 4; i++) MBAR_INIT(smem_u32(&abar[i]), 1);
    }
    __syncthreads();

    // prologue (overlaps k1): W slab
    if (tid == 0) {
        MBAR_EXPECT_TX(smem_u32(&wbar), 32768);
        bulk_g2s(smem_u32(sm), g_WT + (size_t)(bn * 16) * BTILE, 32768, smem_u32(&wbar));
    }
    GRIDDEP_WAIT;                                       // k1 complete

    // epilogue operands (depend on k1 / previous k2)
    const int kl = tid & 7;
    const int k  = bn * 8 + kl;
    const int bl0 = tid >> 3, bl1 = bl0 + 32;
    const int batch0 = bm * 64 + bl0, batch1 = bm * 64 + bl1;
    const float4 gp0 = *(const float4*)&g_gates[(size_t)batch0 * NG + bn * 32 + kl * 4];
    const float4 gp1 = *(const float4*)&g_gates[(size_t)batch1 * NG + bn * 32 + kl * 4];
    const float cold0 = g_c[batch0 * H + k];
    const float cold1 = g_c[batch1 * H + k];

    const unsigned char* sA = g_AT + (size_t)(bm * 16) * ATILE;
    if (tid == 0) {
        #pragma unroll
        for (int s = 0; s < 4; s++) {
            MBAR_EXPECT_TX(smem_u32(&abar[s]), 16384);
            bulk_g2s(smem_u32(sm) + 32768 + s * 16384, sA + (size_t)s * 2 * ATILE, 16384,
                     smem_u32(&abar[s]));
        }
    }
    MBAR_WAIT(smem_u32(&wbar), 0);

    float acc[2][4][4] = {};
    #pragma unroll
    for (int s = 0; s < 4; s++) {
        MBAR_WAIT(smem_u32(&abar[s]), 0);
        const unsigned char* A = sm + 32768 + s * 16384 + (wk & 1) * ATILE;
        const unsigned char* B = sm + (2 * s + (wk & 1)) * BTILE;
        c3232(A, B, wm, lane, (wk >> 1) * 2, acc);
    }
    __syncthreads();

    float* gsm = (float*)sm;                            // [4][64][36]
    float* gk = gsm + wk * 2304;
    #pragma unroll
    for (int mi = 0; mi < 2; mi++)
        #pragma unroll
        for (int ni = 0; ni < 4; ni++) {
            const int r = wm + mi * 16 + (lane >> 2);
            const int c = ni * 8 + (lane & 3) * 2;
            gk[r * 36 + c]           = acc[mi][ni][0];
            gk[r * 36 + c + 1]       = acc[mi][ni][1];
            gk[(r + 8) * 36 + c]     = acc[mi][ni][2];
            gk[(r + 8) * 36 + c + 1] = acc[mi][ni][3];
        }
    __syncthreads();

    const uint32_t tbase = ((uint32_t)bm * 16 + 8 + (k >> 6)) * ATILE;
    {
        float4 s0 = *(const float4*)&gsm[bl0 * 36 + kl * 4];
        float4 s1 = *(const float4*)&gsm[2304 + bl0 * 36 + kl * 4];
        float4 s2 = *(const float4*)&gsm[4608 + bl0 * 36 + kl * 4];
        float4 s3 = *(const float4*)&gsm[6912 + bl0 * 36 + kl * 4];
        float gi = s0.x + s1.x + s2.x + s3.x + gp0.x;
        float gf = s0.y + s1.y + s2.y + s3.y + gp0.y;
        float gg = s0.z + s1.z + s2.z + s3.z + gp0.z;
        float go = s0.w + s1.w + s2.w + s3.w + gp0.w;
        float cn = sigf(gf) * cold0 + sigf(gi) * tanhf(gg);
        float h  = sigf(go) * tanhf(cn);
        g_c[batch0 * H + k] = cn;
        *(__half*)(g_AT + tbase + swz(bl0 * 128 + (k & 63) * 2)) = __float2half_rn(h);
        out[((size_t)batch0 * SEQ + t) * H + k] = h;
    }
    {
        float4 s0 = *(const float4*)&gsm[bl1 * 36 + kl * 4];
        float4 s1 = *(const float4*)&gsm[2304 + bl1 * 36 + kl * 4];
        float4 s2 = *(const float4*)&gsm[4608 + bl1 * 36 + kl * 4];
        float4 s3 = *(const float4*)&gsm[6912 + bl1 * 36 + kl * 4];
        float gi = s0.x + s1.x + s2.x + s3.x + gp1.x;
        float gf = s0.y + s1.y + s2.y + s3.y + gp1.y;
        float gg = s0.z + s1.z + s2.z + s3.z + gp1.z;
        float go = s0.w + s1.w + s2.w + s3.w + gp1.w;
        float cn = sigf(gf) * cold1 + sigf(gi) * tanhf(gg);
        float h  = sigf(go) * tanhf(cn);
        g_c[batch1 * H + k] = cn;
        *(__half*)(g_AT + tbase + swz(bl1 * 128 + (k & 63) * 2)) = __float2half_rn(h);
        out[((size_t)batch1 * SEQ + t) * H + k] = h;
    }
}

// ---------------- attention: 1 batch per block, 256 thr ------------------------
struct AttnS {
    float c_sm[IN];
    float logit[SEQ], attn[SEQ];
    float rmax[4], rsum[4];
    float xpart[4][IN];
};

__device__ __forceinline__ void attn_body(unsigned char* dyn, int b, const float* __restrict__ ba) {
    AttnS* s = (AttnS*)dyn;
    const int tid = threadIdx.x, lane = tid & 31, warp = tid >> 5;

    s->c_sm[tid]       = g_c[b * H + tid];
    s->c_sm[256 + tid] = g_c[b * H + 256 + tid];
    __syncthreads();

    float4 cf[4];
    #pragma unroll
    for (int j = 0; j < 4; j++) cf[j] = ((const float4*)s->c_sm)[j * 32 + lane];

    const uint2* wa = (const uint2*)g_Wa16;
    #pragma unroll 2
    for (int si = 0; si < 16; si++) {
        const int sq = warp * 16 + si;
        const uint2* wp = wa + sq * 128;
        float acc = 0.0f;
        #pragma unroll
        for (int j = 0; j < 4; j++) {
            uint2 v = wp[j * 32 + lane];
            float2 w0 = __half22float2(*(const __half2*)&v.x);
            float2 w1 = __half22float2(*(const __half2*)&v.y);
            acc += cf[j].x * w0.x + cf[j].y * w0.y + cf[j].z * w1.x + cf[j].w * w1.y;
        }
        #pragma unroll
        for (int off = 16; off > 0; off >>= 1) acc += __shfl_xor_sync(0xffffffffu, acc, off);
        if (lane == 0) s->logit[sq] = acc + ba[sq];
    }
    __syncthreads();

    if (tid < 128) {
        float l = s->logit[tid], m = l;
        #pragma unroll
        for (int off = 16; off > 0; off >>= 1) m = fmaxf(m, __shfl_xor_sync(0xffffffffu, m, off));
        if (lane == 0) s->rmax[tid >> 5] = m;
    }
    __syncthreads();
    if (tid < 128) {
        float m = fmaxf(fmaxf(s->rmax[0], s->rmax[1]), fmaxf(s->rmax[2], s->rmax[3]));
        float e = expf(s->logit[tid] - m);
        s->attn[tid] = e;
        #pragma unroll
        for (int off = 16; off > 0; off >>= 1) e += __shfl_xor_sync(0xffffffffu, e, off);
        if (lane == 0) s->rsum[tid >> 5] = e;
    }
    __syncthreads();
    const float inv = 1.0f / (s->rsum[0] + s->rsum[1] + s->rsum[2] + s->rsum[3]);

    {
        const int g = tid >> 6, cth = tid & 63;
        const uint4* xp = ((const uint4*)g_x16) + (size_t)b * SEQ * 64 + cth;
        float acc[8] = {};
        #pragma unroll 4
        for (int i = 0; i < 32; i++) {
            const int sq = g * 32 + i;
            const float a = s->attn[sq];
            uint4 v = xp[(size_t)sq * 64];
            float2 p0 = __half22float2(*(const __half2*)&v.x);
            float2 p1 = __half22float2(*(const __half2*)&v.y);
            float2 p2 = __half22float2(*(const __half2*)&v.z);
            float2 p3 = __half22float2(*(const __half2*)&v.w);
            acc[0] += a * p0.x; acc[1] += a * p0.y;
            acc[2] += a * p1.x; acc[3] += a * p1.y;
            acc[4] += a * p2.x; acc[5] += a * p2.y;
            acc[6] += a * p3.x; acc[7] += a * p3.y;
        }
        #pragma unroll
        for (int q = 0; q < 8; q++) s->xpart[g][cth * 8 + q] = acc[q];
    }
    __syncthreads();

    {
        const int d0 = tid * 2;
        float v0 = (s->xpart[0][d0]     + s->xpart[1][d0])     + (s->xpart[2][d0]     + s->xpart[3][d0]);
        float v1 = (s->xpart[0][d0 + 1] + s->xpart[1][d0 + 1]) + (s->xpart[2][d0 + 1] + s->xpart[3][d0 + 1]);
        v0 *= inv; v1 *= inv;
        uint32_t off = ((uint32_t)(b >> 6) * 16 + (d0 >> 6)) * ATILE + swz((b & 63) * 128 + (d0 & 63) * 2);
        *(__half2*)(g_AT + off) = __floats2half2_rn(v0, v1);
    }
}

// ---------------- k1: h-GEMM + attention -----------------------------------------
__global__ void __launch_bounds__(256, 4) k1_hgemm_attn(const float* __restrict__ ba) {
    extern __shared__ unsigned char dyn[];
    GRIDDEP_LAUNCH;
    if (blockIdx.x < 256) {
        gemm_k1(dyn, blockIdx.x);
    } else {
        GRIDDEP_WAIT;                                   // c/h from previous step
        attn_body(dyn, blockIdx.x - 256, ba);
    }
}

// ---------------- launcher -------------------------------------------------------
static inline void launch_pdl(const void* fn, dim3 g, dim3 b, size_t sh, void** args) {
    cudaLaunchConfig_t cfg = {};
    cfg.gridDim = g;
    cfg.blockDim = b;
    cfg.dynamicSmemBytes = sh;
    cfg.stream = 0;
    cudaLaunchAttribute at[1];
    at[0].id = cudaLaunchAttributeProgrammaticStreamSerialization;
    at[0].val.programmaticStreamSerializationAllowed = 1;
    cfg.attrs = at;
    cfg.numAttrs = 1;
    if (cudaLaunchKernelExC(&cfg, fn, args) != cudaSuccess) {
        (void)cudaGetLastError();                       // clear; fall back to plain
        cudaLaunchKernel(fn, g, b, args, sh, 0);
    }
}

extern "C" void kernel_launch(void* const* d_in, const int* in_sizes, int n_in,
                              void* d_out, int out_size) {
    const float* x    = (const float*)d_in[0];
    const float* W_ih = (const float*)d_in[1];
    const float* W_hh = (const float*)d_in[2];
    const float* b_ih = (const float*)d_in[3];
    const float* b_hh = (const float*)d_in[4];
    const float* Wa   = (const float*)d_in[5];
    const float* ba   = (const float*)d_in[6];
    float* out = (float*)d_out;

    cudaFuncSetAttribute(k1_hgemm_attn,   cudaFuncAttributeMaxDynamicSharedMemorySize, DSM1);
    cudaFuncSetAttribute(k2_xgemm_update, cudaFuncAttributeMaxDynamicSharedMemorySize, DSM2);

    prep_a<<<2048, 1024>>>(W_ih, W_hh, b_ih, b_hh);
    prep_b<<<8352, 1024>>>(x, Wa);

    for (int t = 0; t < SEQ; t++) {
        const float* ba_arg = ba;
        void* a1[] = { (void*)&ba_arg };
        launch_pdl((const void*)k1_hgemm_attn, dim3(512), dim3(256), DSM1, a1);
        float* out_arg = out;
        int t_arg = t;
        void* a2[] = { (void*)&out_arg, (void*)&t_arg };
        launch_pdl((const void*)k2_xgemm_update, dim3(256), dim3(256), DSM2, a2);
    }
}